// round 7
// baseline (speedup 1.0000x reference)
#include <cuda_runtime.h>
#include <cuda_bf16.h>
#include <math.h>
#include <stdint.h>

#define Bz   128
#define LCz  512
#define LEz  512
#define Hz   512
#define Vz   128
#define TDEC 511
#define NBLK 128
#define BHS  (Bz * Hz)   // 65536

// dynamic smem layout (float4 units):
//   Wp  [0,     9216)  : W fragment pack (2 wn * 144 ksteps * 32 lanes) 144KB
//   Ab  [9216, 10240)  : A staging, 2 buffers of 64x8 float4            16KB
//   scr [10240, 11776) : 6144 floats generic scratch                    24KB
//   (F-build phase reuses the Wp region for its 512x36 staging tile)
#define SMEM_BYTES 188416

// ---------------- static device scratch -------------------------------------
__device__ __align__(16) float g_h[2][BHS];
__device__ __align__(16) float g_c[BHS];
__device__ __align__(16) float g_vp[2][2][BHS];   // [parity][k-split]
__device__ __align__(16) float g_attn[BHS];
__device__ __align__(16) __nv_bfloat16 g_enc [(size_t)Bz * LCz * Hz]; // raw enc_hs
__device__ __align__(16) __nv_bfloat16 g_encc[(size_t)Bz * LCz * Hz]; // compacted
__device__ __align__(16) __nv_bfloat16 g_Fc  [(size_t)Bz * LCz * Hz]; // compacted enc@att_W
__device__ __align__(16) __nv_bfloat16 g_vocb16[Vz * Hz];
__device__ int g_lidx[Bz * LCz];
__device__ int g_Lb[Bz];
__device__ float g_nll[Bz * TDEC];
__device__ float g_msk[Bz * TDEC];
__device__ float g_ps[NBLK], g_pc[NBLK];
__device__ unsigned g_arr1[16 * 32];   // padded group counters (128B apart)
__device__ unsigned g_arr0;
__device__ volatile unsigned g_gen;

__device__ __forceinline__ float sigm(float x) { return 1.f / (1.f + expf(-x)); }

__device__ __forceinline__ uint32_t s2u(const void* p) {
    return (uint32_t)__cvta_generic_to_shared(p);
}
__device__ __forceinline__ uint32_t f2tf32(uint32_t raw) {
    uint32_t u;
    float x = __uint_as_float(raw);
    asm("cvt.rna.tf32.f32 %0, %1;" : "=r"(u) : "f"(x));
    return u;
}
__device__ __forceinline__ void mma8(float acc[4],
    uint32_t a0, uint32_t a1, uint32_t a2, uint32_t a3,
    uint32_t b0, uint32_t b1)
{
    asm volatile("mma.sync.aligned.m16n8k8.row.col.f32.tf32.tf32.f32 "
        "{%0,%1,%2,%3},{%4,%5,%6,%7},{%8,%9},{%0,%1,%2,%3};"
        : "+f"(acc[0]), "+f"(acc[1]), "+f"(acc[2]), "+f"(acc[3])
        : "r"(a0), "r"(a1), "r"(a2), "r"(a3), "r"(b0), "r"(b1));
}

// ---------------- hierarchical grid barrier ---------------------------------
__device__ __forceinline__ void gsync() {
    __syncthreads();
    if (threadIdx.x == 0) {
        __threadfence();
        unsigned gen = g_gen;
        unsigned grp = blockIdx.x >> 3;                // 16 groups of 8
        if (atomicAdd(&g_arr1[grp * 32], 1u) == 7u) {
            if (atomicAdd(&g_arr0, 1u) == 15u) {
                #pragma unroll
                for (int i = 0; i < 16; i++) g_arr1[i * 32] = 0u;
                g_arr0 = 0u;
                __threadfence();
                g_gen = gen + 1u;
            } else {
                while (g_gen == gen) __nanosleep(32);
            }
        } else {
            while (g_gen == gen) __nanosleep(32);
        }
        __threadfence();
    }
    __syncthreads();
}

// ---------------- W fragment pack (once per phase) --------------------------
__device__ void pack_W(float4* Wp, int nb, int KS, int Kih,
                       const float* __restrict__ Wih, int ldih,
                       const float* __restrict__ Whh, int ldhh)
{
    for (int idx = threadIdx.x; idx < 2 * KS * 32; idx += 256) {
        int wn  = idx / (KS * 32);
        int rem = idx - wn * (KS * 32);
        int s = rem >> 5, l = rem & 31;
        int gid = l >> 2, tig = l & 3;
        int k0 = s * 8 + tig, k1 = k0 + 4;
        float v[4];
        #pragma unroll
        for (int hh = 0; hh < 2; hh++) {
            int c = hh * 8 + gid;
            int jj = wn * 4 + (c >> 2);
            int gate = c & 3;
            int grow = gate * Hz + nb * 8 + jj;
            const float* pi = Wih + (size_t)grow * ldih;
            const float* ph = Whh + (size_t)grow * ldhh;
            v[hh * 2]     = (k0 < Kih) ? pi[k0] : ph[k0 - Kih];
            v[hh * 2 + 1] = (k1 < Kih) ? pi[k1] : ph[k1 - Kih];
        }
        float4 o;
        o.x = __uint_as_float(f2tf32(__float_as_uint(v[0])));
        o.y = __uint_as_float(f2tf32(__float_as_uint(v[1])));
        o.z = __uint_as_float(f2tf32(__float_as_uint(v[2])));
        o.w = __uint_as_float(f2tf32(__float_as_uint(v[3])));
        Wp[idx] = o;
    }
}

// ---------------- A chunk loader (2 float4 per thread) ----------------------
template<bool DEC>
__device__ __forceinline__ void loadA(float4& r0, float4& r1, int cc,
    const float* __restrict__ xrow, const float* __restrict__ hrow,
    const float* __restrict__ vrow, int quad)
{
    #pragma unroll
    for (int u = 0; u < 2; u++) {
        int kf4 = cc * 8 + quad * 2 + u;
        float4 v;
        if (DEC) {
            if (kf4 < 32) {
                v = *(const float4*)(xrow + kf4 * 4);
            } else if (kf4 < 160) {
                int off = kf4 * 4 - 128;
                float4 a  = *(const float4*)(vrow + off);
                float4 b2 = *(const float4*)(vrow + off + BHS);
                v.x = a.x + b2.x;
                v.y = a.y + b2.y;
                v.z = a.z + b2.z;
                v.w = a.w + b2.w;
            } else {
                v = *(const float4*)(hrow + kf4 * 4 - 640);
            }
        } else {
            if (kf4 < 32) v = *(const float4*)(xrow + kf4 * 4);
            else          v = *(const float4*)(hrow + kf4 * 4 - 128);
        }
        if (u == 0) r0 = v; else r1 = v;
    }
}

// ---------------- fused gates GEMM (tf32 mma) + LSTM cell -------------------
template<bool DEC>
__device__ __forceinline__ void gates_step(
    const float4* __restrict__ Wp, float4* __restrict__ Ab,
    const float* __restrict__ xbase, int t,
    const float* __restrict__ hin, float* __restrict__ hout,
    const float* __restrict__ vbase,
    int mh, int nb, const float bias[2][4])
{
    const int NCH = DEC ? 36 : 20;
    const int KS  = DEC ? 144 : 80;
    int tid = threadIdx.x;
    int l = tid & 31, wrp = tid >> 5;
    int wm = wrp & 3, wn = wrp >> 2;
    int gid = l >> 2, t0 = l & 3;
    int quad = tid & 3, mrow = tid >> 2;
    int m16 = mh * 64 + wm * 16;
    int arow = wm * 16 + ((l >> 3) & 1) * 8 + (l & 7);
    int halfsel = l >> 4;

    int bS = mh * 64 + mrow;
    const float* xrow = xbase + ((size_t)bS * (DEC ? LEz : LCz) + t) * Vz;
    const float* hrow = hin + bS * Hz;
    const float* vrow = DEC ? (vbase + bS * Hz) : (const float*)0;

    float acc[2][4];
    #pragma unroll
    for (int i = 0; i < 2; i++)
        #pragma unroll
        for (int k = 0; k < 4; k++) acc[i][k] = 0.f;

    float4 r0, r1;
    loadA<DEC>(r0, r1, 0, xrow, hrow, vrow, quad);
    {
        int c0 = quad * 2;
        Ab[mrow * 8 + (c0 ^ (mrow & 7))] = r0;
        Ab[mrow * 8 + ((c0 + 1) ^ (mrow & 7))] = r1;
    }
    __syncthreads();

    uint32_t ab0 = s2u(Ab), ab1 = s2u(Ab + 512);
    for (int cc = 0; cc < NCH; cc++) {
        bool more = (cc + 1 < NCH);
        if (more) loadA<DEC>(r0, r1, cc + 1, xrow, hrow, vrow, quad);
        uint32_t ab = (cc & 1) ? ab1 : ab0;
        #pragma unroll
        for (int s4 = 0; s4 < 4; s4++) {
            int ccol = (2 * s4 + halfsel) ^ (arow & 7);
            uint32_t addr = ab + (uint32_t)((arow * 8 + ccol) * 16);
            uint32_t q0, q1, q2, q3;
            asm volatile("ldmatrix.sync.aligned.m8n8.x4.shared.b16 {%0,%1,%2,%3}, [%4];"
                         : "=r"(q0), "=r"(q1), "=r"(q2), "=r"(q3) : "r"(addr));
            uint32_t a0 = f2tf32(q0), a1 = f2tf32(q1), a2 = f2tf32(q2), a3 = f2tf32(q3);
            float4 wv = Wp[((size_t)wn * KS + (cc * 4 + s4)) * 32 + l];
            mma8(acc[0], a0, a1, a2, a3, __float_as_uint(wv.x), __float_as_uint(wv.y));
            mma8(acc[1], a0, a1, a2, a3, __float_as_uint(wv.z), __float_as_uint(wv.w));
        }
        if (more) {
            float4* Bn = (cc & 1) ? Ab : (Ab + 512);
            int c0 = quad * 2;
            Bn[mrow * 8 + (c0 ^ (mrow & 7))] = r0;
            Bn[mrow * 8 + ((c0 + 1) ^ (mrow & 7))] = r1;
        }
        __syncthreads();
    }

    bool evn = ((t0 & 1) == 0);
    #pragma unroll
    for (int hh = 0; hh < 2; hh++) {
        float d0 = acc[hh][0], d1 = acc[hh][1], d2 = acc[hh][2], d3 = acc[hh][3];
        float x0 = __shfl_xor_sync(0xffffffffu, d0, 1);
        float x1 = __shfl_xor_sync(0xffffffffu, d1, 1);
        float x2 = __shfl_xor_sync(0xffffffffu, d2, 1);
        float x3 = __shfl_xor_sync(0xffffffffu, d3, 1);
        int j = nb * 8 + wn * 4 + hh * 2 + (t0 >> 1);
        int b = m16 + gid + (evn ? 0 : 8);
        float gi = (evn ? d0 : x2) + bias[hh][0];
        float gf = (evn ? d1 : x3) + bias[hh][1];
        float gg = (evn ? x0 : d2) + bias[hh][2];
        float go = (evn ? x1 : d3) + bias[hh][3];
        float c  = g_c[b * Hz + j];
        float cn = sigm(gf) * c + sigm(gi) * tanhf(gg);
        float hn = sigm(go) * tanhf(cn);
        g_c[b * Hz + j] = cn;
        hout[b * Hz + j] = hn;
        if (!DEC)
            g_enc[((size_t)b * LCz + t) * Hz + j] = __float2bfloat16(hn);
    }
}

__device__ __forceinline__ void load_bias(float bias[2][4],
    const float* __restrict__ bih, const float* __restrict__ bhh, int nb)
{
    int l = threadIdx.x & 31;
    int wn = (threadIdx.x >> 5) >> 2;
    int t0 = l & 3;
    #pragma unroll
    for (int hh = 0; hh < 2; hh++) {
        int j = nb * 8 + wn * 4 + hh * 2 + (t0 >> 1);
        #pragma unroll
        for (int g4 = 0; g4 < 4; g4++)
            bias[hh][g4] = bih[g4 * Hz + j] + bhh[g4 * Hz + j];
    }
}

// ---------------- pad-compaction scan (block = batch) -----------------------
__device__ void comp_scan(int b, const int* __restrict__ C_pad, float* smf)
{
    int* sm = (int*)smf;
    int tid = threadIdx.x, lane = tid & 31, w = tid >> 5;
    int l0 = tid * 2, l1 = tid * 2 + 1;
    int f0 = (C_pad[b * LCz + l0] == 0) ? 1 : 0;
    int f1 = (C_pad[b * LCz + l1] == 0) ? 1 : 0;
    int s = f0 + f1;
    int x = s;
    #pragma unroll
    for (int o = 1; o < 32; o <<= 1) {
        int y = __shfl_up_sync(0xffffffffu, x, o);
        if (lane >= o) x += y;
    }
    if (lane == 31) sm[w] = x;
    __syncthreads();
    if (tid == 0) {
        int run = 0;
        for (int i = 0; i < 8; i++) { int v = sm[i]; sm[8 + i] = run; run += v; }
        sm[16] = run;
    }
    __syncthreads();
    int excl = sm[8 + w] + x - s;
    if (f0) g_lidx[b * LCz + excl] = l0;
    if (f1) g_lidx[b * LCz + excl + f0] = l1;
    if (tid == 0) g_Lb[b] = sm[16];
    __syncthreads();
}

// ---------------- build compacted enc + F = enc@att_W (block = batch) -------
__device__ void build_F(int b, const float* __restrict__ att_W, float* se)
{
    int tid = threadIdx.x;
    int Lb = g_Lb[b];
    for (int ci0 = 0; ci0 < Lb; ci0 += 32) {
        int R = min(32, Lb - ci0);
        for (int idx = tid; idx < R * 512; idx += 256) {
            int r = idx >> 9, j = idx & 511;
            int l = g_lidx[b * LCz + ci0 + r];
            __nv_bfloat16 hv = g_enc[((size_t)b * LCz + l) * Hz + j];
            se[j * 36 + r] = __bfloat162float(hv);
            g_encc[((size_t)b * LCz + ci0 + r) * Hz + j] = hv;
        }
        __syncthreads();
        #pragma unroll
        for (int half = 0; half < 2; half++) {
            int k = tid + half * 256;
            float acc[32];
            #pragma unroll
            for (int i = 0; i < 32; i++) acc[i] = 0.f;
            for (int j = 0; j < 512; j++) {
                float wv = att_W[j * Hz + k];
                #pragma unroll
                for (int g4 = 0; g4 < 8; g4++) {
                    float4 e = *(const float4*)&se[j * 36 + g4 * 4];
                    acc[g4 * 4 + 0] += e.x * wv;
                    acc[g4 * 4 + 1] += e.y * wv;
                    acc[g4 * 4 + 2] += e.z * wv;
                    acc[g4 * 4 + 3] += e.w * wv;
                }
            }
            for (int r = 0; r < R; r++)
                g_Fc[((size_t)b * LCz + ci0 + r) * Hz + k] = __float2bfloat16(acc[r]);
        }
        __syncthreads();
    }
}

// ---------------- attention over compacted rows (block = batch) -------------
__device__ void attn_block(int b, const float* __restrict__ hout, float* sm)
{
    float* ss   = sm;          // 512
    float* red  = sm + 512;    // 8
    float* sca  = sm + 520;    // 2
    float* wacc = sm + 528;    // 8*512
    int tid = threadIdx.x, lane = tid & 31, w = tid >> 5;
    int Lb = g_Lb[b];

    float qreg[16];
    const float* hb = hout + b * Hz + lane * 16;
    #pragma unroll
    for (int i = 0; i < 16; i += 4) {
        float4 v = *(const float4*)(hb + i);
        qreg[i] = v.x; qreg[i + 1] = v.y; qreg[i + 2] = v.z; qreg[i + 3] = v.w;
    }

    const __nv_bfloat16* Fb = g_Fc + (size_t)b * LCz * Hz;
    #pragma unroll 4
    for (int l = w; l < Lb; l += 8) {
        const __nv_bfloat16* row = Fb + (size_t)l * Hz + lane * 16;
        uint4 u0 = *(const uint4*)row;
        uint4 u1 = *(const uint4*)(row + 8);
        const __nv_bfloat162* h0 = (const __nv_bfloat162*)&u0;
        const __nv_bfloat162* h1 = (const __nv_bfloat162*)&u1;
        float acc = 0.f;
        #pragma unroll
        for (int i = 0; i < 4; i++) {
            float2 f0 = __bfloat1622float2(h0[i]);
            float2 f1 = __bfloat1622float2(h1[i]);
            acc += f0.x * qreg[2 * i]     + f0.y * qreg[2 * i + 1];
            acc += f1.x * qreg[8 + 2 * i] + f1.y * qreg[8 + 2 * i + 1];
        }
        #pragma unroll
        for (int o = 16; o > 0; o >>= 1) acc += __shfl_xor_sync(0xffffffffu, acc, o);
        if (lane == 0) ss[l] = acc;
    }
    __syncthreads();

    float m = -INFINITY;
    for (int l = tid; l < Lb; l += 256) m = fmaxf(m, ss[l]);
    #pragma unroll
    for (int o = 16; o > 0; o >>= 1) m = fmaxf(m, __shfl_xor_sync(0xffffffffu, m, o));
    if (lane == 0) red[w] = m;
    __syncthreads();
    if (tid == 0) {
        float mm = red[0];
        for (int i = 1; i < 8; i++) mm = fmaxf(mm, red[i]);
        sca[0] = mm;
    }
    __syncthreads();
    float bmax = sca[0];

    float s = 0.f;
    for (int l = tid; l < Lb; l += 256) {
        float e = expf(ss[l] - bmax);
        ss[l] = e;
        s += e;
    }
    #pragma unroll
    for (int o = 16; o > 0; o >>= 1) s += __shfl_xor_sync(0xffffffffu, s, o);
    if (lane == 0) red[w] = s;
    __syncthreads();
    if (tid == 0) {
        float t2 = 0.f;
        for (int i = 0; i < 8; i++) t2 += red[i];
        sca[1] = t2;
    }
    __syncthreads();
    float inv = 1.f / sca[1];

    float acc2[16];
    #pragma unroll
    for (int i = 0; i < 16; i++) acc2[i] = 0.f;
    const __nv_bfloat16* Eb = g_encc + (size_t)b * LCz * Hz;
    #pragma unroll 4
    for (int l = w; l < Lb; l += 8) {
        float d = ss[l];
        const __nv_bfloat16* row = Eb + (size_t)l * Hz + lane * 16;
        uint4 u0 = *(const uint4*)row;
        uint4 u1 = *(const uint4*)(row + 8);
        const __nv_bfloat162* h0 = (const __nv_bfloat162*)&u0;
        const __nv_bfloat162* h1 = (const __nv_bfloat162*)&u1;
        #pragma unroll
        for (int i = 0; i < 4; i++) {
            float2 f0 = __bfloat1622float2(h0[i]);
            float2 f1 = __bfloat1622float2(h1[i]);
            acc2[2 * i]         += d * f0.x;
            acc2[2 * i + 1]     += d * f0.y;
            acc2[8 + 2 * i]     += d * f1.x;
            acc2[8 + 2 * i + 1] += d * f1.y;
        }
    }
    #pragma unroll
    for (int i = 0; i < 16; i++) wacc[w * Hz + lane * 16 + i] = acc2[i];
    __syncthreads();

    for (int h = tid; h < Hz; h += 256) {
        float t2 = 0.f;
        #pragma unroll
        for (int ww = 0; ww < 8; ww++) t2 += wacc[ww * Hz + h];
        g_attn[b * Hz + h] = t2 * inv;
    }
}

// ---------------- out-proj: 16m x 64n, K=512 per split (2 splits) -----------
__device__ void outproj16(const float* __restrict__ hout,
                          const float* __restrict__ out_W,
                          const float* __restrict__ out_b,
                          float* __restrict__ vout, float* sm)
{
    int bid = blockIdx.x, tid = threadIdx.x;
    int m0 = (bid & 7) * 16;
    int idx2 = bid >> 3;
    int n0 = (idx2 & 7) * 64;
    int split = idx2 >> 3;
    const float* Asrc = (split == 0) ? hout : g_attn;
    float* As = sm;          // 16 x 16
    float* Ws = sm + 256;    // 16 x 64
    int m = tid >> 4, ng = tid & 15;
    int ar = tid >> 2, k4 = tid & 3;
    float acc[4] = {0.f, 0.f, 0.f, 0.f};
    const float* ap = Asrc + (size_t)(m0 + (tid < 64 ? ar : 0)) * Hz + k4 * 4;
    const float* wp = out_W + (size_t)(n0 + ar) * (2 * Hz) + split * Hz + k4 * 4;

    for (int k0 = 0; k0 < Hz; k0 += 16) {
        if (tid < 64) {
            float4 av = *(const float4*)(ap + k0);
            As[(k4 * 4 + 0) * 16 + ar] = av.x;
            As[(k4 * 4 + 1) * 16 + ar] = av.y;
            As[(k4 * 4 + 2) * 16 + ar] = av.z;
            As[(k4 * 4 + 3) * 16 + ar] = av.w;
        }
        {
            float4 wv = *(const float4*)(wp + k0);
            Ws[(k4 * 4 + 0) * 64 + ar] = wv.x;
            Ws[(k4 * 4 + 1) * 64 + ar] = wv.y;
            Ws[(k4 * 4 + 2) * 64 + ar] = wv.z;
            Ws[(k4 * 4 + 3) * 64 + ar] = wv.w;
        }
        __syncthreads();
        #pragma unroll
        for (int kk = 0; kk < 16; kk++) {
            float a = As[kk * 16 + m];
            float4 wv4 = *(const float4*)&Ws[kk * 64 + ng * 4];
            acc[0] += a * wv4.x; acc[1] += a * wv4.y;
            acc[2] += a * wv4.z; acc[3] += a * wv4.w;
        }
        __syncthreads();
    }
    #pragma unroll
    for (int i = 0; i < 4; i++) {
        int n = n0 + ng * 4 + i;
        float v = acc[i] + ((split == 0) ? out_b[n] : 0.f);
        vout[(size_t)split * BHS + (m0 + m) * Hz + n] = v;
    }
}

// ---------------- per-batch logits + masked CE ------------------------------
__device__ void logits_ce(int b, int tt, const int* __restrict__ E,
                          const float* __restrict__ vp,
                          const float* __restrict__ voc_b, float* sm)
{
    float* st = sm;
    float* sl = sm + 512;
    int tid = threadIdx.x, lane = tid & 31, w = tid >> 5;
    __syncthreads();

    for (int i = tid; i < Hz; i += 256)
        st[i] = tanhf(vp[b * Hz + i] + vp[BHS + b * Hz + i]);
    __syncthreads();

    float sreg[16];
    #pragma unroll
    for (int i = 0; i < 16; i++) sreg[i] = st[lane * 16 + i];

    for (int v = w; v < Vz; v += 8) {
        const __nv_bfloat16* wr = g_vocb16 + (size_t)v * Hz + lane * 16;
        uint4 u0 = *(const uint4*)wr;
        uint4 u1 = *(const uint4*)(wr + 8);
        const __nv_bfloat162* h0 = (const __nv_bfloat162*)&u0;
        const __nv_bfloat162* h1 = (const __nv_bfloat162*)&u1;
        float acc = 0.f;
        #pragma unroll
        for (int i = 0; i < 4; i++) {
            float2 f0 = __bfloat1622float2(h0[i]);
            float2 f1 = __bfloat1622float2(h1[i]);
            acc += f0.x * sreg[2 * i]     + f0.y * sreg[2 * i + 1];
            acc += f1.x * sreg[8 + 2 * i] + f1.y * sreg[8 + 2 * i + 1];
        }
        #pragma unroll
        for (int o = 16; o > 0; o >>= 1) acc += __shfl_xor_sync(0xffffffffu, acc, o);
        if (lane == 0) sl[v] = acc + voc_b[v];
    }
    __syncthreads();

    if (w == 0) {
        float m = -INFINITY;
        for (int v = lane; v < Vz; v += 32) m = fmaxf(m, sl[v]);
        #pragma unroll
        for (int o = 16; o > 0; o >>= 1) m = fmaxf(m, __shfl_xor_sync(0xffffffffu, m, o));
        float s = 0.f;
        for (int v = lane; v < Vz; v += 32) s += expf(sl[v] - m);
        #pragma unroll
        for (int o = 16; o > 0; o >>= 1) s += __shfl_xor_sync(0xffffffffu, s, o);
        if (lane == 0) {
            int tv = E[b * LEz + tt + 1];
            int idx = b * TDEC + tt;
            if (tv != 0) { g_nll[idx] = m + logf(s) - sl[tv]; g_msk[idx] = 1.f; }
            else         { g_nll[idx] = 0.f;                  g_msk[idx] = 0.f; }
        }
    }
}

// ---------------- the single persistent kernel ------------------------------
__global__ void __launch_bounds__(256, 1) persist_kernel(
    const float* __restrict__ C,       const int* __restrict__ C_pad,
    const int* __restrict__ E,         const float* __restrict__ E_emb,
    const float* __restrict__ enc_Wih, const float* __restrict__ enc_Whh,
    const float* __restrict__ enc_bih, const float* __restrict__ enc_bhh,
    const float* __restrict__ dec_Wih, const float* __restrict__ dec_Whh,
    const float* __restrict__ dec_bih, const float* __restrict__ dec_bhh,
    const float* __restrict__ att_W,   const float* __restrict__ out_W,
    const float* __restrict__ out_b,   const float* __restrict__ voc_W,
    const float* __restrict__ voc_b,   float* __restrict__ out)
{
    extern __shared__ __align__(16) float4 dsm[];
    float4* Wp  = dsm;
    float4* Ab  = dsm + 9216;
    float*  scr = (float*)(dsm + 10240);

    int bid = blockIdx.x, tid = threadIdx.x;
    int lane = tid & 31, w = tid >> 5;
    int mh = bid & 1, nb = bid >> 1;

    // ---- init state + bf16 voc_W pack ----
    for (int i = bid * 256 + tid; i < BHS; i += NBLK * 256) { g_h[0][i] = 0.f; g_c[i] = 0.f; }
    float* vpf = (float*)g_vp;
    for (int i = bid * 256 + tid; i < 4 * BHS; i += NBLK * 256) vpf[i] = 0.f;
    for (int i = bid * 256 + tid; i < Vz * Hz; i += NBLK * 256)
        g_vocb16[i] = __float2bfloat16(voc_W[i]);
    gsync();

    // ---- encoder ----
    pack_W(Wp, nb, 80, Vz, enc_Wih, Vz, enc_Whh, Hz);
    __syncthreads();
    float biasE[2][4];
    load_bias(biasE, enc_bih, enc_bhh, nb);
    for (int t = 0; t < LCz; t++) {
        const float* hin = g_h[t & 1];
        float* hout = g_h[1 - (t & 1)];
        gates_step<false>(Wp, Ab, C, t, hin, hout, nullptr, mh, nb, biasE);
        gsync();
    }

    // ---- compaction + F precompute (block = batch bid) ----
    comp_scan(bid, C_pad, scr);
    build_F(bid, att_W, (float*)dsm);
    gsync();

    // ---- decoder ----
    pack_W(Wp, nb, 144, Vz + Hz, dec_Wih, Vz + Hz, dec_Whh, Hz);
    __syncthreads();
    float biasD[2][4];
    load_bias(biasD, dec_bih, dec_bhh, nb);

    for (int t = 0; t < TDEC; t++) {
        const float* hin = g_h[t & 1];
        float* hout = g_h[1 - (t & 1)];

        // A: gates (tf32 mma) + cell; Vprev = sum of 2 partials, parity (t-1)&1
        gates_step<true>(Wp, Ab, E_emb, t, hin, hout,
                         (const float*)g_vp[(t + 1) & 1], mh, nb, biasD);
        gsync();

        // B: attention for batch = bid (scores = Fc · h)
        attn_block(bid, hout, scr);
        gsync();

        // C: out-proj partials (parity t&1) + CE(t-1) (parity (t-1)&1)
        outproj16(hout, out_W, out_b, (float*)g_vp[t & 1], scr);
        if (t > 0) logits_ce(bid, t - 1, E, (const float*)g_vp[(t + 1) & 1], voc_b, scr);
        gsync();
    }

    // ---- last step's CE ----
    logits_ce(bid, TDEC - 1, E, (const float*)g_vp[(TDEC - 1) & 1], voc_b, scr);
    gsync();

    // ---- deterministic reduction ----
    {
        float s = 0.f, c = 0.f;
        for (int i = tid; i < TDEC; i += 256) {
            s += g_nll[bid * TDEC + i];
            c += g_msk[bid * TDEC + i];
        }
        #pragma unroll
        for (int o = 16; o > 0; o >>= 1) {
            s += __shfl_xor_sync(0xffffffffu, s, o);
            c += __shfl_xor_sync(0xffffffffu, c, o);
        }
        __syncthreads();
        if (lane == 0) { scr[w] = s; scr[8 + w] = c; }
        __syncthreads();
        if (tid == 0) {
            float ts = 0.f, tc = 0.f;
            for (int i = 0; i < 8; i++) { ts += scr[i]; tc += scr[8 + i]; }
            g_ps[bid] = ts; g_pc[bid] = tc;
        }
    }
    gsync();
    if (bid == 0 && tid == 0) {
        float ts = 0.f, tc = 0.f;
        for (int i = 0; i < NBLK; i++) { ts += g_ps[i]; tc += g_pc[i]; }
        out[0] = ts / fmaxf(tc, 1.f);
    }
}

// ---------------- host entry (single launch => 1-node graph) ----------------
extern "C" void kernel_launch(void* const* d_in, const int* in_sizes, int n_in,
                              void* d_out, int out_size)
{
    cudaFuncSetAttribute((const void*)persist_kernel,
                         cudaFuncAttributeMaxDynamicSharedMemorySize, SMEM_BYTES);
    persist_kernel<<<NBLK, 256, SMEM_BYTES>>>(
        (const float*)d_in[0],  (const int*)d_in[1],
        (const int*)d_in[2],    (const float*)d_in[3],
        (const float*)d_in[4],  (const float*)d_in[5],
        (const float*)d_in[6],  (const float*)d_in[7],
        (const float*)d_in[8],  (const float*)d_in[9],
        (const float*)d_in[10], (const float*)d_in[11],
        (const float*)d_in[12], (const float*)d_in[13],
        (const float*)d_in[14], (const float*)d_in[15],
        (const float*)d_in[16], (float*)d_out);
}

// round 8
// speedup vs baseline: 1.2380x; 1.2380x over previous
#include <cuda_runtime.h>
#include <cuda_bf16.h>
#include <math.h>
#include <stdint.h>

#define Bz   128
#define LCz  512
#define LEz  512
#define Hz   512
#define Vz   128
#define TDEC 511
#define NBLK 128
#define BHS  (Bz * Hz)   // 65536

// dynamic smem (float4 units):
//   Wp  [0, 9216)      : W fragment pack (144KB)
//   Ab  [9216, 11264)  : A staging, 4 stages x 512 f4 (32KB)
//   scr [11264, 12800) : 6144 floats scratch (24KB)
#define SMEM_BYTES 204800

// ---------------- static device scratch -------------------------------------
__device__ __align__(16) float g_h[2][BHS];
__device__ __align__(16) float g_c[BHS];
__device__ __align__(16) float g_vp[2][2][BHS];     // [parity][k-split]
__device__ __align__(16) float g_attn2[2][BHS];     // attn, parity-buffered
__device__ __align__(16) __nv_bfloat16 g_enc [(size_t)Bz * LCz * Hz];
__device__ __align__(16) __nv_bfloat16 g_encc[(size_t)Bz * LCz * Hz];
__device__ __align__(16) __nv_bfloat16 g_Fc  [(size_t)Bz * LCz * Hz];
__device__ __align__(16) __nv_bfloat16 g_vocb16[Vz * Hz];
__device__ __align__(16) float g_Weff [2048 * Hz];  // Whh + Wv@Wo_h
__device__ __align__(16) float g_Wcomp[2048 * Hz];  // Wv@Wo_a
__device__ float g_beff[2048];
__device__ float g_u[Bz * Hz];
__device__ float g_corr[Bz * 2048];
__device__ int g_lidx[Bz * LCz];
__device__ int g_Lb[Bz];
__device__ float g_nll[Bz * TDEC];
__device__ float g_msk[Bz * TDEC];
__device__ float g_ps[NBLK], g_pc[NBLK];
__device__ unsigned g_arr1[16 * 32];
__device__ unsigned g_arr0;
__device__ volatile unsigned g_gen;

__device__ __forceinline__ float sigm(float x) { return 1.f / (1.f + expf(-x)); }

__device__ __forceinline__ uint32_t s2u(const void* p) {
    return (uint32_t)__cvta_generic_to_shared(p);
}
__device__ __forceinline__ uint32_t f2tf32(uint32_t raw) {
    uint32_t u;
    float x = __uint_as_float(raw);
    asm("cvt.rna.tf32.f32 %0, %1;" : "=r"(u) : "f"(x));
    return u;
}
__device__ __forceinline__ void mma8(float acc[4],
    uint32_t a0, uint32_t a1, uint32_t a2, uint32_t a3,
    uint32_t b0, uint32_t b1)
{
    asm volatile("mma.sync.aligned.m16n8k8.row.col.f32.tf32.tf32.f32 "
        "{%0,%1,%2,%3},{%4,%5,%6,%7},{%8,%9},{%0,%1,%2,%3};"
        : "+f"(acc[0]), "+f"(acc[1]), "+f"(acc[2]), "+f"(acc[3])
        : "r"(a0), "r"(a1), "r"(a2), "r"(a3), "r"(b0), "r"(b1));
}
#define CPA16(dst, src) asm volatile("cp.async.cg.shared.global [%0], [%1], 16;" :: "r"(dst), "l"(src))
#define CPA_COMMIT()    asm volatile("cp.async.commit_group;")
#define CPA_WAIT2()     asm volatile("cp.async.wait_group 2;")

// ---------------- hierarchical grid barrier ---------------------------------
__device__ __forceinline__ void gsync() {
    __syncthreads();
    if (threadIdx.x == 0) {
        __threadfence();
        unsigned gen = g_gen;
        unsigned grp = blockIdx.x >> 3;
        if (atomicAdd(&g_arr1[grp * 32], 1u) == 7u) {
            if (atomicAdd(&g_arr0, 1u) == 15u) {
                #pragma unroll
                for (int i = 0; i < 16; i++) g_arr1[i * 32] = 0u;
                g_arr0 = 0u;
                __threadfence();
                g_gen = gen + 1u;
            } else {
                while (g_gen == gen) __nanosleep(32);
            }
        } else {
            while (g_gen == gen) __nanosleep(32);
        }
        __threadfence();
    }
    __syncthreads();
}

// ---------------- W fragment pack: 3 K-segments -----------------------------
__device__ __forceinline__ float wget(int grow, int k,
    const float* W0, int ld0, int K0,
    const float* W1, int ld1, int K1,
    const float* W2, int ld2)
{
    if (k < K0) return W0[(size_t)grow * ld0 + k];
    if (k < K0 + K1) return W1[(size_t)grow * ld1 + (k - K0)];
    return W2[(size_t)grow * ld2 + (k - K0 - K1)];
}

__device__ void pack_W3(float4* Wp, int nb, int KS,
    const float* W0, int ld0, int K0,
    const float* W1, int ld1, int K1,
    const float* W2, int ld2)
{
    for (int idx = threadIdx.x; idx < 2 * KS * 32; idx += 256) {
        int wn  = idx / (KS * 32);
        int rem = idx - wn * (KS * 32);
        int s = rem >> 5, l = rem & 31;
        int gid = l >> 2, tig = l & 3;
        int k0 = s * 8 + tig, k1 = k0 + 4;
        float v[4];
        #pragma unroll
        for (int hh = 0; hh < 2; hh++) {
            int c = hh * 8 + gid;
            int jj = wn * 4 + (c >> 2);
            int gate = c & 3;
            int grow = gate * Hz + nb * 8 + jj;
            v[hh * 2]     = wget(grow, k0, W0, ld0, K0, W1, ld1, K1, W2, ld2);
            v[hh * 2 + 1] = wget(grow, k1, W0, ld0, K0, W1, ld1, K1, W2, ld2);
        }
        float4 o;
        o.x = __uint_as_float(f2tf32(__float_as_uint(v[0])));
        o.y = __uint_as_float(f2tf32(__float_as_uint(v[1])));
        o.z = __uint_as_float(f2tf32(__float_as_uint(v[2])));
        o.w = __uint_as_float(f2tf32(__float_as_uint(v[3])));
        Wp[idx] = o;
    }
}

// ---------------- gates GEMM with cp.async 4-stage pipeline -----------------
// A layout (floats): [x 0..127 | h 0..511 -> k 128..639 | attn -> k 640..1151]
__device__ __forceinline__ void issue_stage(uint32_t abase, int buf, int cc,
    const float* s0, const float* s1, const float* s2, int quad, int mrow)
{
    #pragma unroll
    for (int u = 0; u < 2; u++) {
        int kf4 = cc * 8 + quad * 2 + u;
        const float* src = (kf4 < 32) ? (s0 + kf4 * 4)
                         : (kf4 < 160) ? (s1 + (kf4 - 32) * 4)
                                       : (s2 + (kf4 - 160) * 4);
        int col = (quad * 2 + u) ^ (mrow & 7);
        uint32_t dst = abase + (uint32_t)(buf * 512 + mrow * 8 + col) * 16;
        CPA16(dst, src);
    }
}

template<bool DEC>
__device__ void gates_step(
    const float4* __restrict__ Wp, float4* __restrict__ Ab,
    const float* __restrict__ xbase, int t,
    const float* __restrict__ hin, float* __restrict__ hout,
    const float* __restrict__ attnprev,
    int mh, int nb, const float bias[2][4], const float* __restrict__ corr)
{
    const int NCH = DEC ? 36 : 20;
    const int KS  = DEC ? 144 : 80;
    int tid = threadIdx.x;
    int l = tid & 31, wrp = tid >> 5;
    int wm = wrp & 3, wn = wrp >> 2;
    int gid = l >> 2, t0 = l & 3;
    int quad = tid & 3, mrow = tid >> 2;
    int m16 = mh * 64 + wm * 16;
    int arow = wm * 16 + ((l >> 3) & 1) * 8 + (l & 7);
    int halfsel = l >> 4;

    int bS = mh * 64 + mrow;
    const float* s0 = xbase + ((size_t)bS * (DEC ? LEz : LCz) + t) * Vz;
    const float* s1 = hin + bS * Hz;
    const float* s2 = DEC ? (attnprev + bS * Hz) : s1;   // s2 never selected for ENC

    uint32_t abase = s2u(Ab);
    // prologue: 3 stages in flight
    issue_stage(abase, 0, 0, s0, s1, s2, quad, mrow); CPA_COMMIT();
    issue_stage(abase, 1, 1, s0, s1, s2, quad, mrow); CPA_COMMIT();
    issue_stage(abase, 2, 2, s0, s1, s2, quad, mrow); CPA_COMMIT();

    float acc[2][4];
    #pragma unroll
    for (int i = 0; i < 2; i++)
        #pragma unroll
        for (int k = 0; k < 4; k++) acc[i][k] = 0.f;

    for (int cc = 0; cc < NCH; cc++) {
        CPA_WAIT2();
        __syncthreads();
        uint32_t ab = abase + (uint32_t)((cc & 3) * 512) * 16;
        #pragma unroll
        for (int s4 = 0; s4 < 4; s4++) {
            int ccol = (2 * s4 + halfsel) ^ (arow & 7);
            uint32_t addr = ab + (uint32_t)((arow * 8 + ccol) * 16);
            uint32_t q0, q1, q2, q3;
            asm volatile("ldmatrix.sync.aligned.m8n8.x4.shared.b16 {%0,%1,%2,%3}, [%4];"
                         : "=r"(q0), "=r"(q1), "=r"(q2), "=r"(q3) : "r"(addr));
            uint32_t a0 = f2tf32(q0), a1 = f2tf32(q1), a2 = f2tf32(q2), a3 = f2tf32(q3);
            float4 wv = Wp[((size_t)wn * KS + (cc * 4 + s4)) * 32 + l];
            mma8(acc[0], a0, a1, a2, a3, __float_as_uint(wv.x), __float_as_uint(wv.y));
            mma8(acc[1], a0, a1, a2, a3, __float_as_uint(wv.z), __float_as_uint(wv.w));
        }
        if (cc + 3 < NCH) {
            issue_stage(abase, (cc + 3) & 3, cc + 3, s0, s1, s2, quad, mrow);
            CPA_COMMIT();
        }
    }

    // cell epilogue
    bool evn = ((t0 & 1) == 0);
    #pragma unroll
    for (int hh = 0; hh < 2; hh++) {
        float d0 = acc[hh][0], d1 = acc[hh][1], d2 = acc[hh][2], d3 = acc[hh][3];
        float x0 = __shfl_xor_sync(0xffffffffu, d0, 1);
        float x1 = __shfl_xor_sync(0xffffffffu, d1, 1);
        float x2 = __shfl_xor_sync(0xffffffffu, d2, 1);
        float x3 = __shfl_xor_sync(0xffffffffu, d3, 1);
        int j = nb * 8 + wn * 4 + hh * 2 + (t0 >> 1);
        int b = m16 + gid + (evn ? 0 : 8);
        float gi = (evn ? d0 : x2) + bias[hh][0];
        float gf = (evn ? d1 : x3) + bias[hh][1];
        float gg = (evn ? x0 : d2) + bias[hh][2];
        float go = (evn ? x1 : d3) + bias[hh][3];
        if (corr) {
            gi -= corr[b * 2048 + j];
            gf -= corr[b * 2048 + 512 + j];
            gg -= corr[b * 2048 + 1024 + j];
            go -= corr[b * 2048 + 1536 + j];
        }
        float c  = g_c[b * Hz + j];
        float cn = sigm(gf) * c + sigm(gi) * tanhf(gg);
        float hn = sigm(go) * tanhf(cn);
        g_c[b * Hz + j] = cn;
        hout[b * Hz + j] = hn;
        if (!DEC)
            g_enc[((size_t)b * LCz + t) * Hz + j] = __float2bfloat16(hn);
    }
}

__device__ __forceinline__ void load_bias2(float bias[2][4],
    const float* __restrict__ bih, const float* __restrict__ bhh,
    const float* __restrict__ beff, int nb)
{
    int l = threadIdx.x & 31;
    int wn = (threadIdx.x >> 5) >> 2;
    int t0 = l & 3;
    #pragma unroll
    for (int hh = 0; hh < 2; hh++) {
        int j = nb * 8 + wn * 4 + hh * 2 + (t0 >> 1);
        #pragma unroll
        for (int g4 = 0; g4 < 4; g4++)
            bias[hh][g4] = beff ? beff[g4 * Hz + j] : (bih[g4 * Hz + j] + bhh[g4 * Hz + j]);
    }
}

// ---------------- pad compaction + build F = enc@att_W + u ------------------
__device__ void comp_scan(int b, const int* __restrict__ C_pad, float* smf)
{
    int* sm = (int*)smf;
    int tid = threadIdx.x, lane = tid & 31, w = tid >> 5;
    int l0 = tid * 2, l1 = tid * 2 + 1;
    int f0 = (C_pad[b * LCz + l0] == 0) ? 1 : 0;
    int f1 = (C_pad[b * LCz + l1] == 0) ? 1 : 0;
    int s = f0 + f1;
    int x = s;
    #pragma unroll
    for (int o = 1; o < 32; o <<= 1) {
        int y = __shfl_up_sync(0xffffffffu, x, o);
        if (lane >= o) x += y;
    }
    if (lane == 31) sm[w] = x;
    __syncthreads();
    if (tid == 0) {
        int run = 0;
        for (int i = 0; i < 8; i++) { int v = sm[i]; sm[8 + i] = run; run += v; }
        sm[16] = run;
    }
    __syncthreads();
    int excl = sm[8 + w] + x - s;
    if (f0) g_lidx[b * LCz + excl] = l0;
    if (f1) g_lidx[b * LCz + excl + f0] = l1;
    if (tid == 0) g_Lb[b] = sm[16];
    __syncthreads();
}

__device__ void build_F(int b, const float* __restrict__ att_W, float* se)
{
    int tid = threadIdx.x;
    int Lb = g_Lb[b];
    for (int ci0 = 0; ci0 < Lb; ci0 += 32) {
        int R = min(32, Lb - ci0);
        for (int idx = tid; idx < R * 512; idx += 256) {
            int r = idx >> 9, j = idx & 511;
            int l = g_lidx[b * LCz + ci0 + r];
            __nv_bfloat16 hv = g_enc[((size_t)b * LCz + l) * Hz + j];
            se[j * 36 + r] = __bfloat162float(hv);
            g_encc[((size_t)b * LCz + ci0 + r) * Hz + j] = hv;
        }
        __syncthreads();
        #pragma unroll
        for (int half = 0; half < 2; half++) {
            int k = tid + half * 256;
            float acc[32];
            #pragma unroll
            for (int i = 0; i < 32; i++) acc[i] = 0.f;
            for (int j = 0; j < 512; j++) {
                float wv = att_W[j * Hz + k];
                #pragma unroll
                for (int g4 = 0; g4 < 8; g4++) {
                    float4 e = *(const float4*)&se[j * 36 + g4 * 4];
                    acc[g4 * 4 + 0] += e.x * wv;
                    acc[g4 * 4 + 1] += e.y * wv;
                    acc[g4 * 4 + 2] += e.z * wv;
                    acc[g4 * 4 + 3] += e.w * wv;
                }
            }
            for (int r = 0; r < R; r++)
                g_Fc[((size_t)b * LCz + ci0 + r) * Hz + k] = __float2bfloat16(acc[r]);
        }
        __syncthreads();
    }
}

__device__ void calc_u(int b, const float* __restrict__ out_W,
                       const float* __restrict__ out_b, float* scr)
{
    int tid = threadIdx.x;
    __syncthreads();
    for (int i = tid; i < Hz; i += 256) scr[i] = g_h[0][b * Hz + i];
    __syncthreads();
    for (int v = tid; v < Hz; v += 256) {
        const float* wr = out_W + (size_t)v * (2 * Hz);
        float acc = 0.f;
        for (int h = 0; h < Hz; h += 4) {
            float4 w4 = *(const float4*)(wr + h);
            acc += w4.x * scr[h] + w4.y * scr[h + 1] + w4.z * scr[h + 2] + w4.w * scr[h + 3];
        }
        g_u[b * Hz + v] = acc + out_b[v];
    }
    __syncthreads();
}

// ---------------- weight composition + t=0 correction -----------------------
__device__ void compose(const float* __restrict__ dec_Wih, const float* __restrict__ dec_Whh,
                        const float* __restrict__ dec_bih, const float* __restrict__ dec_bhh,
                        const float* __restrict__ out_W, const float* __restrict__ out_b)
{
    int bid = blockIdx.x, tid = threadIdx.x;
    int g = bid * 16 + (tid >> 4);
    int c0 = (tid & 15) * 32;
    const float* wv = dec_Wih + (size_t)g * (Vz + Hz) + Vz;
    #pragma unroll 1
    for (int pass = 0; pass < 2; pass++) {
        float acc[32];
        #pragma unroll
        for (int i = 0; i < 32; i++) acc[i] = 0.f;
        float accb = 0.f;
        for (int v = 0; v < Hz; v++) {
            float w = wv[v];
            const float* owr = out_W + (size_t)v * (2 * Hz) + pass * Hz + c0;
            #pragma unroll
            for (int i = 0; i < 32; i += 4) {
                float4 o = *(const float4*)(owr + i);
                acc[i] += w * o.x; acc[i + 1] += w * o.y;
                acc[i + 2] += w * o.z; acc[i + 3] += w * o.w;
            }
            if (pass == 0) accb += w * out_b[v];
        }
        if (pass == 0) {
            for (int i = 0; i < 32; i++)
                g_Weff[(size_t)g * Hz + c0 + i] = dec_Whh[(size_t)g * Hz + c0 + i] + acc[i];
            if ((tid & 15) == 0) g_beff[g] = dec_bih[g] + dec_bhh[g] + accb;
        } else {
            for (int i = 0; i < 32; i++)
                g_Wcomp[(size_t)g * Hz + c0 + i] = acc[i];
        }
    }
}

__device__ void calc_c(int b, const float* __restrict__ dec_Wih, float* scr)
{
    int tid = threadIdx.x;
    __syncthreads();
    for (int i = tid; i < Hz; i += 256) scr[i] = g_u[b * Hz + i];
    __syncthreads();
    for (int g = tid; g < 2048; g += 256) {
        const float* wv = dec_Wih + (size_t)g * (Vz + Hz) + Vz;
        float acc = 0.f;
        for (int v = 0; v < Hz; v += 4) {
            float4 w4 = *(const float4*)(wv + v);
            acc += w4.x * scr[v] + w4.y * scr[v + 1] + w4.z * scr[v + 2] + w4.w * scr[v + 3];
        }
        g_corr[b * 2048 + g] = acc;
    }
}

// ---------------- attention over compacted rows -----------------------------
__device__ void attn_block(int b, const float* __restrict__ hcur,
                           float* __restrict__ dst, float* sm)
{
    float* ss   = sm;
    float* red  = sm + 512;
    float* sca  = sm + 520;
    float* wacc = sm + 528;
    int tid = threadIdx.x, lane = tid & 31, w = tid >> 5;
    int Lb = g_Lb[b];

    float qreg[16];
    const float* hb = hcur + b * Hz + lane * 16;
    #pragma unroll
    for (int i = 0; i < 16; i += 4) {
        float4 v = *(const float4*)(hb + i);
        qreg[i] = v.x; qreg[i + 1] = v.y; qreg[i + 2] = v.z; qreg[i + 3] = v.w;
    }

    const __nv_bfloat16* Fb = g_Fc + (size_t)b * LCz * Hz;
    #pragma unroll 4
    for (int l = w; l < Lb; l += 8) {
        const __nv_bfloat16* row = Fb + (size_t)l * Hz + lane * 16;
        uint4 u0 = *(const uint4*)row;
        uint4 u1 = *(const uint4*)(row + 8);
        const __nv_bfloat162* h0 = (const __nv_bfloat162*)&u0;
        const __nv_bfloat162* h1 = (const __nv_bfloat162*)&u1;
        float acc = 0.f;
        #pragma unroll
        for (int i = 0; i < 4; i++) {
            float2 f0 = __bfloat1622float2(h0[i]);
            float2 f1 = __bfloat1622float2(h1[i]);
            acc += f0.x * qreg[2 * i]     + f0.y * qreg[2 * i + 1];
            acc += f1.x * qreg[8 + 2 * i] + f1.y * qreg[8 + 2 * i + 1];
        }
        #pragma unroll
        for (int o = 16; o > 0; o >>= 1) acc += __shfl_xor_sync(0xffffffffu, acc, o);
        if (lane == 0) ss[l] = acc;
    }
    __syncthreads();

    float m = -INFINITY;
    for (int l = tid; l < Lb; l += 256) m = fmaxf(m, ss[l]);
    #pragma unroll
    for (int o = 16; o > 0; o >>= 1) m = fmaxf(m, __shfl_xor_sync(0xffffffffu, m, o));
    if (lane == 0) red[w] = m;
    __syncthreads();
    if (tid == 0) {
        float mm = red[0];
        for (int i = 1; i < 8; i++) mm = fmaxf(mm, red[i]);
        sca[0] = mm;
    }
    __syncthreads();
    float bmax = sca[0];

    float s = 0.f;
    for (int l = tid; l < Lb; l += 256) {
        float e = expf(ss[l] - bmax);
        ss[l] = e;
        s += e;
    }
    #pragma unroll
    for (int o = 16; o > 0; o >>= 1) s += __shfl_xor_sync(0xffffffffu, s, o);
    if (lane == 0) red[w] = s;
    __syncthreads();
    if (tid == 0) {
        float t2 = 0.f;
        for (int i = 0; i < 8; i++) t2 += red[i];
        sca[1] = t2;
    }
    __syncthreads();
    float inv = 1.f / sca[1];

    float acc2[16];
    #pragma unroll
    for (int i = 0; i < 16; i++) acc2[i] = 0.f;
    const __nv_bfloat16* Eb = g_encc + (size_t)b * LCz * Hz;
    #pragma unroll 4
    for (int l = w; l < Lb; l += 8) {
        float d = ss[l];
        const __nv_bfloat16* row = Eb + (size_t)l * Hz + lane * 16;
        uint4 u0 = *(const uint4*)row;
        uint4 u1 = *(const uint4*)(row + 8);
        const __nv_bfloat162* h0 = (const __nv_bfloat162*)&u0;
        const __nv_bfloat162* h1 = (const __nv_bfloat162*)&u1;
        #pragma unroll
        for (int i = 0; i < 4; i++) {
            float2 f0 = __bfloat1622float2(h0[i]);
            float2 f1 = __bfloat1622float2(h1[i]);
            acc2[2 * i]         += d * f0.x;
            acc2[2 * i + 1]     += d * f0.y;
            acc2[8 + 2 * i]     += d * f1.x;
            acc2[8 + 2 * i + 1] += d * f1.y;
        }
    }
    #pragma unroll
    for (int i = 0; i < 16; i++) wacc[w * Hz + lane * 16 + i] = acc2[i];
    __syncthreads();

    for (int h = tid; h < Hz; h += 256) {
        float t2 = 0.f;
        #pragma unroll
        for (int ww = 0; ww < 8; ww++) t2 += wacc[ww * Hz + h];
        dst[b * Hz + h] = t2 * inv;
    }
}

// ---------------- out-proj: 16m x 64n, K=512 per split ----------------------
__device__ void outproj16(const float* __restrict__ h_src,
                          const float* __restrict__ attn_src,
                          const float* __restrict__ out_W,
                          const float* __restrict__ out_b,
                          float* __restrict__ vout, float* sm)
{
    __syncthreads();
    int bid = blockIdx.x, tid = threadIdx.x;
    int m0 = (bid & 7) * 16;
    int idx2 = bid >> 3;
    int n0 = (idx2 & 7) * 64;
    int split = idx2 >> 3;
    const float* Asrc = (split == 0) ? h_src : attn_src;
    float* As = sm;
    float* Ws = sm + 256;
    int m = tid >> 4, ng = tid & 15;
    int ar = tid >> 2, k4 = tid & 3;
    float acc[4] = {0.f, 0.f, 0.f, 0.f};
    const float* ap = Asrc + (size_t)(m0 + (tid < 64 ? ar : 0)) * Hz + k4 * 4;
    const float* wp = out_W + (size_t)(n0 + ar) * (2 * Hz) + split * Hz + k4 * 4;

    for (int k0 = 0; k0 < Hz; k0 += 16) {
        if (tid < 64) {
            float4 av = *(const float4*)(ap + k0);
            As[(k4 * 4 + 0) * 16 + ar] = av.x;
            As[(k4 * 4 + 1) * 16 + ar] = av.y;
            As[(k4 * 4 + 2) * 16 + ar] = av.z;
            As[(k4 * 4 + 3) * 16 + ar] = av.w;
        }
        {
            float4 wv = *(const float4*)(wp + k0);
            Ws[(k4 * 4 + 0) * 64 + ar] = wv.x;
            Ws[(k4 * 4 + 1) * 64 + ar] = wv.y;
            Ws[(k4 * 4 + 2) * 64 + ar] = wv.z;
            Ws[(k4 * 4 + 3) * 64 + ar] = wv.w;
        }
        __syncthreads();
        #pragma unroll
        for (int kk = 0; kk < 16; kk++) {
            float a = As[kk * 16 + m];
            float4 wv4 = *(const float4*)&Ws[kk * 64 + ng * 4];
            acc[0] += a * wv4.x; acc[1] += a * wv4.y;
            acc[2] += a * wv4.z; acc[3] += a * wv4.w;
        }
        __syncthreads();
    }
    #pragma unroll
    for (int i = 0; i < 4; i++) {
        int n = n0 + ng * 4 + i;
        float v = acc[i] + ((split == 0) ? out_b[n] : 0.f);
        vout[(size_t)split * BHS + (m0 + m) * Hz + n] = v;
    }
}

// ---------------- logits + masked CE ----------------------------------------
__device__ void logits_ce(int b, int tt, const int* __restrict__ E,
                          const float* __restrict__ vp,
                          const float* __restrict__ voc_b, float* sm)
{
    float* st = sm;
    float* sl = sm + 512;
    int tid = threadIdx.x, lane = tid & 31, w = tid >> 5;
    __syncthreads();

    for (int i = tid; i < Hz; i += 256)
        st[i] = tanhf(vp[b * Hz + i] + vp[BHS + b * Hz + i]);
    __syncthreads();

    float sreg[16];
    #pragma unroll
    for (int i = 0; i < 16; i++) sreg[i] = st[lane * 16 + i];

    for (int v = w; v < Vz; v += 8) {
        const __nv_bfloat16* wr = g_vocb16 + (size_t)v * Hz + lane * 16;
        uint4 u0 = *(const uint4*)wr;
        uint4 u1 = *(const uint4*)(wr + 8);
        const __nv_bfloat162* h0 = (const __nv_bfloat162*)&u0;
        const __nv_bfloat162* h1 = (const __nv_bfloat162*)&u1;
        float acc = 0.f;
        #pragma unroll
        for (int i = 0; i < 4; i++) {
            float2 f0 = __bfloat1622float2(h0[i]);
            float2 f1 = __bfloat1622float2(h1[i]);
            acc += f0.x * sreg[2 * i]     + f0.y * sreg[2 * i + 1];
            acc += f1.x * sreg[8 + 2 * i] + f1.y * sreg[8 + 2 * i + 1];
        }
        #pragma unroll
        for (int o = 16; o > 0; o >>= 1) acc += __shfl_xor_sync(0xffffffffu, acc, o);
        if (lane == 0) sl[v] = acc + voc_b[v];
    }
    __syncthreads();

    if (w == 0) {
        float m = -INFINITY;
        for (int v = lane; v < Vz; v += 32) m = fmaxf(m, sl[v]);
        #pragma unroll
        for (int o = 16; o > 0; o >>= 1) m = fmaxf(m, __shfl_xor_sync(0xffffffffu, m, o));
        float s = 0.f;
        for (int v = lane; v < Vz; v += 32) s += expf(sl[v] - m);
        #pragma unroll
        for (int o = 16; o > 0; o >>= 1) s += __shfl_xor_sync(0xffffffffu, s, o);
        if (lane == 0) {
            int tv = E[b * LEz + tt + 1];
            int idx = b * TDEC + tt;
            if (tv != 0) { g_nll[idx] = m + logf(s) - sl[tv]; g_msk[idx] = 1.f; }
            else         { g_nll[idx] = 0.f;                  g_msk[idx] = 0.f; }
        }
    }
}

// ---------------- the single persistent kernel ------------------------------
__global__ void __launch_bounds__(256, 1) persist_kernel(
    const float* __restrict__ C,       const int* __restrict__ C_pad,
    const int* __restrict__ E,         const float* __restrict__ E_emb,
    const float* __restrict__ enc_Wih, const float* __restrict__ enc_Whh,
    const float* __restrict__ enc_bih, const float* __restrict__ enc_bhh,
    const float* __restrict__ dec_Wih, const float* __restrict__ dec_Whh,
    const float* __restrict__ dec_bih, const float* __restrict__ dec_bhh,
    const float* __restrict__ att_W,   const float* __restrict__ out_W,
    const float* __restrict__ out_b,   const float* __restrict__ voc_W,
    const float* __restrict__ voc_b,   float* __restrict__ out)
{
    extern __shared__ __align__(16) float4 dsm[];
    float4* Wp  = dsm;
    float4* Ab  = dsm + 9216;
    float*  scr = (float*)(dsm + 11264);

    int bid = blockIdx.x, tid = threadIdx.x;
    int lane = tid & 31, w = tid >> 5;
    int mh = bid & 1, nb = bid >> 1;

    // ---- init ----
    for (int i = bid * 256 + tid; i < BHS; i += NBLK * 256) { g_h[0][i] = 0.f; g_c[i] = 0.f; }
    float* vpf = (float*)g_vp;
    for (int i = bid * 256 + tid; i < 4 * BHS; i += NBLK * 256) vpf[i] = 0.f;
    float* apf = (float*)g_attn2;
    for (int i = bid * 256 + tid; i < 2 * BHS; i += NBLK * 256) apf[i] = 0.f;
    for (int i = bid * 256 + tid; i < Vz * Hz; i += NBLK * 256)
        g_vocb16[i] = __float2bfloat16(voc_W[i]);
    gsync();

    // ---- encoder ----
    pack_W3(Wp, nb, 80, enc_Wih, Vz, Vz, enc_Whh, Hz, Hz, enc_Whh, Hz);
    __syncthreads();
    float biasE[2][4];
    load_bias2(biasE, enc_bih, enc_bhh, nullptr, nb);
    for (int t = 0; t < LCz; t++) {
        gates_step<false>(Wp, Ab, C, t, g_h[t & 1], g_h[1 - (t & 1)],
                          nullptr, mh, nb, biasE, nullptr);
        gsync();
    }

    // ---- pre-decoder: compaction, F, u ----
    comp_scan(bid, C_pad, scr);
    build_F(bid, att_W, (float*)dsm);
    calc_u(bid, out_W, out_b, scr);
    gsync();

    // ---- composition + t=0 correction ----
    compose(dec_Wih, dec_Whh, dec_bih, dec_bhh, out_W, out_b);
    calc_c(bid, dec_Wih, scr);
    gsync();

    // ---- decoder ----
    pack_W3(Wp, nb, 144, dec_Wih, Vz + Hz, Vz, g_Weff, Hz, Hz, g_Wcomp, Hz);
    __syncthreads();
    float biasD[2][4];
    load_bias2(biasD, dec_bih, dec_bhh, g_beff, nb);

    for (int t = 0; t < TDEC; t++) {
        // Phase A: gates from [Xemb | h(t-1) | attn(t-1)] + cell ; CE(t-2)
        gates_step<true>(Wp, Ab, E_emb, t, g_h[t & 1], g_h[1 - (t & 1)],
                         g_attn2[(t + 1) & 1], mh, nb, biasD,
                         (t == 0) ? g_corr : nullptr);
        if (t >= 2) logits_ce(bid, t - 2, E, (const float*)g_vp[t & 1], voc_b, scr);
        gsync();

        // Phase B: attn(t) ; V(t-1) for CE
        attn_block(bid, g_h[1 - (t & 1)], g_attn2[t & 1], scr);
        if (t >= 1)
            outproj16(g_h[t & 1], g_attn2[(t + 1) & 1], out_W, out_b,
                      (float*)g_vp[(t + 1) & 1], scr);
        gsync();
    }

    // ---- epilogue: V(510), CE(509), CE(510) ----
    outproj16(g_h[1], g_attn2[0], out_W, out_b, (float*)g_vp[0], scr);
    logits_ce(bid, TDEC - 2, E, (const float*)g_vp[1], voc_b, scr);
    gsync();
    logits_ce(bid, TDEC - 1, E, (const float*)g_vp[0], voc_b, scr);
    gsync();

    // ---- deterministic reduction ----
    {
        float s = 0.f, c = 0.f;
        for (int i = tid; i < TDEC; i += 256) {
            s += g_nll[bid * TDEC + i];
            c += g_msk[bid * TDEC + i];
        }
        #pragma unroll
        for (int o = 16; o > 0; o >>= 1) {
            s += __shfl_xor_sync(0xffffffffu, s, o);
            c += __shfl_xor_sync(0xffffffffu, c, o);
        }
        __syncthreads();
        if (lane == 0) { scr[w] = s; scr[8 + w] = c; }
        __syncthreads();
        if (tid == 0) {
            float ts = 0.f, tc = 0.f;
            for (int i = 0; i < 8; i++) { ts += scr[i]; tc += scr[8 + i]; }
            g_ps[bid] = ts; g_pc[bid] = tc;
        }
    }
    gsync();
    if (bid == 0 && tid == 0) {
        float ts = 0.f, tc = 0.f;
        for (int i = 0; i < NBLK; i++) { ts += g_ps[i]; tc += g_pc[i]; }
        out[0] = ts / fmaxf(tc, 1.f);
    }
}

// ---------------- host entry ------------------------------------------------
extern "C" void kernel_launch(void* const* d_in, const int* in_sizes, int n_in,
                              void* d_out, int out_size)
{
    cudaFuncSetAttribute((const void*)persist_kernel,
                         cudaFuncAttributeMaxDynamicSharedMemorySize, SMEM_BYTES);
    persist_kernel<<<NBLK, 256, SMEM_BYTES>>>(
        (const float*)d_in[0],  (const int*)d_in[1],
        (const int*)d_in[2],    (const float*)d_in[3],
        (const float*)d_in[4],  (const float*)d_in[5],
        (const float*)d_in[6],  (const float*)d_in[7],
        (const float*)d_in[8],  (const float*)d_in[9],
        (const float*)d_in[10], (const float*)d_in[11],
        (const float*)d_in[12], (const float*)d_in[13],
        (const float*)d_in[14], (const float*)d_in[15],
        (const float*)d_in[16], (float*)d_out);
}

// round 9
// speedup vs baseline: 1.4102x; 1.1390x over previous
#include <cuda_runtime.h>
#include <cuda_bf16.h>
#include <math.h>
#include <stdint.h>

#define Bz   128
#define LCz  512
#define LEz  512
#define Hz   512
#define Vz   128
#define TDEC 511
#define NBLK 128
#define BHS  (Bz * Hz)   // 65536

// dynamic smem (float4 units):
//   Wp  [0, 9216)      : W fragment pack (144KB)
//   Ab  [9216, 12288)  : A staging, 6 stages x 512 f4 (48KB)
//   scr [12288, 13824) : 6144 floats scratch (24KB)
#define SMEM_BYTES 221184

// ---------------- static device scratch -------------------------------------
__device__ __align__(16) float g_h[2][BHS];
__device__ __align__(16) float g_c[BHS];
__device__ __align__(16) float g_vp[2][2][BHS];     // [parity][k-split]
__device__ __align__(16) float g_attn2[2][BHS];     // attn, parity-buffered
__device__ __align__(16) __nv_bfloat16 g_enc [(size_t)Bz * LCz * Hz];
__device__ __align__(16) __nv_bfloat16 g_encc[(size_t)Bz * LCz * Hz];
__device__ __align__(16) __nv_bfloat16 g_Fc  [(size_t)Bz * LCz * Hz];
__device__ __align__(16) __nv_bfloat16 g_vocb16[Vz * Hz];
__device__ __align__(16) float g_Weff [2048 * Hz];  // Whh + Wv@Wo_h
__device__ __align__(16) float g_Wcomp[2048 * Hz];  // Wv@Wo_a
__device__ float g_beff[2048];
__device__ float g_u[Bz * Hz];
__device__ float g_corr[Bz * 2048];
__device__ int g_lidx[Bz * LCz];
__device__ int g_Lb[Bz];
__device__ float g_nll[Bz * TDEC];
__device__ float g_msk[Bz * TDEC];
__device__ float g_ps[NBLK], g_pc[NBLK];
// full-grid hierarchical barrier
__device__ unsigned g_arr1[16 * 32];
__device__ unsigned g_arr0;
__device__ volatile unsigned g_gen;
// per-half (64-block) barriers, 128B apart
__device__ unsigned g_garr2[2 * 32];
__device__ volatile unsigned g_ggen2[2 * 32];

__device__ __forceinline__ float sigm(float x) { return 1.f / (1.f + expf(-x)); }

__device__ __forceinline__ uint32_t s2u(const void* p) {
    return (uint32_t)__cvta_generic_to_shared(p);
}
__device__ __forceinline__ uint32_t f2tf32(uint32_t raw) {
    uint32_t u;
    float x = __uint_as_float(raw);
    asm("cvt.rna.tf32.f32 %0, %1;" : "=r"(u) : "f"(x));
    return u;
}
__device__ __forceinline__ void mma8(float acc[4],
    uint32_t a0, uint32_t a1, uint32_t a2, uint32_t a3,
    uint32_t b0, uint32_t b1)
{
    asm volatile("mma.sync.aligned.m16n8k8.row.col.f32.tf32.tf32.f32 "
        "{%0,%1,%2,%3},{%4,%5,%6,%7},{%8,%9},{%0,%1,%2,%3};"
        : "+f"(acc[0]), "+f"(acc[1]), "+f"(acc[2]), "+f"(acc[3])
        : "r"(a0), "r"(a1), "r"(a2), "r"(a3), "r"(b0), "r"(b1));
}
#define CPA16(dst, src) asm volatile("cp.async.cg.shared.global [%0], [%1], 16;" :: "r"(dst), "l"(src))
#define CPA_COMMIT()    asm volatile("cp.async.commit_group;")
#define CPA_WAIT4()     asm volatile("cp.async.wait_group 4;")

// ---------------- full-grid barrier (rare) ----------------------------------
__device__ __forceinline__ void gsync_all() {
    __syncthreads();
    if (threadIdx.x == 0) {
        __threadfence();
        unsigned gen = g_gen;
        unsigned grp = blockIdx.x >> 3;
        if (atomicAdd(&g_arr1[grp * 32], 1u) == 7u) {
            if (atomicAdd(&g_arr0, 1u) == 15u) {
                #pragma unroll
                for (int i = 0; i < 16; i++) g_arr1[i * 32] = 0u;
                g_arr0 = 0u;
                __threadfence();
                g_gen = gen + 1u;
            } else {
                while (g_gen == gen) __nanosleep(32);
            }
        } else {
            while (g_gen == gen) __nanosleep(32);
        }
        __threadfence();
    }
    __syncthreads();
}

// ---------------- per-half barrier (64 blocks) ------------------------------
__device__ __forceinline__ void gsync_g(int mh) {
    __syncthreads();
    if (threadIdx.x == 0) {
        __threadfence();
        unsigned gen = g_ggen2[mh * 32];
        if (atomicAdd(&g_garr2[mh * 32], 1u) == 63u) {
            g_garr2[mh * 32] = 0u;
            __threadfence();
            g_ggen2[mh * 32] = gen + 1u;
        } else {
            while (g_ggen2[mh * 32] == gen) __nanosleep(32);
        }
        __threadfence();
    }
    __syncthreads();
}

// ---------------- W fragment pack: 3 K-segments -----------------------------
__device__ __forceinline__ float wget(int grow, int k,
    const float* W0, int ld0, int K0,
    const float* W1, int ld1, int K1,
    const float* W2, int ld2)
{
    if (k < K0) return W0[(size_t)grow * ld0 + k];
    if (k < K0 + K1) return W1[(size_t)grow * ld1 + (k - K0)];
    return W2[(size_t)grow * ld2 + (k - K0 - K1)];
}

__device__ void pack_W3(float4* Wp, int nb, int KS,
    const float* W0, int ld0, int K0,
    const float* W1, int ld1, int K1,
    const float* W2, int ld2)
{
    for (int idx = threadIdx.x; idx < 2 * KS * 32; idx += 256) {
        int wn  = idx / (KS * 32);
        int rem = idx - wn * (KS * 32);
        int s = rem >> 5, l = rem & 31;
        int gid = l >> 2, tig = l & 3;
        int k0 = s * 8 + tig, k1 = k0 + 4;
        float v[4];
        #pragma unroll
        for (int hh = 0; hh < 2; hh++) {
            int c = hh * 8 + gid;
            int jj = wn * 4 + (c >> 2);
            int gate = c & 3;
            int grow = gate * Hz + nb * 8 + jj;
            v[hh * 2]     = wget(grow, k0, W0, ld0, K0, W1, ld1, K1, W2, ld2);
            v[hh * 2 + 1] = wget(grow, k1, W0, ld0, K0, W1, ld1, K1, W2, ld2);
        }
        float4 o;
        o.x = __uint_as_float(f2tf32(__float_as_uint(v[0])));
        o.y = __uint_as_float(f2tf32(__float_as_uint(v[1])));
        o.z = __uint_as_float(f2tf32(__float_as_uint(v[2])));
        o.w = __uint_as_float(f2tf32(__float_as_uint(v[3])));
        Wp[idx] = o;
    }
}

// ---------------- gates GEMM with cp.async 6-stage pipeline -----------------
__device__ __forceinline__ void issue_stage(uint32_t abase, int buf, int cc,
    const float* s0, const float* s1, const float* s2, int quad, int mrow)
{
    #pragma unroll
    for (int u = 0; u < 2; u++) {
        int kf4 = cc * 8 + quad * 2 + u;
        const float* src = (kf4 < 32) ? (s0 + kf4 * 4)
                         : (kf4 < 160) ? (s1 + (kf4 - 32) * 4)
                                       : (s2 + (kf4 - 160) * 4);
        int col = (quad * 2 + u) ^ (mrow & 7);
        uint32_t dst = abase + (uint32_t)(buf * 512 + mrow * 8 + col) * 16;
        CPA16(dst, src);
    }
}

template<bool DEC>
__device__ void gates_step(
    const float4* __restrict__ Wp, float4* __restrict__ Ab,
    const float* __restrict__ xbase, int t,
    const float* __restrict__ hin, float* __restrict__ hout,
    const float* __restrict__ attnprev,
    int mh, int nb, const float bias[2][4], const float* __restrict__ corr)
{
    const int NCH = DEC ? 36 : 20;
    const int KS  = DEC ? 144 : 80;
    int tid = threadIdx.x;
    int l = tid & 31, wrp = tid >> 5;
    int wm = wrp & 3, wn = wrp >> 2;
    int gid = l >> 2, t0 = l & 3;
    int quad = tid & 3, mrow = tid >> 2;
    int m16 = mh * 64 + wm * 16;
    int arow = wm * 16 + ((l >> 3) & 1) * 8 + (l & 7);
    int halfsel = l >> 4;

    int bS = mh * 64 + mrow;
    const float* s0 = xbase + ((size_t)bS * (DEC ? LEz : LCz) + t) * Vz;
    const float* s1 = hin + bS * Hz;
    const float* s2 = DEC ? (attnprev + bS * Hz) : s1;

    uint32_t abase = s2u(Ab);
    // prologue: 5 stages in flight
    #pragma unroll
    for (int p = 0; p < 5; p++) {
        issue_stage(abase, p, p, s0, s1, s2, quad, mrow);
        CPA_COMMIT();
    }

    float acc[2][4];
    #pragma unroll
    for (int i = 0; i < 2; i++)
        #pragma unroll
        for (int k = 0; k < 4; k++) acc[i][k] = 0.f;

    int buf = 0, nbuf = 5;
    for (int cc = 0; cc < NCH; cc++) {
        CPA_WAIT4();
        __syncthreads();
        uint32_t ab = abase + (uint32_t)(buf * 512) * 16;
        #pragma unroll
        for (int s4 = 0; s4 < 4; s4++) {
            int ccol = (2 * s4 + halfsel) ^ (arow & 7);
            uint32_t addr = ab + (uint32_t)((arow * 8 + ccol) * 16);
            uint32_t q0, q1, q2, q3;
            asm volatile("ldmatrix.sync.aligned.m8n8.x4.shared.b16 {%0,%1,%2,%3}, [%4];"
                         : "=r"(q0), "=r"(q1), "=r"(q2), "=r"(q3) : "r"(addr));
            uint32_t a0 = f2tf32(q0), a1 = f2tf32(q1), a2 = f2tf32(q2), a3 = f2tf32(q3);
            float4 wv = Wp[((size_t)wn * KS + (cc * 4 + s4)) * 32 + l];
            mma8(acc[0], a0, a1, a2, a3, __float_as_uint(wv.x), __float_as_uint(wv.y));
            mma8(acc[1], a0, a1, a2, a3, __float_as_uint(wv.z), __float_as_uint(wv.w));
        }
        if (cc + 5 < NCH) {
            issue_stage(abase, nbuf, cc + 5, s0, s1, s2, quad, mrow);
            CPA_COMMIT();
        }
        if (++buf == 6) buf = 0;
        if (++nbuf == 6) nbuf = 0;
    }

    // cell epilogue
    bool evn = ((t0 & 1) == 0);
    #pragma unroll
    for (int hh = 0; hh < 2; hh++) {
        float d0 = acc[hh][0], d1 = acc[hh][1], d2 = acc[hh][2], d3 = acc[hh][3];
        float x0 = __shfl_xor_sync(0xffffffffu, d0, 1);
        float x1 = __shfl_xor_sync(0xffffffffu, d1, 1);
        float x2 = __shfl_xor_sync(0xffffffffu, d2, 1);
        float x3 = __shfl_xor_sync(0xffffffffu, d3, 1);
        int j = nb * 8 + wn * 4 + hh * 2 + (t0 >> 1);
        int b = m16 + gid + (evn ? 0 : 8);
        float gi = (evn ? d0 : x2) + bias[hh][0];
        float gf = (evn ? d1 : x3) + bias[hh][1];
        float gg = (evn ? x0 : d2) + bias[hh][2];
        float go = (evn ? x1 : d3) + bias[hh][3];
        if (corr) {
            gi -= corr[b * 2048 + j];
            gf -= corr[b * 2048 + 512 + j];
            gg -= corr[b * 2048 + 1024 + j];
            go -= corr[b * 2048 + 1536 + j];
        }
        float c  = g_c[b * Hz + j];
        float cn = sigm(gf) * c + sigm(gi) * tanhf(gg);
        float hn = sigm(go) * tanhf(cn);
        g_c[b * Hz + j] = cn;
        hout[b * Hz + j] = hn;
        if (!DEC)
            g_enc[((size_t)b * LCz + t) * Hz + j] = __float2bfloat16(hn);
    }
}

__device__ __forceinline__ void load_bias2(float bias[2][4],
    const float* __restrict__ bih, const float* __restrict__ bhh,
    const float* __restrict__ beff, int nb)
{
    int l = threadIdx.x & 31;
    int wn = (threadIdx.x >> 5) >> 2;
    int t0 = l & 3;
    #pragma unroll
    for (int hh = 0; hh < 2; hh++) {
        int j = nb * 8 + wn * 4 + hh * 2 + (t0 >> 1);
        #pragma unroll
        for (int g4 = 0; g4 < 4; g4++)
            bias[hh][g4] = beff ? beff[g4 * Hz + j] : (bih[g4 * Hz + j] + bhh[g4 * Hz + j]);
    }
}

// ---------------- pad compaction + F build + u ------------------------------
__device__ void comp_scan(int b, const int* __restrict__ C_pad, float* smf)
{
    int* sm = (int*)smf;
    int tid = threadIdx.x, lane = tid & 31, w = tid >> 5;
    int l0 = tid * 2, l1 = tid * 2 + 1;
    int f0 = (C_pad[b * LCz + l0] == 0) ? 1 : 0;
    int f1 = (C_pad[b * LCz + l1] == 0) ? 1 : 0;
    int s = f0 + f1;
    int x = s;
    #pragma unroll
    for (int o = 1; o < 32; o <<= 1) {
        int y = __shfl_up_sync(0xffffffffu, x, o);
        if (lane >= o) x += y;
    }
    if (lane == 31) sm[w] = x;
    __syncthreads();
    if (tid == 0) {
        int run = 0;
        for (int i = 0; i < 8; i++) { int v = sm[i]; sm[8 + i] = run; run += v; }
        sm[16] = run;
    }
    __syncthreads();
    int excl = sm[8 + w] + x - s;
    if (f0) g_lidx[b * LCz + excl] = l0;
    if (f1) g_lidx[b * LCz + excl + f0] = l1;
    if (tid == 0) g_Lb[b] = sm[16];
    __syncthreads();
}

__device__ void build_F(int b, const float* __restrict__ att_W, float* se)
{
    int tid = threadIdx.x;
    int Lb = g_Lb[b];
    for (int ci0 = 0; ci0 < Lb; ci0 += 32) {
        int R = min(32, Lb - ci0);
        for (int idx = tid; idx < R * 512; idx += 256) {
            int r = idx >> 9, j = idx & 511;
            int l = g_lidx[b * LCz + ci0 + r];
            __nv_bfloat16 hv = g_enc[((size_t)b * LCz + l) * Hz + j];
            se[j * 36 + r] = __bfloat162float(hv);
            g_encc[((size_t)b * LCz + ci0 + r) * Hz + j] = hv;
        }
        __syncthreads();
        #pragma unroll
        for (int half = 0; half < 2; half++) {
            int k = tid + half * 256;
            float acc[32];
            #pragma unroll
            for (int i = 0; i < 32; i++) acc[i] = 0.f;
            for (int j = 0; j < 512; j++) {
                float wv = att_W[j * Hz + k];
                #pragma unroll
                for (int g4 = 0; g4 < 8; g4++) {
                    float4 e = *(const float4*)&se[j * 36 + g4 * 4];
                    acc[g4 * 4 + 0] += e.x * wv;
                    acc[g4 * 4 + 1] += e.y * wv;
                    acc[g4 * 4 + 2] += e.z * wv;
                    acc[g4 * 4 + 3] += e.w * wv;
                }
            }
            for (int r = 0; r < R; r++)
                g_Fc[((size_t)b * LCz + ci0 + r) * Hz + k] = __float2bfloat16(acc[r]);
        }
        __syncthreads();
    }
}

__device__ void calc_u(int b, const float* __restrict__ out_W,
                       const float* __restrict__ out_b, float* scr)
{
    int tid = threadIdx.x;
    __syncthreads();
    for (int i = tid; i < Hz; i += 256) scr[i] = g_h[0][b * Hz + i];
    __syncthreads();
    for (int v = tid; v < Hz; v += 256) {
        const float* wr = out_W + (size_t)v * (2 * Hz);
        float acc = 0.f;
        for (int h = 0; h < Hz; h += 4) {
            float4 w4 = *(const float4*)(wr + h);
            acc += w4.x * scr[h] + w4.y * scr[h + 1] + w4.z * scr[h + 2] + w4.w * scr[h + 3];
        }
        g_u[b * Hz + v] = acc + out_b[v];
    }
    __syncthreads();
}

// ---------------- weight composition + t=0 correction -----------------------
__device__ void compose(const float* __restrict__ dec_Wih, const float* __restrict__ dec_Whh,
                        const float* __restrict__ dec_bih, const float* __restrict__ dec_bhh,
                        const float* __restrict__ out_W, const float* __restrict__ out_b)
{
    int bid = blockIdx.x, tid = threadIdx.x;
    int g = bid * 16 + (tid >> 4);
    int c0 = (tid & 15) * 32;
    const float* wv = dec_Wih + (size_t)g * (Vz + Hz) + Vz;
    #pragma unroll 1
    for (int pass = 0; pass < 2; pass++) {
        float acc[32];
        #pragma unroll
        for (int i = 0; i < 32; i++) acc[i] = 0.f;
        float accb = 0.f;
        for (int v = 0; v < Hz; v++) {
            float w = wv[v];
            const float* owr = out_W + (size_t)v * (2 * Hz) + pass * Hz + c0;
            #pragma unroll
            for (int i = 0; i < 32; i += 4) {
                float4 o = *(const float4*)(owr + i);
                acc[i] += w * o.x; acc[i + 1] += w * o.y;
                acc[i + 2] += w * o.z; acc[i + 3] += w * o.w;
            }
            if (pass == 0) accb += w * out_b[v];
        }
        if (pass == 0) {
            for (int i = 0; i < 32; i++)
                g_Weff[(size_t)g * Hz + c0 + i] = dec_Whh[(size_t)g * Hz + c0 + i] + acc[i];
            if ((tid & 15) == 0) g_beff[g] = dec_bih[g] + dec_bhh[g] + accb;
        } else {
            for (int i = 0; i < 32; i++)
                g_Wcomp[(size_t)g * Hz + c0 + i] = acc[i];
        }
    }
}

__device__ void calc_c(int b, const float* __restrict__ dec_Wih, float* scr)
{
    int tid = threadIdx.x;
    __syncthreads();
    for (int i = tid; i < Hz; i += 256) scr[i] = g_u[b * Hz + i];
    __syncthreads();
    for (int g = tid; g < 2048; g += 256) {
        const float* wv = dec_Wih + (size_t)g * (Vz + Hz) + Vz;
        float acc = 0.f;
        for (int v = 0; v < Hz; v += 4) {
            float4 w4 = *(const float4*)(wv + v);
            acc += w4.x * scr[v] + w4.y * scr[v + 1] + w4.z * scr[v + 2] + w4.w * scr[v + 3];
        }
        g_corr[b * 2048 + g] = acc;
    }
}

// ---------------- attention over compacted rows -----------------------------
__device__ void attn_block(int b, const float* __restrict__ hcur,
                           float* __restrict__ dst, float* sm)
{
    float* ss   = sm;
    float* red  = sm + 512;
    float* sca  = sm + 520;
    float* wacc = sm + 528;
    int tid = threadIdx.x, lane = tid & 31, w = tid >> 5;
    int Lb = g_Lb[b];

    float qreg[16];
    const float* hb = hcur + b * Hz + lane * 16;
    #pragma unroll
    for (int i = 0; i < 16; i += 4) {
        float4 v = *(const float4*)(hb + i);
        qreg[i] = v.x; qreg[i + 1] = v.y; qreg[i + 2] = v.z; qreg[i + 3] = v.w;
    }

    const __nv_bfloat16* Fb = g_Fc + (size_t)b * LCz * Hz;
    #pragma unroll 4
    for (int l = w; l < Lb; l += 8) {
        const __nv_bfloat16* row = Fb + (size_t)l * Hz + lane * 16;
        uint4 u0 = *(const uint4*)row;
        uint4 u1 = *(const uint4*)(row + 8);
        const __nv_bfloat162* h0 = (const __nv_bfloat162*)&u0;
        const __nv_bfloat162* h1 = (const __nv_bfloat162*)&u1;
        float acc = 0.f;
        #pragma unroll
        for (int i = 0; i < 4; i++) {
            float2 f0 = __bfloat1622float2(h0[i]);
            float2 f1 = __bfloat1622float2(h1[i]);
            acc += f0.x * qreg[2 * i]     + f0.y * qreg[2 * i + 1];
            acc += f1.x * qreg[8 + 2 * i] + f1.y * qreg[8 + 2 * i + 1];
        }
        #pragma unroll
        for (int o = 16; o > 0; o >>= 1) acc += __shfl_xor_sync(0xffffffffu, acc, o);
        if (lane == 0) ss[l] = acc;
    }
    __syncthreads();

    float m = -INFINITY;
    for (int l = tid; l < Lb; l += 256) m = fmaxf(m, ss[l]);
    #pragma unroll
    for (int o = 16; o > 0; o >>= 1) m = fmaxf(m, __shfl_xor_sync(0xffffffffu, m, o));
    if (lane == 0) red[w] = m;
    __syncthreads();
    if (tid == 0) {
        float mm = red[0];
        for (int i = 1; i < 8; i++) mm = fmaxf(mm, red[i]);
        sca[0] = mm;
    }
    __syncthreads();
    float bmax = sca[0];

    float s = 0.f;
    for (int l = tid; l < Lb; l += 256) {
        float e = expf(ss[l] - bmax);
        ss[l] = e;
        s += e;
    }
    #pragma unroll
    for (int o = 16; o > 0; o >>= 1) s += __shfl_xor_sync(0xffffffffu, s, o);
    if (lane == 0) red[w] = s;
    __syncthreads();
    if (tid == 0) {
        float t2 = 0.f;
        for (int i = 0; i < 8; i++) t2 += red[i];
        sca[1] = t2;
    }
    __syncthreads();
    float inv = 1.f / sca[1];

    float acc2[16];
    #pragma unroll
    for (int i = 0; i < 16; i++) acc2[i] = 0.f;
    const __nv_bfloat16* Eb = g_encc + (size_t)b * LCz * Hz;
    #pragma unroll 4
    for (int l = w; l < Lb; l += 8) {
        float d = ss[l];
        const __nv_bfloat16* row = Eb + (size_t)l * Hz + lane * 16;
        uint4 u0 = *(const uint4*)row;
        uint4 u1 = *(const uint4*)(row + 8);
        const __nv_bfloat162* h0 = (const __nv_bfloat162*)&u0;
        const __nv_bfloat162* h1 = (const __nv_bfloat162*)&u1;
        #pragma unroll
        for (int i = 0; i < 4; i++) {
            float2 f0 = __bfloat1622float2(h0[i]);
            float2 f1 = __bfloat1622float2(h1[i]);
            acc2[2 * i]         += d * f0.x;
            acc2[2 * i + 1]     += d * f0.y;
            acc2[8 + 2 * i]     += d * f1.x;
            acc2[8 + 2 * i + 1] += d * f1.y;
        }
    }
    #pragma unroll
    for (int i = 0; i < 16; i++) wacc[w * Hz + lane * 16 + i] = acc2[i];
    __syncthreads();

    for (int h = tid; h < Hz; h += 256) {
        float t2 = 0.f;
        #pragma unroll
        for (int ww = 0; ww < 8; ww++) t2 += wacc[ww * Hz + h];
        dst[b * Hz + h] = t2 * inv;
    }
}

// ---------------- out-proj: pipelined, 16m x 64n, K=512 per split -----------
__device__ void outproj16(const float* __restrict__ h_src,
                          const float* __restrict__ attn_src,
                          const float* __restrict__ out_W,
                          const float* __restrict__ out_b,
                          float* __restrict__ vout, float* sm, int mh)
{
    __syncthreads();
    int bid = blockIdx.x, tid = threadIdx.x;
    int gb = bid >> 1;
    int m0 = mh * 64 + (gb & 3) * 16;
    int n0 = ((gb >> 2) & 7) * 64;
    int split = (gb >> 5) & 1;
    const float* Asrc = (split == 0) ? h_src : attn_src;

    int arow = tid & 15, akg = tid >> 4;     // A loader (tid<64)
    int wr = tid >> 2, wkg = tid & 3;        // W loader (all 256)
    int m = tid >> 4, ng = tid & 15;

    const float* ap = Asrc + (size_t)(m0 + arow) * Hz + akg * 8;
    const float* wp = out_W + (size_t)(n0 + wr) * (2 * Hz) + split * Hz + wkg * 8;

    float4 pa0, pa1, pw0, pw1;
    if (tid < 64) { pa0 = *(const float4*)ap; pa1 = *(const float4*)(ap + 4); }
    pw0 = *(const float4*)wp; pw1 = *(const float4*)(wp + 4);

    float acc[4] = {0.f, 0.f, 0.f, 0.f};
    for (int it = 0; it < 16; it++) {
        float* As = sm + (it & 1) * 2560;
        float* Ws = As + 512;
        if (tid < 64) {
            int kb = akg * 8;
            As[(kb + 0) * 16 + arow] = pa0.x; As[(kb + 1) * 16 + arow] = pa0.y;
            As[(kb + 2) * 16 + arow] = pa0.z; As[(kb + 3) * 16 + arow] = pa0.w;
            As[(kb + 4) * 16 + arow] = pa1.x; As[(kb + 5) * 16 + arow] = pa1.y;
            As[(kb + 6) * 16 + arow] = pa1.z; As[(kb + 7) * 16 + arow] = pa1.w;
        }
        {
            int kb = wkg * 8;
            Ws[(kb + 0) * 64 + wr] = pw0.x; Ws[(kb + 1) * 64 + wr] = pw0.y;
            Ws[(kb + 2) * 64 + wr] = pw0.z; Ws[(kb + 3) * 64 + wr] = pw0.w;
            Ws[(kb + 4) * 64 + wr] = pw1.x; Ws[(kb + 5) * 64 + wr] = pw1.y;
            Ws[(kb + 6) * 64 + wr] = pw1.z; Ws[(kb + 7) * 64 + wr] = pw1.w;
        }
        __syncthreads();
        if (it < 15) {
            const float* ap2 = ap + (it + 1) * 32;
            const float* wp2 = wp + (it + 1) * 32;
            if (tid < 64) { pa0 = *(const float4*)ap2; pa1 = *(const float4*)(ap2 + 4); }
            pw0 = *(const float4*)wp2; pw1 = *(const float4*)(wp2 + 4);
        }
        #pragma unroll
        for (int kk = 0; kk < 32; kk++) {
            float a = As[kk * 16 + m];
            float4 w4 = *(const float4*)&Ws[kk * 64 + ng * 4];
            acc[0] += a * w4.x; acc[1] += a * w4.y;
            acc[2] += a * w4.z; acc[3] += a * w4.w;
        }
    }
    __syncthreads();
    #pragma unroll
    for (int i = 0; i < 4; i++) {
        int n = n0 + ng * 4 + i;
        float v = acc[i] + ((split == 0) ? out_b[n] : 0.f);
        vout[(size_t)split * BHS + (m0 + m) * Hz + n] = v;
    }
}

// ---------------- logits + masked CE ----------------------------------------
__device__ void logits_ce(int b, int tt, const int* __restrict__ E,
                          const float* __restrict__ vp,
                          const float* __restrict__ voc_b, float* sm)
{
    float* st = sm;
    float* sl = sm + 512;
    int tid = threadIdx.x, lane = tid & 31, w = tid >> 5;
    __syncthreads();

    for (int i = tid; i < Hz; i += 256)
        st[i] = tanhf(vp[b * Hz + i] + vp[BHS + b * Hz + i]);
    __syncthreads();

    float sreg[16];
    #pragma unroll
    for (int i = 0; i < 16; i++) sreg[i] = st[lane * 16 + i];

    for (int v = w; v < Vz; v += 8) {
        const __nv_bfloat16* wr = g_vocb16 + (size_t)v * Hz + lane * 16;
        uint4 u0 = *(const uint4*)wr;
        uint4 u1 = *(const uint4*)(wr + 8);
        const __nv_bfloat162* h0 = (const __nv_bfloat162*)&u0;
        const __nv_bfloat162* h1 = (const __nv_bfloat162*)&u1;
        float acc = 0.f;
        #pragma unroll
        for (int i = 0; i < 4; i++) {
            float2 f0 = __bfloat1622float2(h0[i]);
            float2 f1 = __bfloat1622float2(h1[i]);
            acc += f0.x * sreg[2 * i]     + f0.y * sreg[2 * i + 1];
            acc += f1.x * sreg[8 + 2 * i] + f1.y * sreg[8 + 2 * i + 1];
        }
        #pragma unroll
        for (int o = 16; o > 0; o >>= 1) acc += __shfl_xor_sync(0xffffffffu, acc, o);
        if (lane == 0) sl[v] = acc + voc_b[v];
    }
    __syncthreads();

    if (w == 0) {
        float m = -INFINITY;
        for (int v = lane; v < Vz; v += 32) m = fmaxf(m, sl[v]);
        #pragma unroll
        for (int o = 16; o > 0; o >>= 1) m = fmaxf(m, __shfl_xor_sync(0xffffffffu, m, o));
        float s = 0.f;
        for (int v = lane; v < Vz; v += 32) s += expf(sl[v] - m);
        #pragma unroll
        for (int o = 16; o > 0; o >>= 1) s += __shfl_xor_sync(0xffffffffu, s, o);
        if (lane == 0) {
            int tv = E[b * LEz + tt + 1];
            int idx = b * TDEC + tt;
            if (tv != 0) { g_nll[idx] = m + logf(s) - sl[tv]; g_msk[idx] = 1.f; }
            else         { g_nll[idx] = 0.f;                  g_msk[idx] = 0.f; }
        }
    }
}

// ---------------- the single persistent kernel ------------------------------
__global__ void __launch_bounds__(256, 1) persist_kernel(
    const float* __restrict__ C,       const int* __restrict__ C_pad,
    const int* __restrict__ E,         const float* __restrict__ E_emb,
    const float* __restrict__ enc_Wih, const float* __restrict__ enc_Whh,
    const float* __restrict__ enc_bih, const float* __restrict__ enc_bhh,
    const float* __restrict__ dec_Wih, const float* __restrict__ dec_Whh,
    const float* __restrict__ dec_bih, const float* __restrict__ dec_bhh,
    const float* __restrict__ att_W,   const float* __restrict__ out_W,
    const float* __restrict__ out_b,   const float* __restrict__ voc_W,
    const float* __restrict__ voc_b,   float* __restrict__ out)
{
    extern __shared__ __align__(16) float4 dsm[];
    float4* Wp  = dsm;
    float4* Ab  = dsm + 9216;
    float*  scr = (float*)(dsm + 12288);

    int bid = blockIdx.x, tid = threadIdx.x;
    int lane = tid & 31, w = tid >> 5;
    int mh = bid & 1, nb = bid >> 1;
    int mhb = mh * 64 + nb;              // this block's own batch

    // ---- init (shared state) ----
    for (int i = bid * 256 + tid; i < BHS; i += NBLK * 256) { g_h[0][i] = 0.f; g_c[i] = 0.f; }
    float* vpf = (float*)g_vp;
    for (int i = bid * 256 + tid; i < 4 * BHS; i += NBLK * 256) vpf[i] = 0.f;
    float* apf = (float*)g_attn2;
    for (int i = bid * 256 + tid; i < 2 * BHS; i += NBLK * 256) apf[i] = 0.f;
    for (int i = bid * 256 + tid; i < Vz * Hz; i += NBLK * 256)
        g_vocb16[i] = __float2bfloat16(voc_W[i]);
    gsync_all();

    // ---- encoder (group-scoped recurrence) ----
    pack_W3(Wp, nb, 80, enc_Wih, Vz, Vz, enc_Whh, Hz, Hz, enc_Whh, Hz);
    __syncthreads();
    float biasE[2][4];
    load_bias2(biasE, enc_bih, enc_bhh, nullptr, nb);
    for (int t = 0; t < LCz; t++) {
        gates_step<false>(Wp, Ab, C, t, g_h[t & 1], g_h[1 - (t & 1)],
                          nullptr, mh, nb, biasE, nullptr);
        gsync_g(mh);
    }

    // ---- pre-decoder: compaction, F, u, corr (own batch; group-scoped) -----
    comp_scan(mhb, C_pad, scr);
    build_F(mhb, att_W, (float*)dsm);
    calc_u(mhb, out_W, out_b, scr);
    calc_c(mhb, dec_Wih, scr);

    // ---- composition (disjoint writes to shared g_Weff) => full barrier ----
    compose(dec_Wih, dec_Whh, dec_bih, dec_bhh, out_W, out_b);
    gsync_all();

    // ---- decoder (group-scoped recurrence) ----
    pack_W3(Wp, nb, 144, dec_Wih, Vz + Hz, Vz, g_Weff, Hz, Hz, g_Wcomp, Hz);
    __syncthreads();
    float biasD[2][4];
    load_bias2(biasD, dec_bih, dec_bhh, g_beff, nb);

    for (int t = 0; t < TDEC; t++) {
        // Phase A: gates from [Xemb | h(t-1) | attn(t-1)] + cell ; CE(t-2)
        gates_step<true>(Wp, Ab, E_emb, t, g_h[t & 1], g_h[1 - (t & 1)],
                         g_attn2[(t + 1) & 1], mh, nb, biasD,
                         (t == 0) ? g_corr : nullptr);
        if (t >= 2) logits_ce(mhb, t - 2, E, (const float*)g_vp[t & 1], voc_b, scr);
        gsync_g(mh);

        // Phase B: attn(t) ; V(t-1) for CE
        attn_block(mhb, g_h[1 - (t & 1)], g_attn2[t & 1], scr);
        if (t >= 1)
            outproj16(g_h[t & 1], g_attn2[(t + 1) & 1], out_W, out_b,
                      (float*)g_vp[(t + 1) & 1], scr, mh);
        gsync_g(mh);
    }

    // ---- epilogue: V(510), CE(509), CE(510) ----
    outproj16(g_h[1], g_attn2[0], out_W, out_b, (float*)g_vp[0], scr, mh);
    logits_ce(mhb, TDEC - 2, E, (const float*)g_vp[1], voc_b, scr);
    gsync_g(mh);
    logits_ce(mhb, TDEC - 1, E, (const float*)g_vp[0], voc_b, scr);

    // ---- per-batch reduction (block-local data) ----
    {
        float s = 0.f, c = 0.f;
        for (int i = tid; i < TDEC; i += 256) {
            s += g_nll[mhb * TDEC + i];
            c += g_msk[mhb * TDEC + i];
        }
        #pragma unroll
        for (int o = 16; o > 0; o >>= 1) {
            s += __shfl_xor_sync(0xffffffffu, s, o);
            c += __shfl_xor_sync(0xffffffffu, c, o);
        }
        __syncthreads();
        if (lane == 0) { scr[w] = s; scr[8 + w] = c; }
        __syncthreads();
        if (tid == 0) {
            float ts = 0.f, tc = 0.f;
            for (int i = 0; i < 8; i++) { ts += scr[i]; tc += scr[8 + i]; }
            g_ps[bid] = ts; g_pc[bid] = tc;
        }
    }
    gsync_all();
    if (bid == 0 && tid == 0) {
        float ts = 0.f, tc = 0.f;
        for (int i = 0; i < NBLK; i++) { ts += g_ps[i]; tc += g_pc[i]; }
        out[0] = ts / fmaxf(tc, 1.f);
    }
}

// ---------------- host entry ------------------------------------------------
extern "C" void kernel_launch(void* const* d_in, const int* in_sizes, int n_in,
                              void* d_out, int out_size)
{
    cudaFuncSetAttribute((const void*)persist_kernel,
                         cudaFuncAttributeMaxDynamicSharedMemorySize, SMEM_BYTES);
    persist_kernel<<<NBLK, 256, SMEM_BYTES>>>(
        (const float*)d_in[0],  (const int*)d_in[1],
        (const int*)d_in[2],    (const float*)d_in[3],
        (const float*)d_in[4],  (const float*)d_in[5],
        (const float*)d_in[6],  (const float*)d_in[7],
        (const float*)d_in[8],  (const float*)d_in[9],
        (const float*)d_in[10], (const float*)d_in[11],
        (const float*)d_in[12], (const float*)d_in[13],
        (const float*)d_in[14], (const float*)d_in[15],
        (const float*)d_in[16], (float*)d_out);
}

// round 11
// speedup vs baseline: 1.5745x; 1.1166x over previous
#include <cuda_runtime.h>
#include <cuda_bf16.h>
#include <math.h>
#include <stdint.h>

#define Bz   128
#define LCz  512
#define LEz  512
#define Hz   512
#define Vz   128
#define TDEC 511
#define NBLK 128
#define BHS  (Bz * Hz)   // 65536

// dynamic smem (float4 units):
//   Wp  [0, 4608)      : bf16 W fragment pack (72KB)
//   Ab  [4608, 6528)   : A staging, 6 stages x 320 f4 (30KB, 5-f4 row stride)
//   scr [6528, 8064)   : 6144 floats scratch (24KB)
#define SMEM_BYTES 129024
#define AROWS 5          // f4 row stride in A staging

// ---------------- static device scratch -------------------------------------
__device__ __align__(16) float g_h[2][BHS];
__device__ __align__(16) __nv_bfloat16 g_hb16[2][BHS];
__device__ __align__(16) float g_c[BHS];
__device__ __align__(16) float g_vp[2][2][BHS];     // [parity][k-split]
__device__ __align__(16) float g_attn2[2][BHS];     // attn fp32, parity
__device__ __align__(16) __nv_bfloat16 g_ab16[2][BHS];
__device__ __align__(16) __nv_bfloat16 g_Cb16[(size_t)Bz * LCz * Vz];   // 16.8MB
__device__ __align__(16) __nv_bfloat16 g_Eb16[(size_t)Bz * LEz * Vz];   // 16.8MB
__device__ __align__(16) __nv_bfloat16 g_enc [(size_t)Bz * LCz * Hz];
__device__ __align__(16) __nv_bfloat16 g_encc[(size_t)Bz * LCz * Hz];
__device__ __align__(16) __nv_bfloat16 g_Fc  [(size_t)Bz * LCz * Hz];
__device__ __align__(16) __nv_bfloat16 g_vocb16[Vz * Hz];
__device__ __align__(16) __nv_bfloat16 g_oWb16[512 * 1024];             // out_W bf16
__device__ __align__(16) float g_Weff [2048 * Hz];  // Whh + Wv@Wo_h
__device__ __align__(16) float g_Wcomp[2048 * Hz];  // Wv@Wo_a
__device__ float g_beff[2048];
__device__ float g_u[Bz * Hz];
__device__ float g_corr[Bz * 2048];
__device__ int g_lidx[Bz * LCz];
__device__ int g_Lb[Bz];
__device__ float g_nll[Bz * TDEC];
__device__ float g_msk[Bz * TDEC];
__device__ float g_ps[NBLK], g_pc[NBLK];
__device__ unsigned g_arr1[16 * 32];
__device__ unsigned g_arr0;
__device__ volatile unsigned g_gen;
__device__ unsigned g_garr2[2 * 32];
__device__ volatile unsigned g_ggen2[2 * 32];

__device__ __forceinline__ float sigm(float x) { return 1.f / (1.f + expf(-x)); }

__device__ __forceinline__ uint32_t s2u(const void* p) {
    return (uint32_t)__cvta_generic_to_shared(p);
}
__device__ __forceinline__ uint32_t bpack(float lo, float hi) {
    __nv_bfloat162 v = __floats2bfloat162_rn(lo, hi);
    return *(uint32_t*)&v;
}
__device__ __forceinline__ void mma16(float acc[4],
    uint32_t a0, uint32_t a1, uint32_t a2, uint32_t a3,
    uint32_t b0, uint32_t b1)
{
    asm volatile("mma.sync.aligned.m16n8k16.row.col.f32.bf16.bf16.f32 "
        "{%0,%1,%2,%3},{%4,%5,%6,%7},{%8,%9},{%0,%1,%2,%3};"
        : "+f"(acc[0]), "+f"(acc[1]), "+f"(acc[2]), "+f"(acc[3])
        : "r"(a0), "r"(a1), "r"(a2), "r"(a3), "r"(b0), "r"(b1));
}
#define CPA16(dst, src) asm volatile("cp.async.cg.shared.global [%0], [%1], 16;" :: "r"(dst), "l"(src))
#define CPA_COMMIT()    asm volatile("cp.async.commit_group;")
#define CPA_WAIT4()     asm volatile("cp.async.wait_group 4;")

// ---------------- full-grid barrier (rare) ----------------------------------
__device__ __forceinline__ void gsync_all() {
    __syncthreads();
    if (threadIdx.x == 0) {
        __threadfence();
        unsigned gen = g_gen;
        unsigned grp = blockIdx.x >> 3;
        if (atomicAdd(&g_arr1[grp * 32], 1u) == 7u) {
            if (atomicAdd(&g_arr0, 1u) == 15u) {
                #pragma unroll
                for (int i = 0; i < 16; i++) g_arr1[i * 32] = 0u;
                g_arr0 = 0u;
                __threadfence();
                g_gen = gen + 1u;
            } else {
                while (g_gen == gen) __nanosleep(32);
            }
        } else {
            while (g_gen == gen) __nanosleep(32);
        }
        __threadfence();
    }
    __syncthreads();
}

// ---------------- per-half barrier (64 blocks) ------------------------------
__device__ __forceinline__ void gsync_g(int mh) {
    __syncthreads();
    if (threadIdx.x == 0) {
        __threadfence();
        unsigned gen = g_ggen2[mh * 32];
        if (atomicAdd(&g_garr2[mh * 32], 1u) == 63u) {
            g_garr2[mh * 32] = 0u;
            __threadfence();
            g_ggen2[mh * 32] = gen + 1u;
        } else {
            while (g_ggen2[mh * 32] == gen) __nanosleep(32);
        }
        __threadfence();
    }
    __syncthreads();
}

// ---------------- W fragment pack (bf16, 3 K-segments) ----------------------
__device__ __forceinline__ float wget(int grow, int k,
    const float* W0, int ld0, int K0,
    const float* W1, int ld1, int K1,
    const float* W2, int ld2)
{
    if (k < K0) return W0[(size_t)grow * ld0 + k];
    if (k < K0 + K1) return W1[(size_t)grow * ld1 + (k - K0)];
    return W2[(size_t)grow * ld2 + (k - K0 - K1)];
}

__device__ void pack_Wb3(uint4* Wp, int nb, int KS16,
    const float* W0, int ld0, int K0,
    const float* W1, int ld1, int K1,
    const float* W2, int ld2)
{
    for (int idx = threadIdx.x; idx < 2 * KS16 * 32; idx += 256) {
        int wn  = idx / (KS16 * 32);
        int rem = idx - wn * (KS16 * 32);
        int s = rem >> 5, l = rem & 31;
        int gid = l >> 2, t0 = l & 3;
        uint32_t r[4];
        #pragma unroll
        for (int hh = 0; hh < 2; hh++) {
            int c = hh * 8 + gid;
            int jj = wn * 4 + (c >> 2);
            int gate = c & 3;
            int grow = gate * Hz + nb * 8 + jj;
            int k0 = s * 16 + t0 * 2;
            float w00 = wget(grow, k0,     W0, ld0, K0, W1, ld1, K1, W2, ld2);
            float w01 = wget(grow, k0 + 1, W0, ld0, K0, W1, ld1, K1, W2, ld2);
            float w10 = wget(grow, k0 + 8, W0, ld0, K0, W1, ld1, K1, W2, ld2);
            float w11 = wget(grow, k0 + 9, W0, ld0, K0, W1, ld1, K1, W2, ld2);
            r[hh * 2]     = bpack(w00, w01);
            r[hh * 2 + 1] = bpack(w10, w11);
        }
        Wp[idx] = make_uint4(r[0], r[1], r[2], r[3]);
    }
}

// ---------------- gates GEMM: bf16 m16n8k16, cp.async 6-stage ---------------
// A (bf16): [x 0..127 | h -> k 128..639 | attn -> k 640..1151]
template<bool DEC>
__device__ __forceinline__ void issue_stage(uint32_t abase, int buf, int cc,
    const __nv_bfloat16* s0, const __nv_bfloat16* s1, const __nv_bfloat16* s2)
{
    int tid = threadIdx.x;
    int row = tid >> 2, c = tid & 3;
    int k = cc * 32 + c * 8;
    const __nv_bfloat16* src;
    if (k < 128) src = s0 + k;
    else if (!DEC || k < 640) src = s1 + (k - 128);
    else src = s2 + (k - 640);
    uint32_t dst = abase + (uint32_t)(buf * (64 * AROWS) + row * AROWS + (c ^ (row & 3))) * 16;
    CPA16(dst, src);
}

template<bool DEC>
__device__ void gates_step(
    const uint4* __restrict__ Wp, float4* __restrict__ Ab,
    const __nv_bfloat16* __restrict__ xbase, int t,
    float* __restrict__ hout,
    const __nv_bfloat16* __restrict__ hb_in,
    const __nv_bfloat16* __restrict__ ab_in,
    __nv_bfloat16* __restrict__ hb_out,
    int mh, int nb, const float bias[2][4], const float* __restrict__ corr)
{
    const int NCH  = DEC ? 36 : 20;    // k32 chunks
    const int KS16 = DEC ? 72 : 40;
    int tid = threadIdx.x;
    int l = tid & 31, wrp = tid >> 5;
    int wm = wrp & 3, wn = wrp >> 2;
    int gid = l >> 2, t0 = l & 3;
    int m16 = mh * 64 + wm * 16;
    int arow = wm * 16 + ((l >> 3) & 1) * 8 + (l & 7);
    int halfsel = l >> 4;

    int rowb = mh * 64 + (tid >> 2);   // this thread's staging row batch
    const __nv_bfloat16* s0 = xbase + (size_t)rowb * ((DEC ? LEz : LCz) * Vz) + (size_t)t * Vz;
    const __nv_bfloat16* s1 = hb_in + rowb * Hz;
    const __nv_bfloat16* s2 = DEC ? (ab_in + rowb * Hz) : s1;

    uint32_t abase = s2u(Ab);
    #pragma unroll
    for (int p = 0; p < 5; p++) {
        issue_stage<DEC>(abase, p, p, s0, s1, s2);
        CPA_COMMIT();
    }

    float acc[2][4];
    #pragma unroll
    for (int i = 0; i < 2; i++)
        #pragma unroll
        for (int k = 0; k < 4; k++) acc[i][k] = 0.f;

    int buf = 0, nbuf = 5;
    for (int cc = 0; cc < NCH; cc++) {
        CPA_WAIT4();
        __syncthreads();
        uint32_t ab = abase + (uint32_t)(buf * (64 * AROWS)) * 16;
        #pragma unroll
        for (int kk = 0; kk < 2; kk++) {
            int ccol = (kk * 2 + halfsel) ^ (arow & 3);
            uint32_t addr = ab + (uint32_t)(arow * AROWS + ccol) * 16;
            uint32_t a0, a1, a2, a3;
            asm volatile("ldmatrix.sync.aligned.m8n8.x4.shared.b16 {%0,%1,%2,%3}, [%4];"
                         : "=r"(a0), "=r"(a1), "=r"(a2), "=r"(a3) : "r"(addr));
            uint4 wv = Wp[((size_t)wn * KS16 + (cc * 2 + kk)) * 32 + l];
            mma16(acc[0], a0, a1, a2, a3, wv.x, wv.y);
            mma16(acc[1], a0, a1, a2, a3, wv.z, wv.w);
        }
        if (cc + 5 < NCH) {
            issue_stage<DEC>(abase, nbuf, cc + 5, s0, s1, s2);
            CPA_COMMIT();
        }
        if (++buf == 6) buf = 0;
        if (++nbuf == 6) nbuf = 0;
    }

    // cell epilogue (same D layout as m16n8k8)
    bool evn = ((t0 & 1) == 0);
    #pragma unroll
    for (int hh = 0; hh < 2; hh++) {
        float d0 = acc[hh][0], d1 = acc[hh][1], d2 = acc[hh][2], d3 = acc[hh][3];
        float x0 = __shfl_xor_sync(0xffffffffu, d0, 1);
        float x1 = __shfl_xor_sync(0xffffffffu, d1, 1);
        float x2 = __shfl_xor_sync(0xffffffffu, d2, 1);
        float x3 = __shfl_xor_sync(0xffffffffu, d3, 1);
        int j = nb * 8 + wn * 4 + hh * 2 + (t0 >> 1);
        int b = m16 + gid + (evn ? 0 : 8);
        float gi = (evn ? d0 : x2) + bias[hh][0];
        float gf = (evn ? d1 : x3) + bias[hh][1];
        float gg = (evn ? x0 : d2) + bias[hh][2];
        float go = (evn ? x1 : d3) + bias[hh][3];
        if (corr) {
            gi -= corr[b * 2048 + j];
            gf -= corr[b * 2048 + 512 + j];
            gg -= corr[b * 2048 + 1024 + j];
            go -= corr[b * 2048 + 1536 + j];
        }
        float c  = g_c[b * Hz + j];
        float cn = sigm(gf) * c + sigm(gi) * tanhf(gg);
        float hn = sigm(go) * tanhf(cn);
        g_c[b * Hz + j] = cn;
        hout[b * Hz + j] = hn;
        hb_out[b * Hz + j] = __float2bfloat16(hn);
        if (!DEC)
            g_enc[((size_t)b * LCz + t) * Hz + j] = __float2bfloat16(hn);
    }
}

__device__ __forceinline__ void load_bias2(float bias[2][4],
    const float* __restrict__ bih, const float* __restrict__ bhh,
    const float* __restrict__ beff, int nb)
{
    int l = threadIdx.x & 31;
    int wn = (threadIdx.x >> 5) >> 2;
    int t0 = l & 3;
    #pragma unroll
    for (int hh = 0; hh < 2; hh++) {
        int j = nb * 8 + wn * 4 + hh * 2 + (t0 >> 1);
        #pragma unroll
        for (int g4 = 0; g4 < 4; g4++)
            bias[hh][g4] = beff ? beff[g4 * Hz + j] : (bih[g4 * Hz + j] + bhh[g4 * Hz + j]);
    }
}

// ---------------- pad compaction + F build + u ------------------------------
__device__ void comp_scan(int b, const int* __restrict__ C_pad, float* smf)
{
    int* sm = (int*)smf;
    int tid = threadIdx.x, lane = tid & 31, w = tid >> 5;
    int l0 = tid * 2, l1 = tid * 2 + 1;
    int f0 = (C_pad[b * LCz + l0] == 0) ? 1 : 0;
    int f1 = (C_pad[b * LCz + l1] == 0) ? 1 : 0;
    int s = f0 + f1;
    int x = s;
    #pragma unroll
    for (int o = 1; o < 32; o <<= 1) {
        int y = __shfl_up_sync(0xffffffffu, x, o);
        if (lane >= o) x += y;
    }
    if (lane == 31) sm[w] = x;
    __syncthreads();
    if (tid == 0) {
        int run = 0;
        for (int i = 0; i < 8; i++) { int v = sm[i]; sm[8 + i] = run; run += v; }
        sm[16] = run;
    }
    __syncthreads();
    int excl = sm[8 + w] + x - s;
    if (f0) g_lidx[b * LCz + excl] = l0;
    if (f1) g_lidx[b * LCz + excl + f0] = l1;
    if (tid == 0) g_Lb[b] = sm[16];
    __syncthreads();
}

__device__ void build_F(int b, const float* __restrict__ att_W, float* se)
{
    int tid = threadIdx.x;
    int Lb = g_Lb[b];
    for (int ci0 = 0; ci0 < Lb; ci0 += 32) {
        int R = min(32, Lb - ci0);
        for (int idx = tid; idx < R * 512; idx += 256) {
            int r = idx >> 9, j = idx & 511;
            int l = g_lidx[b * LCz + ci0 + r];
            __nv_bfloat16 hv = g_enc[((size_t)b * LCz + l) * Hz + j];
            se[j * 36 + r] = __bfloat162float(hv);
            g_encc[((size_t)b * LCz + ci0 + r) * Hz + j] = hv;
        }
        __syncthreads();
        #pragma unroll
        for (int half = 0; half < 2; half++) {
            int k = tid + half * 256;
            float acc[32];
            #pragma unroll
            for (int i = 0; i < 32; i++) acc[i] = 0.f;
            for (int j = 0; j < 512; j++) {
                float wv = att_W[j * Hz + k];
                #pragma unroll
                for (int g4 = 0; g4 < 8; g4++) {
                    float4 e = *(const float4*)&se[j * 36 + g4 * 4];
                    acc[g4 * 4 + 0] += e.x * wv;
                    acc[g4 * 4 + 1] += e.y * wv;
                    acc[g4 * 4 + 2] += e.z * wv;
                    acc[g4 * 4 + 3] += e.w * wv;
                }
            }
            for (int r = 0; r < R; r++)
                g_Fc[((size_t)b * LCz + ci0 + r) * Hz + k] = __float2bfloat16(acc[r]);
        }
        __syncthreads();
    }
}

__device__ void calc_u(int b, const float* __restrict__ out_W,
                       const float* __restrict__ out_b, float* scr)
{
    int tid = threadIdx.x;
    __syncthreads();
    for (int i = tid; i < Hz; i += 256) scr[i] = g_h[0][b * Hz + i];
    __syncthreads();
    for (int v = tid; v < Hz; v += 256) {
        const float* wr = out_W + (size_t)v * (2 * Hz);
        float acc = 0.f;
        for (int h = 0; h < Hz; h += 4) {
            float4 w4 = *(const float4*)(wr + h);
            acc += w4.x * scr[h] + w4.y * scr[h + 1] + w4.z * scr[h + 2] + w4.w * scr[h + 3];
        }
        g_u[b * Hz + v] = acc + out_b[v];
    }
    __syncthreads();
}

// ---------------- weight composition + t=0 correction -----------------------
__device__ void compose(const float* __restrict__ dec_Wih, const float* __restrict__ dec_Whh,
                        const float* __restrict__ dec_bih, const float* __restrict__ dec_bhh,
                        const float* __restrict__ out_W, const float* __restrict__ out_b)
{
    int bid = blockIdx.x, tid = threadIdx.x;
    int g = bid * 16 + (tid >> 4);
    int c0 = (tid & 15) * 32;
    const float* wv = dec_Wih + (size_t)g * (Vz + Hz) + Vz;
    #pragma unroll 1
    for (int pass = 0; pass < 2; pass++) {
        float acc[32];
        #pragma unroll
        for (int i = 0; i < 32; i++) acc[i] = 0.f;
        float accb = 0.f;
        for (int v = 0; v < Hz; v++) {
            float w = wv[v];
            const float* owr = out_W + (size_t)v * (2 * Hz) + pass * Hz + c0;
            #pragma unroll
            for (int i = 0; i < 32; i += 4) {
                float4 o = *(const float4*)(owr + i);
                acc[i] += w * o.x; acc[i + 1] += w * o.y;
                acc[i + 2] += w * o.z; acc[i + 3] += w * o.w;
            }
            if (pass == 0) accb += w * out_b[v];
        }
        if (pass == 0) {
            for (int i = 0; i < 32; i++)
                g_Weff[(size_t)g * Hz + c0 + i] = dec_Whh[(size_t)g * Hz + c0 + i] + acc[i];
            if ((tid & 15) == 0) g_beff[g] = dec_bih[g] + dec_bhh[g] + accb;
        } else {
            for (int i = 0; i < 32; i++)
                g_Wcomp[(size_t)g * Hz + c0 + i] = acc[i];
        }
    }
}

__device__ void calc_c(int b, const float* __restrict__ dec_Wih, float* scr)
{
    int tid = threadIdx.x;
    __syncthreads();
    for (int i = tid; i < Hz; i += 256) scr[i] = g_u[b * Hz + i];
    __syncthreads();
    for (int g = tid; g < 2048; g += 256) {
        const float* wv = dec_Wih + (size_t)g * (Vz + Hz) + Vz;
        float acc = 0.f;
        for (int v = 0; v < Hz; v += 4) {
            float4 w4 = *(const float4*)(wv + v);
            acc += w4.x * scr[v] + w4.y * scr[v + 1] + w4.z * scr[v + 2] + w4.w * scr[v + 3];
        }
        g_corr[b * 2048 + g] = acc;
    }
}

// ---------------- attention over compacted rows -----------------------------
__device__ void attn_block(int b, const float* __restrict__ hcur,
                           float* __restrict__ dst, __nv_bfloat16* __restrict__ dstb,
                           float* sm)
{
    float* ss   = sm;
    float* red  = sm + 512;
    float* sca  = sm + 520;
    float* wacc = sm + 528;
    int tid = threadIdx.x, lane = tid & 31, w = tid >> 5;
    int Lb = g_Lb[b];

    float qreg[16];
    const float* hb = hcur + b * Hz + lane * 16;
    #pragma unroll
    for (int i = 0; i < 16; i += 4) {
        float4 v = *(const float4*)(hb + i);
        qreg[i] = v.x; qreg[i + 1] = v.y; qreg[i + 2] = v.z; qreg[i + 3] = v.w;
    }

    const __nv_bfloat16* Fb = g_Fc + (size_t)b * LCz * Hz;
    #pragma unroll 4
    for (int l = w; l < Lb; l += 8) {
        const __nv_bfloat16* row = Fb + (size_t)l * Hz + lane * 16;
        uint4 u0 = *(const uint4*)row;
        uint4 u1 = *(const uint4*)(row + 8);
        const __nv_bfloat162* h0 = (const __nv_bfloat162*)&u0;
        const __nv_bfloat162* h1 = (const __nv_bfloat162*)&u1;
        float acc = 0.f;
        #pragma unroll
        for (int i = 0; i < 4; i++) {
            float2 f0 = __bfloat1622float2(h0[i]);
            float2 f1 = __bfloat1622float2(h1[i]);
            acc += f0.x * qreg[2 * i]     + f0.y * qreg[2 * i + 1];
            acc += f1.x * qreg[8 + 2 * i] + f1.y * qreg[8 + 2 * i + 1];
        }
        #pragma unroll
        for (int o = 16; o > 0; o >>= 1) acc += __shfl_xor_sync(0xffffffffu, acc, o);
        if (lane == 0) ss[l] = acc;
    }
    __syncthreads();

    float m = -INFINITY;
    for (int l = tid; l < Lb; l += 256) m = fmaxf(m, ss[l]);
    #pragma unroll
    for (int o = 16; o > 0; o >>= 1) m = fmaxf(m, __shfl_xor_sync(0xffffffffu, m, o));
    if (lane == 0) red[w] = m;
    __syncthreads();
    if (tid == 0) {
        float mm = red[0];
        for (int i = 1; i < 8; i++) mm = fmaxf(mm, red[i]);
        sca[0] = mm;
    }
    __syncthreads();
    float bmax = sca[0];

    float s = 0.f;
    for (int l = tid; l < Lb; l += 256) {
        float e = expf(ss[l] - bmax);
        ss[l] = e;
        s += e;
    }
    #pragma unroll
    for (int o = 16; o > 0; o >>= 1) s += __shfl_xor_sync(0xffffffffu, s, o);
    if (lane == 0) red[w] = s;
    __syncthreads();
    if (tid == 0) {
        float t2 = 0.f;
        for (int i = 0; i < 8; i++) t2 += red[i];
        sca[1] = t2;
    }
    __syncthreads();
    float inv = 1.f / sca[1];

    float acc2[16];
    #pragma unroll
    for (int i = 0; i < 16; i++) acc2[i] = 0.f;
    const __nv_bfloat16* Eb = g_encc + (size_t)b * LCz * Hz;
    #pragma unroll 4
    for (int l = w; l < Lb; l += 8) {
        float d = ss[l];
        const __nv_bfloat16* row = Eb + (size_t)l * Hz + lane * 16;
        uint4 u0 = *(const uint4*)row;
        uint4 u1 = *(const uint4*)(row + 8);
        const __nv_bfloat162* h0 = (const __nv_bfloat162*)&u0;
        const __nv_bfloat162* h1 = (const __nv_bfloat162*)&u1;
        #pragma unroll
        for (int i = 0; i < 4; i++) {
            float2 f0 = __bfloat1622float2(h0[i]);
            float2 f1 = __bfloat1622float2(h1[i]);
            acc2[2 * i]         += d * f0.x;
            acc2[2 * i + 1]     += d * f0.y;
            acc2[8 + 2 * i]     += d * f1.x;
            acc2[8 + 2 * i + 1] += d * f1.y;
        }
    }
    #pragma unroll
    for (int i = 0; i < 16; i++) wacc[w * Hz + lane * 16 + i] = acc2[i];
    __syncthreads();

    for (int h = tid; h < Hz; h += 256) {
        float t2 = 0.f;
        #pragma unroll
        for (int ww = 0; ww < 8; ww++) t2 += wacc[ww * Hz + h];
        float v = t2 * inv;
        dst[b * Hz + h] = v;
        dstb[b * Hz + h] = __float2bfloat16(v);
    }
}

// ---------------- out-proj: pipelined, bf16 W, 16m x 64n --------------------
__device__ void outproj16(const float* __restrict__ h_src,
                          const float* __restrict__ attn_src,
                          const float* __restrict__ out_b,
                          float* __restrict__ vout, float* sm, int mh)
{
    __syncthreads();
    int bid = blockIdx.x, tid = threadIdx.x;
    int gb = bid >> 1;
    int m0 = mh * 64 + (gb & 3) * 16;
    int n0 = ((gb >> 2) & 7) * 64;
    int split = (gb >> 5) & 1;
    const float* Asrc = (split == 0) ? h_src : attn_src;

    int arow = tid & 15, akg = tid >> 4;     // A loader (tid<64)
    int wr = tid >> 2, wkg = tid & 3;        // W loader: uint4 = 8 bf16
    int m = tid >> 4, ng = tid & 15;

    const float* ap = Asrc + (size_t)(m0 + arow) * Hz + akg * 8;
    const __nv_bfloat16* wp = g_oWb16 + (size_t)(n0 + wr) * 1024 + split * Hz + wkg * 8;

    float4 pa0, pa1;
    uint4 pw;
    if (tid < 64) { pa0 = *(const float4*)ap; pa1 = *(const float4*)(ap + 4); }
    pw = *(const uint4*)wp;

    float acc[4] = {0.f, 0.f, 0.f, 0.f};
    for (int it = 0; it < 16; it++) {
        float* As = sm + (it & 1) * 2560;
        float* Ws = As + 512;
        if (tid < 64) {
            int kb = akg * 8;
            As[(kb + 0) * 16 + arow] = pa0.x; As[(kb + 1) * 16 + arow] = pa0.y;
            As[(kb + 2) * 16 + arow] = pa0.z; As[(kb + 3) * 16 + arow] = pa0.w;
            As[(kb + 4) * 16 + arow] = pa1.x; As[(kb + 5) * 16 + arow] = pa1.y;
            As[(kb + 6) * 16 + arow] = pa1.z; As[(kb + 7) * 16 + arow] = pa1.w;
        }
        {
            int kb = wkg * 8;
            const __nv_bfloat162* ph = (const __nv_bfloat162*)&pw;
            #pragma unroll
            for (int i = 0; i < 4; i++) {
                float2 f = __bfloat1622float2(ph[i]);
                Ws[(kb + 2 * i) * 64 + wr]     = f.x;
                Ws[(kb + 2 * i + 1) * 64 + wr] = f.y;
            }
        }
        __syncthreads();
        if (it < 15) {
            if (tid < 64) {
                const float* ap2 = ap + (it + 1) * 32;
                pa0 = *(const float4*)ap2; pa1 = *(const float4*)(ap2 + 4);
            }
            pw = *(const uint4*)(wp + (it + 1) * 32);
        }
        #pragma unroll
        for (int kk = 0; kk < 32; kk++) {
            float a = As[kk * 16 + m];
            float4 w4 = *(const float4*)&Ws[kk * 64 + ng * 4];
            acc[0] += a * w4.x; acc[1] += a * w4.y;
            acc[2] += a * w4.z; acc[3] += a * w4.w;
        }
    }
    __syncthreads();
    #pragma unroll
    for (int i = 0; i < 4; i++) {
        int n = n0 + ng * 4 + i;
        float v = acc[i] + ((split == 0) ? out_b[n] : 0.f);
        vout[(size_t)split * BHS + (m0 + m) * Hz + n] = v;
    }
}

// ---------------- logits + masked CE ----------------------------------------
__device__ void logits_ce(int b, int tt, const int* __restrict__ E,
                          const float* __restrict__ vp,
                          const float* __restrict__ voc_b, float* sm)
{
    float* st = sm;
    float* sl = sm + 512;
    int tid = threadIdx.x, lane = tid & 31, w = tid >> 5;
    __syncthreads();

    for (int i = tid; i < Hz; i += 256)
        st[i] = tanhf(vp[b * Hz + i] + vp[BHS + b * Hz + i]);
    __syncthreads();

    float sreg[16];
    #pragma unroll
    for (int i = 0; i < 16; i++) sreg[i] = st[lane * 16 + i];

    for (int v = w; v < Vz; v += 8) {
        const __nv_bfloat16* wr = g_vocb16 + (size_t)v * Hz + lane * 16;
        uint4 u0 = *(const uint4*)wr;
        uint4 u1 = *(const uint4*)(wr + 8);
        const __nv_bfloat162* h0 = (const __nv_bfloat162*)&u0;
        const __nv_bfloat162* h1 = (const __nv_bfloat162*)&u1;
        float acc = 0.f;
        #pragma unroll
        for (int i = 0; i < 4; i++) {
            float2 f0 = __bfloat1622float2(h0[i]);
            float2 f1 = __bfloat1622float2(h1[i]);
            acc += f0.x * sreg[2 * i]     + f0.y * sreg[2 * i + 1];
            acc += f1.x * sreg[8 + 2 * i] + f1.y * sreg[8 + 2 * i + 1];
        }
        #pragma unroll
        for (int o = 16; o > 0; o >>= 1) acc += __shfl_xor_sync(0xffffffffu, acc, o);
        if (lane == 0) sl[v] = acc + voc_b[v];
    }
    __syncthreads();

    if (w == 0) {
        float m = -INFINITY;
        for (int v = lane; v < Vz; v += 32) m = fmaxf(m, sl[v]);
        #pragma unroll
        for (int o = 16; o > 0; o >>= 1) m = fmaxf(m, __shfl_xor_sync(0xffffffffu, m, o));
        float s = 0.f;
        for (int v = lane; v < Vz; v += 32) s += expf(sl[v] - m);
        #pragma unroll
        for (int o = 16; o > 0; o >>= 1) s += __shfl_xor_sync(0xffffffffu, s, o);
        if (lane == 0) {
            int tv = E[b * LEz + tt + 1];
            int idx = b * TDEC + tt;
            if (tv != 0) { g_nll[idx] = m + logf(s) - sl[tv]; g_msk[idx] = 1.f; }
            else         { g_nll[idx] = 0.f;                  g_msk[idx] = 0.f; }
        }
    }
}

// ---------------- the single persistent kernel ------------------------------
__global__ void __launch_bounds__(256, 1) persist_kernel(
    const float* __restrict__ C,       const int* __restrict__ C_pad,
    const int* __restrict__ E,         const float* __restrict__ E_emb,
    const float* __restrict__ enc_Wih, const float* __restrict__ enc_Whh,
    const float* __restrict__ enc_bih, const float* __restrict__ enc_bhh,
    const float* __restrict__ dec_Wih, const float* __restrict__ dec_Whh,
    const float* __restrict__ dec_bih, const float* __restrict__ dec_bhh,
    const float* __restrict__ att_W,   const float* __restrict__ out_W,
    const float* __restrict__ out_b,   const float* __restrict__ voc_W,
    const float* __restrict__ voc_b,   float* __restrict__ out)
{
    extern __shared__ __align__(16) float4 dsm[];
    uint4*  Wp  = (uint4*)dsm;
    float4* Ab  = dsm + 4608;
    float*  scr = (float*)(dsm + 6528);

    int bid = blockIdx.x, tid = threadIdx.x;
    int lane = tid & 31, w = tid >> 5;
    int mh = bid & 1, nb = bid >> 1;
    int mhb = mh * 64 + nb;

    // ---- init + bf16 pre-conversions ----
    for (int i = bid * 256 + tid; i < BHS; i += NBLK * 256) {
        g_h[0][i] = 0.f; g_c[i] = 0.f;
        g_hb16[0][i] = __float2bfloat16(0.f);
        g_ab16[0][i] = __float2bfloat16(0.f);
        g_ab16[1][i] = __float2bfloat16(0.f);
    }
    float* vpf = (float*)g_vp;
    for (int i = bid * 256 + tid; i < 4 * BHS; i += NBLK * 256) vpf[i] = 0.f;
    float* apf = (float*)g_attn2;
    for (int i = bid * 256 + tid; i < 2 * BHS; i += NBLK * 256) apf[i] = 0.f;
    for (int i = bid * 256 + tid; i < Vz * Hz; i += NBLK * 256)
        g_vocb16[i] = __float2bfloat16(voc_W[i]);
    for (size_t i = bid * 256 + tid; i < (size_t)Bz * LCz * Vz; i += NBLK * 256)
        g_Cb16[i] = __float2bfloat16(C[i]);
    for (size_t i = bid * 256 + tid; i < (size_t)Bz * LEz * Vz; i += NBLK * 256)
        g_Eb16[i] = __float2bfloat16(E_emb[i]);
    for (int i = bid * 256 + tid; i < 512 * 1024; i += NBLK * 256)   // out_W is 512x1024
        g_oWb16[i] = __float2bfloat16(out_W[i]);
    gsync_all();

    // ---- encoder ----
    pack_Wb3(Wp, nb, 40, enc_Wih, Vz, Vz, enc_Whh, Hz, Hz, enc_Whh, Hz);
    __syncthreads();
    float biasE[2][4];
    load_bias2(biasE, enc_bih, enc_bhh, nullptr, nb);
    for (int t = 0; t < LCz; t++) {
        gates_step<false>(Wp, Ab, g_Cb16, t, g_h[1 - (t & 1)],
                          g_hb16[t & 1], nullptr, g_hb16[1 - (t & 1)],
                          mh, nb, biasE, nullptr);
        gsync_g(mh);
    }

    // ---- pre-decoder (own batch) ----
    comp_scan(mhb, C_pad, scr);
    build_F(mhb, att_W, (float*)dsm);
    calc_u(mhb, out_W, out_b, scr);
    calc_c(mhb, dec_Wih, scr);

    // ---- composition (shared) => full barrier ----
    compose(dec_Wih, dec_Whh, dec_bih, dec_bhh, out_W, out_b);
    gsync_all();

    // ---- decoder ----
    pack_Wb3(Wp, nb, 72, dec_Wih, Vz + Hz, Vz, g_Weff, Hz, Hz, g_Wcomp, Hz);
    __syncthreads();
    float biasD[2][4];
    load_bias2(biasD, dec_bih, dec_bhh, g_beff, nb);

    for (int t = 0; t < TDEC; t++) {
        // Phase A: gates from [Xemb | h(t-1) | attn(t-1)] + cell ; CE(t-2)
        gates_step<true>(Wp, Ab, g_Eb16, t, g_h[1 - (t & 1)],
                         g_hb16[t & 1], g_ab16[(t + 1) & 1], g_hb16[1 - (t & 1)],
                         mh, nb, biasD, (t == 0) ? g_corr : nullptr);
        if (t >= 2) logits_ce(mhb, t - 2, E, (const float*)g_vp[t & 1], voc_b, scr);
        gsync_g(mh);

        // Phase B: attn(t) ; V(t-1) for CE
        attn_block(mhb, g_h[1 - (t & 1)], g_attn2[t & 1], g_ab16[t & 1], scr);
        if (t >= 1)
            outproj16(g_h[t & 1], g_attn2[(t + 1) & 1], out_b,
                      (float*)g_vp[(t + 1) & 1], scr, mh);
        gsync_g(mh);
    }

    // ---- epilogue: V(510), CE(509), CE(510) ----
    outproj16(g_h[1], g_attn2[0], out_b, (float*)g_vp[0], scr, mh);
    logits_ce(mhb, TDEC - 2, E, (const float*)g_vp[1], voc_b, scr);
    gsync_g(mh);
    logits_ce(mhb, TDEC - 1, E, (const float*)g_vp[0], voc_b, scr);

    // ---- per-batch reduction ----
    {
        float s = 0.f, c = 0.f;
        for (int i = tid; i < TDEC; i += 256) {
            s += g_nll[mhb * TDEC + i];
            c += g_msk[mhb * TDEC + i];
        }
        #pragma unroll
        for (int o = 16; o > 0; o >>= 1) {
            s += __shfl_xor_sync(0xffffffffu, s, o);
            c += __shfl_xor_sync(0xffffffffu, c, o);
        }
        __syncthreads();
        if (lane == 0) { scr[w] = s; scr[8 + w] = c; }
        __syncthreads();
        if (tid == 0) {
            float ts = 0.f, tc = 0.f;
            for (int i = 0; i < 8; i++) { ts += scr[i]; tc += scr[8 + i]; }
            g_ps[bid] = ts; g_pc[bid] = tc;
        }
    }
    gsync_all();
    if (bid == 0 && tid == 0) {
        float ts = 0.f, tc = 0.f;
        for (int i = 0; i < NBLK; i++) { ts += g_ps[i]; tc += g_pc[i]; }
        out[0] = ts / fmaxf(tc, 1.f);
    }
}

// ---------------- host entry ------------------------------------------------
extern "C" void kernel_launch(void* const* d_in, const int* in_sizes, int n_in,
                              void* d_out, int out_size)
{
    cudaFuncSetAttribute((const void*)persist_kernel,
                         cudaFuncAttributeMaxDynamicSharedMemorySize, SMEM_BYTES);
    persist_kernel<<<NBLK, 256, SMEM_BYTES>>>(
        (const float*)d_in[0],  (const int*)d_in[1],
        (const int*)d_in[2],    (const float*)d_in[3],
        (const float*)d_in[4],  (const float*)d_in[5],
        (const float*)d_in[6],  (const float*)d_in[7],
        (const float*)d_in[8],  (const float*)d_in[9],
        (const float*)d_in[10], (const float*)d_in[11],
        (const float*)d_in[12], (const float*)d_in[13],
        (const float*)d_in[14], (const float*)d_in[15],
        (const float*)d_in[16], (float*)d_out);
}

// round 13
// speedup vs baseline: 1.6653x; 1.0576x over previous
#include <cuda_runtime.h>
#include <cuda_bf16.h>
#include <math.h>
#include <stdint.h>

#define Bz   128
#define LCz  512
#define LEz  512
#define Hz   512
#define Vz   128
#define TDEC 511
#define NBLK 128
#define NTHR 512
#define BHS  (Bz * Hz)   // 65536

// dynamic smem (float4 units):
//   Wp   [0, 4608)     : bf16 W fragment pack (72KB)
//   Ab   [4608, 6528)  : A staging, 6 stages x 320 f4 (30KB, 5-f4 row stride)
//   scrA [f4 6528]     : 4624 floats (attn)
//   scrB [scrA+4624]   : 5120 floats (outproj/CE)
#define SMEM_BYTES 143424
#define AROWS 5

#define NB(id) asm volatile("bar.sync %0, 256;" :: "r"(id) : "memory")

// ---------------- static device scratch -------------------------------------
__device__ __align__(16) float g_h[2][BHS];
__device__ __align__(16) __nv_bfloat16 g_hb16[2][BHS];
__device__ __align__(16) float g_c[BHS];
__device__ __align__(16) float g_vp[2][2][BHS];
__device__ __align__(16) float g_attn2[2][BHS];
__device__ __align__(16) __nv_bfloat16 g_ab16[2][BHS];
__device__ __align__(16) __nv_bfloat16 g_Cb16[(size_t)Bz * LCz * Vz];
__device__ __align__(16) __nv_bfloat16 g_Eb16[(size_t)Bz * LEz * Vz];
__device__ __align__(16) __nv_bfloat16 g_enc [(size_t)Bz * LCz * Hz];
__device__ __align__(16) __nv_bfloat16 g_encc[(size_t)Bz * LCz * Hz];
__device__ __align__(16) __nv_bfloat16 g_Fc  [(size_t)Bz * LCz * Hz];
__device__ __align__(16) __nv_bfloat16 g_vocb16[Vz * Hz];
__device__ __align__(16) __nv_bfloat16 g_oWb16[512 * 1024];
__device__ __align__(16) float g_Weff [2048 * Hz];
__device__ __align__(16) float g_Wcomp[2048 * Hz];
__device__ float g_beff[2048];
__device__ float g_u[Bz * Hz];
__device__ float g_corr[Bz * 2048];
__device__ int g_lidx[Bz * LCz];
__device__ int g_Lb[Bz];
__device__ float g_nll[Bz * TDEC];
__device__ float g_msk[Bz * TDEC];
__device__ float g_ps[NBLK], g_pc[NBLK];
__device__ unsigned g_arr1[16 * 32];
__device__ unsigned g_arr0;
__device__ volatile unsigned g_gen;
__device__ unsigned g_garr2[2 * 32];
__device__ volatile unsigned g_ggen2[2 * 32];

__device__ __forceinline__ float sigm(float x) { return 1.f / (1.f + expf(-x)); }

__device__ __forceinline__ uint32_t s2u(const void* p) {
    return (uint32_t)__cvta_generic_to_shared(p);
}
__device__ __forceinline__ uint32_t bpack(float lo, float hi) {
    __nv_bfloat162 v = __floats2bfloat162_rn(lo, hi);
    return *(uint32_t*)&v;
}
__device__ __forceinline__ void mma16(float acc[4],
    uint32_t a0, uint32_t a1, uint32_t a2, uint32_t a3,
    uint32_t b0, uint32_t b1)
{
    asm volatile("mma.sync.aligned.m16n8k16.row.col.f32.bf16.bf16.f32 "
        "{%0,%1,%2,%3},{%4,%5,%6,%7},{%8,%9},{%0,%1,%2,%3};"
        : "+f"(acc[0]), "+f"(acc[1]), "+f"(acc[2]), "+f"(acc[3])
        : "r"(a0), "r"(a1), "r"(a2), "r"(a3), "r"(b0), "r"(b1));
}
#define CPA16(dst, src) asm volatile("cp.async.cg.shared.global [%0], [%1], 16;" :: "r"(dst), "l"(src))
#define CPA_COMMIT()    asm volatile("cp.async.commit_group;")
#define CPA_WAIT4()     asm volatile("cp.async.wait_group 4;")

// ---------------- barriers ---------------------------------------------------
__device__ __forceinline__ void gsync_all() {
    __syncthreads();
    if (threadIdx.x == 0) {
        __threadfence();
        unsigned gen = g_gen;
        unsigned grp = blockIdx.x >> 3;
        if (atomicAdd(&g_arr1[grp * 32], 1u) == 7u) {
            if (atomicAdd(&g_arr0, 1u) == 15u) {
                #pragma unroll
                for (int i = 0; i < 16; i++) g_arr1[i * 32] = 0u;
                g_arr0 = 0u;
                __threadfence();
                g_gen = gen + 1u;
            } else {
                while (g_gen == gen) __nanosleep(32);
            }
        } else {
            while (g_gen == gen) __nanosleep(32);
        }
        __threadfence();
    }
    __syncthreads();
}

__device__ __forceinline__ void gsync_g(int mh) {
    __syncthreads();
    if (threadIdx.x == 0) {
        __threadfence();
        unsigned gen = g_ggen2[mh * 32];
        if (atomicAdd(&g_garr2[mh * 32], 1u) == 63u) {
            g_garr2[mh * 32] = 0u;
            __threadfence();
            g_ggen2[mh * 32] = gen + 1u;
        } else {
            while (g_ggen2[mh * 32] == gen) __nanosleep(32);
        }
        __threadfence();
    }
    __syncthreads();
}

// ---------------- W fragment pack (bf16, 3 K-segments) ----------------------
__device__ __forceinline__ float wget(int grow, int k,
    const float* W0, int ld0, int K0,
    const float* W1, int ld1, int K1,
    const float* W2, int ld2)
{
    if (k < K0) return W0[(size_t)grow * ld0 + k];
    if (k < K0 + K1) return W1[(size_t)grow * ld1 + (k - K0)];
    return W2[(size_t)grow * ld2 + (k - K0 - K1)];
}

__device__ void pack_Wb3(uint4* Wp, int nb, int KS16,
    const float* W0, int ld0, int K0,
    const float* W1, int ld1, int K1,
    const float* W2, int ld2)
{
    for (int idx = threadIdx.x; idx < 2 * KS16 * 32; idx += NTHR) {
        int wn  = idx / (KS16 * 32);
        int rem = idx - wn * (KS16 * 32);
        int s = rem >> 5, l = rem & 31;
        int gid = l >> 2, t0 = l & 3;
        uint32_t r[4];
        #pragma unroll
        for (int hh = 0; hh < 2; hh++) {
            int c = hh * 8 + gid;
            int jj = wn * 4 + (c >> 2);
            int gate = c & 3;
            int grow = gate * Hz + nb * 8 + jj;
            int k0 = s * 16 + t0 * 2;
            float w00 = wget(grow, k0,     W0, ld0, K0, W1, ld1, K1, W2, ld2);
            float w01 = wget(grow, k0 + 1, W0, ld0, K0, W1, ld1, K1, W2, ld2);
            float w10 = wget(grow, k0 + 8, W0, ld0, K0, W1, ld1, K1, W2, ld2);
            float w11 = wget(grow, k0 + 9, W0, ld0, K0, W1, ld1, K1, W2, ld2);
            r[hh * 2]     = bpack(w00, w01);
            r[hh * 2 + 1] = bpack(w10, w11);
        }
        Wp[idx] = make_uint4(r[0], r[1], r[2], r[3]);
    }
}

// ---------------- gates GEMM: warp-specialized producers/consumers ----------
template<bool DEC>
__device__ __forceinline__ void issue_stage(uint32_t abase, int buf, int cc,
    const __nv_bfloat16* s0, const __nv_bfloat16* s1, const __nv_bfloat16* s2,
    int tid2)
{
    int row = tid2 >> 2, c = tid2 & 3;
    int k = cc * 32 + c * 8;
    const __nv_bfloat16* src;
    if (k < 128) src = s0 + k;
    else if (!DEC || k < 640) src = s1 + (k - 128);
    else src = s2 + (k - 640);
    uint32_t dst = abase + (uint32_t)(buf * (64 * AROWS) + row * AROWS + (c ^ (row & 3))) * 16;
    CPA16(dst, src);
}

template<bool DEC>
__device__ void gates_step(
    const uint4* __restrict__ Wp, float4* __restrict__ Ab,
    const __nv_bfloat16* __restrict__ xbase, int t,
    float* __restrict__ hout,
    const __nv_bfloat16* __restrict__ hb_in,
    const __nv_bfloat16* __restrict__ ab_in,
    __nv_bfloat16* __restrict__ hb_out,
    int mh, int nb, const float bias[2][4], const float* __restrict__ corr)
{
    const int NCH  = DEC ? 36 : 20;
    const int KS16 = DEC ? 72 : 40;
    int tid = threadIdx.x;
    int l = tid & 31, wrp = tid >> 5;
    bool prod = (wrp >= 8);
    int wm = wrp & 3, wn = (wrp >> 2) & 1;
    int gid = l >> 2, t0 = l & 3;
    int m16 = mh * 64 + wm * 16;
    int arow = wm * 16 + ((l >> 3) & 1) * 8 + (l & 7);
    int halfsel = l >> 4;

    int tid2 = tid - 256;
    const __nv_bfloat16 *s0 = nullptr, *s1 = nullptr, *s2 = nullptr;
    uint32_t abase = s2u(Ab);
    if (prod) {
        int rowb = mh * 64 + (tid2 >> 2);
        s0 = xbase + (size_t)rowb * ((DEC ? LEz : LCz) * Vz) + (size_t)t * Vz;
        s1 = hb_in + rowb * Hz;
        s2 = DEC ? (ab_in + rowb * Hz) : s1;
        #pragma unroll
        for (int p = 0; p < 5; p++) {
            issue_stage<DEC>(abase, p, p, s0, s1, s2, tid2);
            CPA_COMMIT();
        }
    }

    float acc[2][4];
    #pragma unroll
    for (int i = 0; i < 2; i++)
        #pragma unroll
        for (int k = 0; k < 4; k++) acc[i][k] = 0.f;

    int buf = 0, nbuf = 5;
    for (int cc = 0; cc < NCH; cc++) {
        if (prod) CPA_WAIT4();
        __syncthreads();
        if (!prod) {
            uint32_t ab = abase + (uint32_t)(buf * (64 * AROWS)) * 16;
            #pragma unroll
            for (int kk = 0; kk < 2; kk++) {
                int ccol = (kk * 2 + halfsel) ^ (arow & 3);
                uint32_t addr = ab + (uint32_t)(arow * AROWS + ccol) * 16;
                uint32_t a0, a1, a2, a3;
                asm volatile("ldmatrix.sync.aligned.m8n8.x4.shared.b16 {%0,%1,%2,%3}, [%4];"
                             : "=r"(a0), "=r"(a1), "=r"(a2), "=r"(a3) : "r"(addr));
                uint4 wv = Wp[((size_t)wn * KS16 + (cc * 2 + kk)) * 32 + l];
                mma16(acc[0], a0, a1, a2, a3, wv.x, wv.y);
                mma16(acc[1], a0, a1, a2, a3, wv.z, wv.w);
            }
        } else if (cc + 5 < NCH) {
            issue_stage<DEC>(abase, nbuf, cc + 5, s0, s1, s2, tid2);
            CPA_COMMIT();
        }
        if (++buf == 6) buf = 0;
        if (++nbuf == 6) nbuf = 0;
    }

    if (!prod) {
        bool evn = ((t0 & 1) == 0);
        #pragma unroll
        for (int hh = 0; hh < 2; hh++) {
            float d0 = acc[hh][0], d1 = acc[hh][1], d2 = acc[hh][2], d3 = acc[hh][3];
            float x0 = __shfl_xor_sync(0xffffffffu, d0, 1);
            float x1 = __shfl_xor_sync(0xffffffffu, d1, 1);
            float x2 = __shfl_xor_sync(0xffffffffu, d2, 1);
            float x3 = __shfl_xor_sync(0xffffffffu, d3, 1);
            int j = nb * 8 + wn * 4 + hh * 2 + (t0 >> 1);
            int b = m16 + gid + (evn ? 0 : 8);
            float gi = (evn ? d0 : x2) + bias[hh][0];
            float gf = (evn ? d1 : x3) + bias[hh][1];
            float gg = (evn ? x0 : d2) + bias[hh][2];
            float go = (evn ? x1 : d3) + bias[hh][3];
            if (corr) {
                gi -= corr[b * 2048 + j];
                gf -= corr[b * 2048 + 512 + j];
                gg -= corr[b * 2048 + 1024 + j];
                go -= corr[b * 2048 + 1536 + j];
            }
            float c  = g_c[b * Hz + j];
            float cn = sigm(gf) * c + sigm(gi) * tanhf(gg);
            float hn = sigm(go) * tanhf(cn);
            g_c[b * Hz + j] = cn;
            hout[b * Hz + j] = hn;
            hb_out[b * Hz + j] = __float2bfloat16(hn);
            if (!DEC)
                g_enc[((size_t)b * LCz + t) * Hz + j] = __float2bfloat16(hn);
        }
    }
}

__device__ __forceinline__ void load_bias2(float bias[2][4],
    const float* __restrict__ bih, const float* __restrict__ bhh,
    const float* __restrict__ beff, int nb)
{
    int l = threadIdx.x & 31;
    int wn = ((threadIdx.x >> 5) >> 2) & 1;
    int t0 = l & 3;
    #pragma unroll
    for (int hh = 0; hh < 2; hh++) {
        int j = nb * 8 + wn * 4 + hh * 2 + (t0 >> 1);
        #pragma unroll
        for (int g4 = 0; g4 < 4; g4++)
            bias[hh][g4] = beff ? beff[g4 * Hz + j] : (bih[g4 * Hz + j] + bhh[g4 * Hz + j]);
    }
}

// ---------------- pad compaction (512 threads) ------------------------------
__device__ void comp_scan(int b, const int* __restrict__ C_pad, float* smf)
{
    int* sm = (int*)smf;
    int tid = threadIdx.x, lane = tid & 31, w = tid >> 5;
    int f = (C_pad[b * LCz + tid] == 0) ? 1 : 0;
    int x = f;
    #pragma unroll
    for (int o = 1; o < 32; o <<= 1) {
        int y = __shfl_up_sync(0xffffffffu, x, o);
        if (lane >= o) x += y;
    }
    if (lane == 31) sm[w] = x;
    __syncthreads();
    if (tid == 0) {
        int run = 0;
        for (int i = 0; i < 16; i++) { int v = sm[i]; sm[16 + i] = run; run += v; }
        sm[32] = run;
    }
    __syncthreads();
    int excl = sm[16 + w] + x - f;
    if (f) g_lidx[b * LCz + excl] = tid;
    if (tid == 0) g_Lb[b] = sm[32];
    __syncthreads();
}

__device__ void build_F(int b, const float* __restrict__ att_W, float* se)
{
    int tid = threadIdx.x;
    int Lb = g_Lb[b];
    for (int ci0 = 0; ci0 < Lb; ci0 += 32) {
        int R = min(32, Lb - ci0);
        for (int idx = tid; idx < R * 512; idx += NTHR) {
            int r = idx >> 9, j = idx & 511;
            int l = g_lidx[b * LCz + ci0 + r];
            __nv_bfloat16 hv = g_enc[((size_t)b * LCz + l) * Hz + j];
            se[j * 36 + r] = __bfloat162float(hv);
            g_encc[((size_t)b * LCz + ci0 + r) * Hz + j] = hv;
        }
        __syncthreads();
        {
            int k = tid;  // 512 threads cover all k
            float acc[32];
            #pragma unroll
            for (int i = 0; i < 32; i++) acc[i] = 0.f;
            for (int j = 0; j < 512; j++) {
                float wv = att_W[j * Hz + k];
                #pragma unroll
                for (int g4 = 0; g4 < 8; g4++) {
                    float4 e = *(const float4*)&se[j * 36 + g4 * 4];
                    acc[g4 * 4 + 0] += e.x * wv;
                    acc[g4 * 4 + 1] += e.y * wv;
                    acc[g4 * 4 + 2] += e.z * wv;
                    acc[g4 * 4 + 3] += e.w * wv;
                }
            }
            for (int r = 0; r < R; r++)
                g_Fc[((size_t)b * LCz + ci0 + r) * Hz + k] = __float2bfloat16(acc[r]);
        }
        __syncthreads();
    }
}

__device__ void calc_u(int b, const float* __restrict__ out_W,
                       const float* __restrict__ out_b, float* scr)
{
    int tid = threadIdx.x;
    __syncthreads();
    if (tid < Hz) scr[tid] = g_h[0][b * Hz + tid];
    __syncthreads();
    if (tid < Hz) {
        const float* wr = out_W + (size_t)tid * (2 * Hz);
        float acc = 0.f;
        for (int h = 0; h < Hz; h += 4) {
            float4 w4 = *(const float4*)(wr + h);
            acc += w4.x * scr[h] + w4.y * scr[h + 1] + w4.z * scr[h + 2] + w4.w * scr[h + 3];
        }
        g_u[b * Hz + tid] = acc + out_b[tid];
    }
    __syncthreads();
}

__device__ void compose(const float* __restrict__ dec_Wih, const float* __restrict__ dec_Whh,
                        const float* __restrict__ dec_bih, const float* __restrict__ dec_bhh,
                        const float* __restrict__ out_W, const float* __restrict__ out_b)
{
    int bid = blockIdx.x, tid = threadIdx.x;
    if (tid >= 256) return;               // no internal syncs — safe to guard
    int g = bid * 16 + (tid >> 4);
    int c0 = (tid & 15) * 32;
    const float* wv = dec_Wih + (size_t)g * (Vz + Hz) + Vz;
    #pragma unroll 1
    for (int pass = 0; pass < 2; pass++) {
        float acc[32];
        #pragma unroll
        for (int i = 0; i < 32; i++) acc[i] = 0.f;
        float accb = 0.f;
        for (int v = 0; v < Hz; v++) {
            float w = wv[v];
            const float* owr = out_W + (size_t)v * (2 * Hz) + pass * Hz + c0;
            #pragma unroll
            for (int i = 0; i < 32; i += 4) {
                float4 o = *(const float4*)(owr + i);
                acc[i] += w * o.x; acc[i + 1] += w * o.y;
                acc[i + 2] += w * o.z; acc[i + 3] += w * o.w;
            }
            if (pass == 0) accb += w * out_b[v];
        }
        if (pass == 0) {
            for (int i = 0; i < 32; i++)
                g_Weff[(size_t)g * Hz + c0 + i] = dec_Whh[(size_t)g * Hz + c0 + i] + acc[i];
            if ((tid & 15) == 0) g_beff[g] = dec_bih[g] + dec_bhh[g] + accb;
        } else {
            for (int i = 0; i < 32; i++)
                g_Wcomp[(size_t)g * Hz + c0 + i] = acc[i];
        }
    }
}

__device__ void calc_c(int b, const float* __restrict__ dec_Wih, float* scr)
{
    int tid = threadIdx.x;
    __syncthreads();
    if (tid < Hz) scr[tid] = g_u[b * Hz + tid];
    __syncthreads();
    for (int g = tid; g < 2048; g += NTHR) {
        const float* wv = dec_Wih + (size_t)g * (Vz + Hz) + Vz;
        float acc = 0.f;
        for (int v = 0; v < Hz; v += 4) {
            float4 w4 = *(const float4*)(wv + v);
            acc += w4.x * scr[v] + w4.y * scr[v + 1] + w4.z * scr[v + 2] + w4.w * scr[v + 3];
        }
        g_corr[b * 2048 + g] = acc;
    }
}

// ---------------- attention (group A: threads 0..255, barrier 1) -------------
__device__ void attn_block(int b, const float* __restrict__ hcur,
                           float* __restrict__ dst, __nv_bfloat16* __restrict__ dstb,
                           float* sm)
{
    float* ss   = sm;
    float* red  = sm + 512;
    float* sca  = sm + 520;
    float* wacc = sm + 528;
    int tid = threadIdx.x, lane = tid & 31, w = tid >> 5;  // tid < 256, w < 8
    int Lb = g_Lb[b];

    float qreg[16];
    const float* hb = hcur + b * Hz + lane * 16;
    #pragma unroll
    for (int i = 0; i < 16; i += 4) {
        float4 v = *(const float4*)(hb + i);
        qreg[i] = v.x; qreg[i + 1] = v.y; qreg[i + 2] = v.z; qreg[i + 3] = v.w;
    }

    const __nv_bfloat16* Fb = g_Fc + (size_t)b * LCz * Hz;
    #pragma unroll 4
    for (int l = w; l < Lb; l += 8) {
        const __nv_bfloat16* row = Fb + (size_t)l * Hz + lane * 16;
        uint4 u0 = *(const uint4*)row;
        uint4 u1 = *(const uint4*)(row + 8);
        const __nv_bfloat162* h0 = (const __nv_bfloat162*)&u0;
        const __nv_bfloat162* h1 = (const __nv_bfloat162*)&u1;
        float acc = 0.f;
        #pragma unroll
        for (int i = 0; i < 4; i++) {
            float2 f0 = __bfloat1622float2(h0[i]);
            float2 f1 = __bfloat1622float2(h1[i]);
            acc += f0.x * qreg[2 * i]     + f0.y * qreg[2 * i + 1];
            acc += f1.x * qreg[8 + 2 * i] + f1.y * qreg[8 + 2 * i + 1];
        }
        #pragma unroll
        for (int o = 16; o > 0; o >>= 1) acc += __shfl_xor_sync(0xffffffffu, acc, o);
        if (lane == 0) ss[l] = acc;
    }
    NB(1);

    float m = -INFINITY;
    for (int l = tid; l < Lb; l += 256) m = fmaxf(m, ss[l]);
    #pragma unroll
    for (int o = 16; o > 0; o >>= 1) m = fmaxf(m, __shfl_xor_sync(0xffffffffu, m, o));
    if (lane == 0) red[w] = m;
    NB(1);
    if (tid == 0) {
        float mm = red[0];
        for (int i = 1; i < 8; i++) mm = fmaxf(mm, red[i]);
        sca[0] = mm;
    }
    NB(1);
    float bmax = sca[0];

    float s = 0.f;
    for (int l = tid; l < Lb; l += 256) {
        float e = expf(ss[l] - bmax);
        ss[l] = e;
        s += e;
    }
    #pragma unroll
    for (int o = 16; o > 0; o >>= 1) s += __shfl_xor_sync(0xffffffffu, s, o);
    if (lane == 0) red[w] = s;
    NB(1);
    if (tid == 0) {
        float t2 = 0.f;
        for (int i = 0; i < 8; i++) t2 += red[i];
        sca[1] = t2;
    }
    NB(1);
    float inv = 1.f / sca[1];

    float acc2[16];
    #pragma unroll
    for (int i = 0; i < 16; i++) acc2[i] = 0.f;
    const __nv_bfloat16* Eb = g_encc + (size_t)b * LCz * Hz;
    #pragma unroll 4
    for (int l = w; l < Lb; l += 8) {
        float d = ss[l];
        const __nv_bfloat16* row = Eb + (size_t)l * Hz + lane * 16;
        uint4 u0 = *(const uint4*)row;
        uint4 u1 = *(const uint4*)(row + 8);
        const __nv_bfloat162* h0 = (const __nv_bfloat162*)&u0;
        const __nv_bfloat162* h1 = (const __nv_bfloat162*)&u1;
        #pragma unroll
        for (int i = 0; i < 4; i++) {
            float2 f0 = __bfloat1622float2(h0[i]);
            float2 f1 = __bfloat1622float2(h1[i]);
            acc2[2 * i]         += d * f0.x;
            acc2[2 * i + 1]     += d * f0.y;
            acc2[8 + 2 * i]     += d * f1.x;
            acc2[8 + 2 * i + 1] += d * f1.y;
        }
    }
    #pragma unroll
    for (int i = 0; i < 16; i++) wacc[w * Hz + lane * 16 + i] = acc2[i];
    NB(1);

    for (int h = tid; h < Hz; h += 256) {
        float t2 = 0.f;
        #pragma unroll
        for (int ww = 0; ww < 8; ww++) t2 += wacc[ww * Hz + h];
        float v = t2 * inv;
        dst[b * Hz + h] = v;
        dstb[b * Hz + h] = __float2bfloat16(v);
    }
}

// ---------------- out-proj (group B: t256 = tid-256, barrier 2) --------------
__device__ void outproj16(const float* __restrict__ h_src,
                          const float* __restrict__ attn_src,
                          const float* __restrict__ out_b,
                          float* __restrict__ vout, float* sm, int mh, int t256)
{
    NB(2);
    int bid = blockIdx.x;
    int gb = bid >> 1;
    int m0 = mh * 64 + (gb & 3) * 16;
    int n0 = ((gb >> 2) & 7) * 64;
    int split = (gb >> 5) & 1;
    const float* Asrc = (split == 0) ? h_src : attn_src;

    int arow = t256 & 15, akg = t256 >> 4;
    int wr = t256 >> 2, wkg = t256 & 3;
    int m = t256 >> 4, ng = t256 & 15;

    const float* ap = Asrc + (size_t)(m0 + arow) * Hz + akg * 8;
    const __nv_bfloat16* wp = g_oWb16 + (size_t)(n0 + wr) * 1024 + split * Hz + wkg * 8;

    float4 pa0, pa1;
    uint4 pw;
    if (t256 < 64) { pa0 = *(const float4*)ap; pa1 = *(const float4*)(ap + 4); }
    pw = *(const uint4*)wp;

    float acc[4] = {0.f, 0.f, 0.f, 0.f};
    for (int it = 0; it < 16; it++) {
        float* As = sm + (it & 1) * 2560;
        float* Ws = As + 512;
        if (t256 < 64) {
            int kb = akg * 8;
            As[(kb + 0) * 16 + arow] = pa0.x; As[(kb + 1) * 16 + arow] = pa0.y;
            As[(kb + 2) * 16 + arow] = pa0.z; As[(kb + 3) * 16 + arow] = pa0.w;
            As[(kb + 4) * 16 + arow] = pa1.x; As[(kb + 5) * 16 + arow] = pa1.y;
            As[(kb + 6) * 16 + arow] = pa1.z; As[(kb + 7) * 16 + arow] = pa1.w;
        }
        {
            int kb = wkg * 8;
            const __nv_bfloat162* ph = (const __nv_bfloat162*)&pw;
            #pragma unroll
            for (int i = 0; i < 4; i++) {
                float2 f = __bfloat1622float2(ph[i]);
                Ws[(kb + 2 * i) * 64 + wr]     = f.x;
                Ws[(kb + 2 * i + 1) * 64 + wr] = f.y;
            }
        }
        NB(2);
        if (it < 15) {
            if (t256 < 64) {
                const float* ap2 = ap + (it + 1) * 32;
                pa0 = *(const float4*)ap2; pa1 = *(const float4*)(ap2 + 4);
            }
            pw = *(const uint4*)(wp + (it + 1) * 32);
        }
        #pragma unroll
        for (int kk = 0; kk < 32; kk++) {
            float a = As[kk * 16 + m];
            float4 w4 = *(const float4*)&Ws[kk * 64 + ng * 4];
            acc[0] += a * w4.x; acc[1] += a * w4.y;
            acc[2] += a * w4.z; acc[3] += a * w4.w;
        }
    }
    NB(2);
    #pragma unroll
    for (int i = 0; i < 4; i++) {
        int n = n0 + ng * 4 + i;
        float v = acc[i] + ((split == 0) ? out_b[n] : 0.f);
        vout[(size_t)split * BHS + (m0 + m) * Hz + n] = v;
    }
}

// ---------------- logits + CE (group barrier id, local t256) -----------------
__device__ void logits_ce(int b, int tt, const int* __restrict__ E,
                          const float* __restrict__ vp,
                          const float* __restrict__ voc_b, float* sm,
                          int t256, int barid)
{
    float* st = sm;
    float* sl = sm + 512;
    int lane = t256 & 31, w = t256 >> 5;
    NB(barid);

    for (int i = t256; i < Hz; i += 256)
        st[i] = tanhf(vp[b * Hz + i] + vp[BHS + b * Hz + i]);
    NB(barid);

    float sreg[16];
    #pragma unroll
    for (int i = 0; i < 16; i++) sreg[i] = st[lane * 16 + i];

    for (int v = w; v < Vz; v += 8) {
        const __nv_bfloat16* wr = g_vocb16 + (size_t)v * Hz + lane * 16;
        uint4 u0 = *(const uint4*)wr;
        uint4 u1 = *(const uint4*)(wr + 8);
        const __nv_bfloat162* h0 = (const __nv_bfloat162*)&u0;
        const __nv_bfloat162* h1 = (const __nv_bfloat162*)&u1;
        float acc = 0.f;
        #pragma unroll
        for (int i = 0; i < 4; i++) {
            float2 f0 = __bfloat1622float2(h0[i]);
            float2 f1 = __bfloat1622float2(h1[i]);
            acc += f0.x * sreg[2 * i]     + f0.y * sreg[2 * i + 1];
            acc += f1.x * sreg[8 + 2 * i] + f1.y * sreg[8 + 2 * i + 1];
        }
        #pragma unroll
        for (int o = 16; o > 0; o >>= 1) acc += __shfl_xor_sync(0xffffffffu, acc, o);
        if (lane == 0) sl[v] = acc + voc_b[v];
    }
    NB(barid);

    if (w == 0) {
        float m = -INFINITY;
        for (int v = lane; v < Vz; v += 32) m = fmaxf(m, sl[v]);
        #pragma unroll
        for (int o = 16; o > 0; o >>= 1) m = fmaxf(m, __shfl_xor_sync(0xffffffffu, m, o));
        float s = 0.f;
        for (int v = lane; v < Vz; v += 32) s += expf(sl[v] - m);
        #pragma unroll
        for (int o = 16; o > 0; o >>= 1) s += __shfl_xor_sync(0xffffffffu, s, o);
        if (lane == 0) {
            int tv = E[b * LEz + tt + 1];
            int idx = b * TDEC + tt;
            if (tv != 0) { g_nll[idx] = m + logf(s) - sl[tv]; g_msk[idx] = 1.f; }
            else         { g_nll[idx] = 0.f;                  g_msk[idx] = 0.f; }
        }
    }
    NB(barid);
}

// ---------------- the single persistent kernel ------------------------------
__global__ void __launch_bounds__(NTHR, 1) persist_kernel(
    const float* __restrict__ C,       const int* __restrict__ C_pad,
    const int* __restrict__ E,         const float* __restrict__ E_emb,
    const float* __restrict__ enc_Wih, const float* __restrict__ enc_Whh,
    const float* __restrict__ enc_bih, const float* __restrict__ enc_bhh,
    const float* __restrict__ dec_Wih, const float* __restrict__ dec_Whh,
    const float* __restrict__ dec_bih, const float* __restrict__ dec_bhh,
    const float* __restrict__ att_W,   const float* __restrict__ out_W,
    const float* __restrict__ out_b,   const float* __restrict__ voc_W,
    const float* __restrict__ voc_b,   float* __restrict__ out)
{
    extern __shared__ __align__(16) float4 dsm[];
    uint4*  Wp   = (uint4*)dsm;
    float4* Ab   = dsm + 4608;
    float*  scrA = (float*)(dsm + 6528);
    float*  scrB = scrA + 4624;

    int bid = blockIdx.x, tid = threadIdx.x;
    int lane = tid & 31, w = tid >> 5;
    int mh = bid & 1, nb = bid >> 1;
    int mhb = mh * 64 + nb;

    // ---- init + bf16 pre-conversions ----
    for (int i = bid * NTHR + tid; i < BHS; i += NBLK * NTHR) {
        g_h[0][i] = 0.f; g_c[i] = 0.f;
        g_hb16[0][i] = __float2bfloat16(0.f);
        g_ab16[0][i] = __float2bfloat16(0.f);
        g_ab16[1][i] = __float2bfloat16(0.f);
    }
    float* vpf = (float*)g_vp;
    for (int i = bid * NTHR + tid; i < 4 * BHS; i += NBLK * NTHR) vpf[i] = 0.f;
    float* apf = (float*)g_attn2;
    for (int i = bid * NTHR + tid; i < 2 * BHS; i += NBLK * NTHR) apf[i] = 0.f;
    for (int i = bid * NTHR + tid; i < Vz * Hz; i += NBLK * NTHR)
        g_vocb16[i] = __float2bfloat16(voc_W[i]);
    for (size_t i = bid * NTHR + tid; i < (size_t)Bz * LCz * Vz; i += NBLK * NTHR)
        g_Cb16[i] = __float2bfloat16(C[i]);
    for (size_t i = bid * NTHR + tid; i < (size_t)Bz * LEz * Vz; i += NBLK * NTHR)
        g_Eb16[i] = __float2bfloat16(E_emb[i]);
    for (int i = bid * NTHR + tid; i < 512 * 1024; i += NBLK * NTHR)
        g_oWb16[i] = __float2bfloat16(out_W[i]);
    gsync_all();

    // ---- encoder ----
    pack_Wb3(Wp, nb, 40, enc_Wih, Vz, Vz, enc_Whh, Hz, Hz, enc_Whh, Hz);
    __syncthreads();
    float biasE[2][4];
    load_bias2(biasE, enc_bih, enc_bhh, nullptr, nb);
    for (int t = 0; t < LCz; t++) {
        gates_step<false>(Wp, Ab, g_Cb16, t, g_h[1 - (t & 1)],
                          g_hb16[t & 1], nullptr, g_hb16[1 - (t & 1)],
                          mh, nb, biasE, nullptr);
        gsync_g(mh);
    }

    // ---- pre-decoder (own batch) ----
    comp_scan(mhb, C_pad, scrA);
    build_F(mhb, att_W, (float*)dsm);
    calc_u(mhb, out_W, out_b, scrA);
    calc_c(mhb, dec_Wih, scrA);

    // ---- composition (shared) => full barrier ----
    compose(dec_Wih, dec_Whh, dec_bih, dec_bhh, out_W, out_b);
    gsync_all();

    // ---- decoder ----
    pack_Wb3(Wp, nb, 72, dec_Wih, Vz + Hz, Vz, g_Weff, Hz, Hz, g_Wcomp, Hz);
    __syncthreads();
    float biasD[2][4];
    load_bias2(biasD, dec_bih, dec_bhh, g_beff, nb);

    for (int t = 0; t < TDEC; t++) {
        // Phase A: gates(t) (warp-specialized producers/consumers)
        gates_step<true>(Wp, Ab, g_Eb16, t, g_h[1 - (t & 1)],
                         g_hb16[t & 1], g_ab16[(t + 1) & 1], g_hb16[1 - (t & 1)],
                         mh, nb, biasD, (t == 0) ? g_corr : nullptr);
        gsync_g(mh);

        // Phase B: group A attn(t) || group B outproj(t-1) + CE(t-2)
        if (tid < 256) {
            attn_block(mhb, g_h[1 - (t & 1)], g_attn2[t & 1], g_ab16[t & 1], scrA);
        } else {
            int t256 = tid - 256;
            if (t >= 1)
                outproj16(g_h[t & 1], g_attn2[(t + 1) & 1], out_b,
                          (float*)g_vp[(t + 1) & 1], scrB, mh, t256);
            if (t >= 2)
                logits_ce(mhb, t - 2, E, (const float*)g_vp[t & 1], voc_b, scrB,
                          t256, 2);
        }
        gsync_g(mh);
    }

    // ---- tail: V(510) (group B) || CE(509) (group A); then CE(510) ----
    if (tid < 256) {
        logits_ce(mhb, TDEC - 2, E, (const float*)g_vp[1], voc_b, scrA, tid, 1);
    } else {
        outproj16(g_h[1], g_attn2[0], out_b, (float*)g_vp[0], scrB, mh, tid - 256);
    }
    gsync_g(mh);
    if (tid < 256)
        logits_ce(mhb, TDEC - 1, E, (const float*)g_vp[0], voc_b, scrA, tid, 1);
    __syncthreads();

    // ---- per-batch reduction ----
    {
        float s = 0.f, c = 0.f;
        for (int i = tid; i < TDEC; i += NTHR) {
            s += g_nll[mhb * TDEC + i];
            c += g_msk[mhb * TDEC + i];
        }
        #pragma unroll
        for (int o = 16; o > 0; o >>= 1) {
            s += __shfl_xor_sync(0xffffffffu, s, o);
            c += __shfl_xor_sync(0xffffffffu, c, o);
        }
        __syncthreads();
        if (lane == 0) { scrA[w] = s; scrA[16 + w] = c; }
        __syncthreads();
        if (tid == 0) {
            float ts = 0.f, tc = 0.f;
            for (int i = 0; i < 16; i++) { ts += scrA[i]; tc += scrA[16 + i]; }
            g_ps[bid] = ts; g_pc[bid] = tc;
        }
    }
    gsync_all();
    if (bid == 0 && tid == 0) {
        float ts = 0.f, tc = 0.f;
        for (int i = 0; i < NBLK; i++) { ts += g_ps[i]; tc += g_pc[i]; }
        out[0] = ts / fmaxf(tc, 1.f);
    }
}

// ---------------- host entry ------------------------------------------------
extern "C" void kernel_launch(void* const* d_in, const int* in_sizes, int n_in,
                              void* d_out, int out_size)
{
    cudaFuncSetAttribute((const void*)persist_kernel,
                         cudaFuncAttributeMaxDynamicSharedMemorySize, SMEM_BYTES);
    persist_kernel<<<NBLK, NTHR, SMEM_BYTES>>>(
        (const float*)d_in[0],  (const int*)d_in[1],
        (const int*)d_in[2],    (const float*)d_in[3],
        (const float*)d_in[4],  (const float*)d_in[5],
        (const float*)d_in[6],  (const float*)d_in[7],
        (const float*)d_in[8],  (const float*)d_in[9],
        (const float*)d_in[10], (const float*)d_in[11],
        (const float*)d_in[12], (const float*)d_in[13],
        (const float*)d_in[14], (const float*)d_in[15],
        (const float*)d_in[16], (float*)d_out);
}

// round 14
// speedup vs baseline: 1.7924x; 1.0763x over previous
#include <cuda_runtime.h>
#include <cuda_bf16.h>
#include <cuda_fp16.h>
#include <cuda_fp8.h>
#include <math.h>
#include <stdint.h>

#define Bz   128
#define LCz  512
#define LEz  512
#define Hz   512
#define Vz   128
#define TDEC 511
#define NBLK 128
#define NTHR 512
#define BHS  (Bz * Hz)   // 65536

#define SMEM_BYTES 143424
#define AROWS 5

#define NB(id) asm volatile("bar.sync %0, 256;" :: "r"(id) : "memory")

// ---------------- static device scratch -------------------------------------
__device__ __align__(16) float g_h[2][BHS];
__device__ __align__(16) __nv_bfloat16 g_hb16[2][BHS];
__device__ __align__(16) float g_c[BHS];
__device__ __align__(16) float g_vp[2][2][BHS];
__device__ __align__(16) float g_attn2[2][BHS];
__device__ __align__(16) __nv_bfloat16 g_ab16[2][BHS];
__device__ __align__(16) __nv_bfloat16 g_Cb16[(size_t)Bz * LCz * Vz];
__device__ __align__(16) __nv_bfloat16 g_Eb16[(size_t)Bz * LEz * Vz];
__device__ __align__(16) __nv_bfloat16 g_enc [(size_t)Bz * LCz * Hz];
__device__ __align__(16) unsigned char g_encc[(size_t)Bz * LCz * Hz];   // fp8 e4m3
__device__ __align__(16) unsigned char g_Fc  [(size_t)Bz * LCz * Hz];   // fp8 e4m3
__device__ __align__(16) __nv_bfloat16 g_vocb16[Vz * Hz];
__device__ __align__(16) __nv_bfloat16 g_oWb16[512 * 1024];
__device__ __align__(16) float g_Weff [2048 * Hz];
__device__ __align__(16) float g_Wcomp[2048 * Hz];
__device__ float g_beff[2048];
__device__ float g_u[Bz * Hz];
__device__ float g_corr[Bz * 2048];
__device__ int g_lidx[Bz * LCz];
__device__ int g_Lb[Bz];
__device__ float g_nll[Bz * TDEC];
__device__ float g_msk[Bz * TDEC];
__device__ float g_ps[NBLK], g_pc[NBLK];
__device__ unsigned g_arr1[16 * 32];
__device__ unsigned g_arr0;
__device__ volatile unsigned g_gen;
__device__ unsigned g_garr2[2 * 32];
__device__ unsigned g_ggen2[2 * 32];

__device__ __forceinline__ float sigm(float x) { return 1.f / (1.f + expf(-x)); }

__device__ __forceinline__ uint32_t s2u(const void* p) {
    return (uint32_t)__cvta_generic_to_shared(p);
}
__device__ __forceinline__ uint32_t bpack(float lo, float hi) {
    __nv_bfloat162 v = __floats2bfloat162_rn(lo, hi);
    return *(uint32_t*)&v;
}
__device__ __forceinline__ void mma16(float acc[4],
    uint32_t a0, uint32_t a1, uint32_t a2, uint32_t a3,
    uint32_t b0, uint32_t b1)
{
    asm volatile("mma.sync.aligned.m16n8k16.row.col.f32.bf16.bf16.f32 "
        "{%0,%1,%2,%3},{%4,%5,%6,%7},{%8,%9},{%0,%1,%2,%3};"
        : "+f"(acc[0]), "+f"(acc[1]), "+f"(acc[2]), "+f"(acc[3])
        : "r"(a0), "r"(a1), "r"(a2), "r"(a3), "r"(b0), "r"(b1));
}
#define CPA16(dst, src) asm volatile("cp.async.cg.shared.global [%0], [%1], 16;" :: "r"(dst), "l"(src))
#define CPA_COMMIT()    asm volatile("cp.async.commit_group;")
#define CPA_WAIT4()     asm volatile("cp.async.wait_group 4;")

// fp8 e4m3 helpers
__device__ __forceinline__ unsigned char f2fp8(float x) {
    return (unsigned char)__nv_cvt_float_to_fp8(x, __NV_SATFINITE, __NV_E4M3);
}
__device__ __forceinline__ float2 fp8x2_to_f2(unsigned short p) {
    __half2_raw hr = __nv_cvt_fp8x2_to_halfraw2((__nv_fp8x2_storage_t)p, __NV_E4M3);
    return __half22float2(*(__half2*)&hr);
}

// ---------------- barriers ---------------------------------------------------
__device__ __forceinline__ unsigned ld_cg_u32(const unsigned* p) {
    unsigned v;
    asm volatile("ld.global.cg.u32 %0, [%1];" : "=r"(v) : "l"(p) : "memory");
    return v;
}
__device__ __forceinline__ unsigned ld_acq_u32(const unsigned* p) {
    unsigned v;
    asm volatile("ld.acquire.gpu.global.u32 %0, [%1];" : "=r"(v) : "l"(p) : "memory");
    return v;
}
__device__ __forceinline__ unsigned atom_add_acqrel(unsigned* p, unsigned v) {
    unsigned old;
    asm volatile("atom.acq_rel.gpu.global.add.u32 %0, [%1], %2;" : "=r"(old) : "l"(p), "r"(v) : "memory");
    return old;
}
__device__ __forceinline__ void st_rel_u32(unsigned* p, unsigned v) {
    asm volatile("st.release.gpu.global.u32 [%0], %1;" :: "l"(p), "r"(v) : "memory");
}

// full-grid barrier (rare; proven fence version)
__device__ __forceinline__ void gsync_all() {
    __syncthreads();
    if (threadIdx.x == 0) {
        __threadfence();
        unsigned gen = g_gen;
        unsigned grp = blockIdx.x >> 3;
        if (atomicAdd(&g_arr1[grp * 32], 1u) == 7u) {
            if (atomicAdd(&g_arr0, 1u) == 15u) {
                #pragma unroll
                for (int i = 0; i < 16; i++) g_arr1[i * 32] = 0u;
                g_arr0 = 0u;
                __threadfence();
                g_gen = gen + 1u;
            } else {
                while (g_gen == gen) __nanosleep(32);
            }
        } else {
            while (g_gen == gen) __nanosleep(32);
        }
        __threadfence();
    }
    __syncthreads();
}

// per-half barrier: CG-style (release-atomic arrive, relaxed spin, acquire exit)
__device__ __forceinline__ void gsync_g(int mh) {
    __syncthreads();
    if (threadIdx.x == 0) {
        unsigned* ctr = &g_garr2[mh * 32];
        unsigned* genp = &g_ggen2[mh * 32];
        unsigned gen = ld_cg_u32(genp);
        unsigned old = atom_add_acqrel(ctr, 1u);
        if (old == 63u) {
            *ctr = 0u;                       // published by release store below
            st_rel_u32(genp, gen + 1u);
        } else {
            while (ld_cg_u32(genp) == gen) __nanosleep(32);
            (void)ld_acq_u32(genp);          // acquire: order subsequent reads
        }
    }
    __syncthreads();
}

// ---------------- W fragment pack (bf16, 3 K-segments) ----------------------
__device__ __forceinline__ float wget(int grow, int k,
    const float* W0, int ld0, int K0,
    const float* W1, int ld1, int K1,
    const float* W2, int ld2)
{
    if (k < K0) return W0[(size_t)grow * ld0 + k];
    if (k < K0 + K1) return W1[(size_t)grow * ld1 + (k - K0)];
    return W2[(size_t)grow * ld2 + (k - K0 - K1)];
}

__device__ void pack_Wb3(uint4* Wp, int nb, int KS16,
    const float* W0, int ld0, int K0,
    const float* W1, int ld1, int K1,
    const float* W2, int ld2)
{
    for (int idx = threadIdx.x; idx < 2 * KS16 * 32; idx += NTHR) {
        int wn  = idx / (KS16 * 32);
        int rem = idx - wn * (KS16 * 32);
        int s = rem >> 5, l = rem & 31;
        int gid = l >> 2, t0 = l & 3;
        uint32_t r[4];
        #pragma unroll
        for (int hh = 0; hh < 2; hh++) {
            int c = hh * 8 + gid;
            int jj = wn * 4 + (c >> 2);
            int gate = c & 3;
            int grow = gate * Hz + nb * 8 + jj;
            int k0 = s * 16 + t0 * 2;
            float w00 = wget(grow, k0,     W0, ld0, K0, W1, ld1, K1, W2, ld2);
            float w01 = wget(grow, k0 + 1, W0, ld0, K0, W1, ld1, K1, W2, ld2);
            float w10 = wget(grow, k0 + 8, W0, ld0, K0, W1, ld1, K1, W2, ld2);
            float w11 = wget(grow, k0 + 9, W0, ld0, K0, W1, ld1, K1, W2, ld2);
            r[hh * 2]     = bpack(w00, w01);
            r[hh * 2 + 1] = bpack(w10, w11);
        }
        Wp[idx] = make_uint4(r[0], r[1], r[2], r[3]);
    }
}

// ---------------- gates GEMM: warp-specialized producers/consumers ----------
template<bool DEC>
__device__ __forceinline__ void issue_stage(uint32_t abase, int buf, int cc,
    const __nv_bfloat16* s0, const __nv_bfloat16* s1, const __nv_bfloat16* s2,
    int tid2)
{
    int row = tid2 >> 2, c = tid2 & 3;
    int k = cc * 32 + c * 8;
    const __nv_bfloat16* src;
    if (k < 128) src = s0 + k;
    else if (!DEC || k < 640) src = s1 + (k - 128);
    else src = s2 + (k - 640);
    uint32_t dst = abase + (uint32_t)(buf * (64 * AROWS) + row * AROWS + (c ^ (row & 3))) * 16;
    CPA16(dst, src);
}

template<bool DEC>
__device__ void gates_step(
    const uint4* __restrict__ Wp, float4* __restrict__ Ab,
    const __nv_bfloat16* __restrict__ xbase, int t,
    float* __restrict__ hout,
    const __nv_bfloat16* __restrict__ hb_in,
    const __nv_bfloat16* __restrict__ ab_in,
    __nv_bfloat16* __restrict__ hb_out,
    int mh, int nb, const float bias[2][4], const float* __restrict__ corr)
{
    const int NCH  = DEC ? 36 : 20;
    const int KS16 = DEC ? 72 : 40;
    int tid = threadIdx.x;
    int l = tid & 31, wrp = tid >> 5;
    bool prod = (wrp >= 8);
    int wm = wrp & 3, wn = (wrp >> 2) & 1;
    int gid = l >> 2, t0 = l & 3;
    int m16 = mh * 64 + wm * 16;
    int arow = wm * 16 + ((l >> 3) & 1) * 8 + (l & 7);
    int halfsel = l >> 4;

    int tid2 = tid - 256;
    const __nv_bfloat16 *s0 = nullptr, *s1 = nullptr, *s2 = nullptr;
    uint32_t abase = s2u(Ab);
    if (prod) {
        int rowb = mh * 64 + (tid2 >> 2);
        s0 = xbase + (size_t)rowb * ((DEC ? LEz : LCz) * Vz) + (size_t)t * Vz;
        s1 = hb_in + rowb * Hz;
        s2 = DEC ? (ab_in + rowb * Hz) : s1;
        #pragma unroll
        for (int p = 0; p < 5; p++) {
            issue_stage<DEC>(abase, p, p, s0, s1, s2, tid2);
            CPA_COMMIT();
        }
    }

    float acc[2][4];
    #pragma unroll
    for (int i = 0; i < 2; i++)
        #pragma unroll
        for (int k = 0; k < 4; k++) acc[i][k] = 0.f;

    int buf = 0, nbuf = 5;
    for (int cc = 0; cc < NCH; cc++) {
        if (prod) CPA_WAIT4();
        __syncthreads();
        if (!prod) {
            uint32_t ab = abase + (uint32_t)(buf * (64 * AROWS)) * 16;
            #pragma unroll
            for (int kk = 0; kk < 2; kk++) {
                int ccol = (kk * 2 + halfsel) ^ (arow & 3);
                uint32_t addr = ab + (uint32_t)(arow * AROWS + ccol) * 16;
                uint32_t a0, a1, a2, a3;
                asm volatile("ldmatrix.sync.aligned.m8n8.x4.shared.b16 {%0,%1,%2,%3}, [%4];"
                             : "=r"(a0), "=r"(a1), "=r"(a2), "=r"(a3) : "r"(addr));
                uint4 wv = Wp[((size_t)wn * KS16 + (cc * 2 + kk)) * 32 + l];
                mma16(acc[0], a0, a1, a2, a3, wv.x, wv.y);
                mma16(acc[1], a0, a1, a2, a3, wv.z, wv.w);
            }
        } else if (cc + 5 < NCH) {
            issue_stage<DEC>(abase, nbuf, cc + 5, s0, s1, s2, tid2);
            CPA_COMMIT();
        }
        if (++buf == 6) buf = 0;
        if (++nbuf == 6) nbuf = 0;
    }

    if (!prod) {
        bool evn = ((t0 & 1) == 0);
        #pragma unroll
        for (int hh = 0; hh < 2; hh++) {
            float d0 = acc[hh][0], d1 = acc[hh][1], d2 = acc[hh][2], d3 = acc[hh][3];
            float x0 = __shfl_xor_sync(0xffffffffu, d0, 1);
            float x1 = __shfl_xor_sync(0xffffffffu, d1, 1);
            float x2 = __shfl_xor_sync(0xffffffffu, d2, 1);
            float x3 = __shfl_xor_sync(0xffffffffu, d3, 1);
            int j = nb * 8 + wn * 4 + hh * 2 + (t0 >> 1);
            int b = m16 + gid + (evn ? 0 : 8);
            float gi = (evn ? d0 : x2) + bias[hh][0];
            float gf = (evn ? d1 : x3) + bias[hh][1];
            float gg = (evn ? x0 : d2) + bias[hh][2];
            float go = (evn ? x1 : d3) + bias[hh][3];
            if (corr) {
                gi -= corr[b * 2048 + j];
                gf -= corr[b * 2048 + 512 + j];
                gg -= corr[b * 2048 + 1024 + j];
                go -= corr[b * 2048 + 1536 + j];
            }
            float c  = g_c[b * Hz + j];
            float cn = sigm(gf) * c + sigm(gi) * tanhf(gg);
            float hn = sigm(go) * tanhf(cn);
            g_c[b * Hz + j] = cn;
            hout[b * Hz + j] = hn;
            hb_out[b * Hz + j] = __float2bfloat16(hn);
            if (!DEC)
                g_enc[((size_t)b * LCz + t) * Hz + j] = __float2bfloat16(hn);
        }
    }
}

__device__ __forceinline__ void load_bias2(float bias[2][4],
    const float* __restrict__ bih, const float* __restrict__ bhh,
    const float* __restrict__ beff, int nb)
{
    int l = threadIdx.x & 31;
    int wn = ((threadIdx.x >> 5) >> 2) & 1;
    int t0 = l & 3;
    #pragma unroll
    for (int hh = 0; hh < 2; hh++) {
        int j = nb * 8 + wn * 4 + hh * 2 + (t0 >> 1);
        #pragma unroll
        for (int g4 = 0; g4 < 4; g4++)
            bias[hh][g4] = beff ? beff[g4 * Hz + j] : (bih[g4 * Hz + j] + bhh[g4 * Hz + j]);
    }
}

// ---------------- pad compaction (512 threads) ------------------------------
__device__ void comp_scan(int b, const int* __restrict__ C_pad, float* smf)
{
    int* sm = (int*)smf;
    int tid = threadIdx.x, lane = tid & 31, w = tid >> 5;
    int f = (C_pad[b * LCz + tid] == 0) ? 1 : 0;
    int x = f;
    #pragma unroll
    for (int o = 1; o < 32; o <<= 1) {
        int y = __shfl_up_sync(0xffffffffu, x, o);
        if (lane >= o) x += y;
    }
    if (lane == 31) sm[w] = x;
    __syncthreads();
    if (tid == 0) {
        int run = 0;
        for (int i = 0; i < 16; i++) { int v = sm[i]; sm[16 + i] = run; run += v; }
        sm[32] = run;
    }
    __syncthreads();
    int excl = sm[16 + w] + x - f;
    if (f) g_lidx[b * LCz + excl] = tid;
    if (tid == 0) g_Lb[b] = sm[32];
    __syncthreads();
}

__device__ void build_F(int b, const float* __restrict__ att_W, float* se)
{
    int tid = threadIdx.x;
    int Lb = g_Lb[b];
    for (int ci0 = 0; ci0 < Lb; ci0 += 32) {
        int R = min(32, Lb - ci0);
        for (int idx = tid; idx < R * 512; idx += NTHR) {
            int r = idx >> 9, j = idx & 511;
            int l = g_lidx[b * LCz + ci0 + r];
            __nv_bfloat16 hv = g_enc[((size_t)b * LCz + l) * Hz + j];
            float fv = __bfloat162float(hv);
            se[j * 36 + r] = fv;
            g_encc[((size_t)b * LCz + ci0 + r) * Hz + j] = f2fp8(fv);
        }
        __syncthreads();
        {
            int k = tid;
            float acc[32];
            #pragma unroll
            for (int i = 0; i < 32; i++) acc[i] = 0.f;
            for (int j = 0; j < 512; j++) {
                float wv = att_W[j * Hz + k];
                #pragma unroll
                for (int g4 = 0; g4 < 8; g4++) {
                    float4 e = *(const float4*)&se[j * 36 + g4 * 4];
                    acc[g4 * 4 + 0] += e.x * wv;
                    acc[g4 * 4 + 1] += e.y * wv;
                    acc[g4 * 4 + 2] += e.z * wv;
                    acc[g4 * 4 + 3] += e.w * wv;
                }
            }
            for (int r = 0; r < R; r++)
                g_Fc[((size_t)b * LCz + ci0 + r) * Hz + k] = f2fp8(acc[r]);
        }
        __syncthreads();
    }
}

__device__ void calc_u(int b, const float* __restrict__ out_W,
                       const float* __restrict__ out_b, float* scr)
{
    int tid = threadIdx.x;
    __syncthreads();
    if (tid < Hz) scr[tid] = g_h[0][b * Hz + tid];
    __syncthreads();
    if (tid < Hz) {
        const float* wr = out_W + (size_t)tid * (2 * Hz);
        float acc = 0.f;
        for (int h = 0; h < Hz; h += 4) {
            float4 w4 = *(const float4*)(wr + h);
            acc += w4.x * scr[h] + w4.y * scr[h + 1] + w4.z * scr[h + 2] + w4.w * scr[h + 3];
        }
        g_u[b * Hz + tid] = acc + out_b[tid];
    }
    __syncthreads();
}

__device__ void compose(const float* __restrict__ dec_Wih, const float* __restrict__ dec_Whh,
                        const float* __restrict__ dec_bih, const float* __restrict__ dec_bhh,
                        const float* __restrict__ out_W, const float* __restrict__ out_b)
{
    int bid = blockIdx.x, tid = threadIdx.x;
    if (tid >= 256) return;
    int g = bid * 16 + (tid >> 4);
    int c0 = (tid & 15) * 32;
    const float* wv = dec_Wih + (size_t)g * (Vz + Hz) + Vz;
    #pragma unroll 1
    for (int pass = 0; pass < 2; pass++) {
        float acc[32];
        #pragma unroll
        for (int i = 0; i < 32; i++) acc[i] = 0.f;
        float accb = 0.f;
        for (int v = 0; v < Hz; v++) {
            float w = wv[v];
            const float* owr = out_W + (size_t)v * (2 * Hz) + pass * Hz + c0;
            #pragma unroll
            for (int i = 0; i < 32; i += 4) {
                float4 o = *(const float4*)(owr + i);
                acc[i] += w * o.x; acc[i + 1] += w * o.y;
                acc[i + 2] += w * o.z; acc[i + 3] += w * o.w;
            }
            if (pass == 0) accb += w * out_b[v];
        }
        if (pass == 0) {
            for (int i = 0; i < 32; i++)
                g_Weff[(size_t)g * Hz + c0 + i] = dec_Whh[(size_t)g * Hz + c0 + i] + acc[i];
            if ((tid & 15) == 0) g_beff[g] = dec_bih[g] + dec_bhh[g] + accb;
        } else {
            for (int i = 0; i < 32; i++)
                g_Wcomp[(size_t)g * Hz + c0 + i] = acc[i];
        }
    }
}

__device__ void calc_c(int b, const float* __restrict__ dec_Wih, float* scr)
{
    int tid = threadIdx.x;
    __syncthreads();
    if (tid < Hz) scr[tid] = g_u[b * Hz + tid];
    __syncthreads();
    for (int g = tid; g < 2048; g += NTHR) {
        const float* wv = dec_Wih + (size_t)g * (Vz + Hz) + Vz;
        float acc = 0.f;
        for (int v = 0; v < Hz; v += 4) {
            float4 w4 = *(const float4*)(wv + v);
            acc += w4.x * scr[v] + w4.y * scr[v + 1] + w4.z * scr[v + 2] + w4.w * scr[v + 3];
        }
        g_corr[b * 2048 + g] = acc;
    }
}

// ---------------- attention (group A, fp8 streams) ---------------------------
__device__ void attn_block(int b, const float* __restrict__ hcur,
                           float* __restrict__ dst, __nv_bfloat16* __restrict__ dstb,
                           float* sm)
{
    float* ss   = sm;
    float* red  = sm + 512;
    float* sca  = sm + 520;
    float* wacc = sm + 528;
    int tid = threadIdx.x, lane = tid & 31, w = tid >> 5;
    int Lb = g_Lb[b];

    float qreg[16];
    const float* hb = hcur + b * Hz + lane * 16;
    #pragma unroll
    for (int i = 0; i < 16; i += 4) {
        float4 v = *(const float4*)(hb + i);
        qreg[i] = v.x; qreg[i + 1] = v.y; qreg[i + 2] = v.z; qreg[i + 3] = v.w;
    }

    const unsigned char* Fb = g_Fc + (size_t)b * LCz * Hz;
    #pragma unroll 4
    for (int l = w; l < Lb; l += 8) {
        uint4 u0 = *(const uint4*)(Fb + (size_t)l * Hz + lane * 16);  // 16 fp8
        const unsigned short* p2 = (const unsigned short*)&u0;
        float acc = 0.f;
        #pragma unroll
        for (int i = 0; i < 8; i++) {
            float2 f = fp8x2_to_f2(p2[i]);
            acc += f.x * qreg[2 * i] + f.y * qreg[2 * i + 1];
        }
        #pragma unroll
        for (int o = 16; o > 0; o >>= 1) acc += __shfl_xor_sync(0xffffffffu, acc, o);
        if (lane == 0) ss[l] = acc;
    }
    NB(1);

    float m = -INFINITY;
    for (int l = tid; l < Lb; l += 256) m = fmaxf(m, ss[l]);
    #pragma unroll
    for (int o = 16; o > 0; o >>= 1) m = fmaxf(m, __shfl_xor_sync(0xffffffffu, m, o));
    if (lane == 0) red[w] = m;
    NB(1);
    if (tid == 0) {
        float mm = red[0];
        for (int i = 1; i < 8; i++) mm = fmaxf(mm, red[i]);
        sca[0] = mm;
    }
    NB(1);
    float bmax = sca[0];

    float s = 0.f;
    for (int l = tid; l < Lb; l += 256) {
        float e = expf(ss[l] - bmax);
        ss[l] = e;
        s += e;
    }
    #pragma unroll
    for (int o = 16; o > 0; o >>= 1) s += __shfl_xor_sync(0xffffffffu, s, o);
    if (lane == 0) red[w] = s;
    NB(1);
    if (tid == 0) {
        float t2 = 0.f;
        for (int i = 0; i < 8; i++) t2 += red[i];
        sca[1] = t2;
    }
    NB(1);
    float inv = 1.f / sca[1];

    float acc2[16];
    #pragma unroll
    for (int i = 0; i < 16; i++) acc2[i] = 0.f;
    const unsigned char* Eb = g_encc + (size_t)b * LCz * Hz;
    #pragma unroll 4
    for (int l = w; l < Lb; l += 8) {
        float d = ss[l];
        uint4 u0 = *(const uint4*)(Eb + (size_t)l * Hz + lane * 16);
        const unsigned short* p2 = (const unsigned short*)&u0;
        #pragma unroll
        for (int i = 0; i < 8; i++) {
            float2 f = fp8x2_to_f2(p2[i]);
            acc2[2 * i]     += d * f.x;
            acc2[2 * i + 1] += d * f.y;
        }
    }
    #pragma unroll
    for (int i = 0; i < 16; i++) wacc[w * Hz + lane * 16 + i] = acc2[i];
    NB(1);

    for (int h = tid; h < Hz; h += 256) {
        float t2 = 0.f;
        #pragma unroll
        for (int ww = 0; ww < 8; ww++) t2 += wacc[ww * Hz + h];
        float v = t2 * inv;
        dst[b * Hz + h] = v;
        dstb[b * Hz + h] = __float2bfloat16(v);
    }
}

// ---------------- out-proj (group B) -----------------------------------------
__device__ void outproj16(const float* __restrict__ h_src,
                          const float* __restrict__ attn_src,
                          const float* __restrict__ out_b,
                          float* __restrict__ vout, float* sm, int mh, int t256)
{
    NB(2);
    int bid = blockIdx.x;
    int gb = bid >> 1;
    int m0 = mh * 64 + (gb & 3) * 16;
    int n0 = ((gb >> 2) & 7) * 64;
    int split = (gb >> 5) & 1;
    const float* Asrc = (split == 0) ? h_src : attn_src;

    int arow = t256 & 15, akg = t256 >> 4;
    int wr = t256 >> 2, wkg = t256 & 3;
    int m = t256 >> 4, ng = t256 & 15;

    const float* ap = Asrc + (size_t)(m0 + arow) * Hz + akg * 8;
    const __nv_bfloat16* wp = g_oWb16 + (size_t)(n0 + wr) * 1024 + split * Hz + wkg * 8;

    float4 pa0, pa1;
    uint4 pw;
    if (t256 < 64) { pa0 = *(const float4*)ap; pa1 = *(const float4*)(ap + 4); }
    pw = *(const uint4*)wp;

    float acc[4] = {0.f, 0.f, 0.f, 0.f};
    for (int it = 0; it < 16; it++) {
        float* As = sm + (it & 1) * 2560;
        float* Ws = As + 512;
        if (t256 < 64) {
            int kb = akg * 8;
            As[(kb + 0) * 16 + arow] = pa0.x; As[(kb + 1) * 16 + arow] = pa0.y;
            As[(kb + 2) * 16 + arow] = pa0.z; As[(kb + 3) * 16 + arow] = pa0.w;
            As[(kb + 4) * 16 + arow] = pa1.x; As[(kb + 5) * 16 + arow] = pa1.y;
            As[(kb + 6) * 16 + arow] = pa1.z; As[(kb + 7) * 16 + arow] = pa1.w;
        }
        {
            int kb = wkg * 8;
            const __nv_bfloat162* ph = (const __nv_bfloat162*)&pw;
            #pragma unroll
            for (int i = 0; i < 4; i++) {
                float2 f = __bfloat1622float2(ph[i]);
                Ws[(kb + 2 * i) * 64 + wr]     = f.x;
                Ws[(kb + 2 * i + 1) * 64 + wr] = f.y;
            }
        }
        NB(2);
        if (it < 15) {
            if (t256 < 64) {
                const float* ap2 = ap + (it + 1) * 32;
                pa0 = *(const float4*)ap2; pa1 = *(const float4*)(ap2 + 4);
            }
            pw = *(const uint4*)(wp + (it + 1) * 32);
        }
        #pragma unroll
        for (int kk = 0; kk < 32; kk++) {
            float a = As[kk * 16 + m];
            float4 w4 = *(const float4*)&Ws[kk * 64 + ng * 4];
            acc[0] += a * w4.x; acc[1] += a * w4.y;
            acc[2] += a * w4.z; acc[3] += a * w4.w;
        }
    }
    NB(2);
    #pragma unroll
    for (int i = 0; i < 4; i++) {
        int n = n0 + ng * 4 + i;
        float v = acc[i] + ((split == 0) ? out_b[n] : 0.f);
        vout[(size_t)split * BHS + (m0 + m) * Hz + n] = v;
    }
}

// ---------------- logits + CE ------------------------------------------------
__device__ void logits_ce(int b, int tt, const int* __restrict__ E,
                          const float* __restrict__ vp,
                          const float* __restrict__ voc_b, float* sm,
                          int t256, int barid)
{
    float* st = sm;
    float* sl = sm + 512;
    int lane = t256 & 31, w = t256 >> 5;
    NB(barid);

    for (int i = t256; i < Hz; i += 256)
        st[i] = tanhf(vp[b * Hz + i] + vp[BHS + b * Hz + i]);
    NB(barid);

    float sreg[16];
    #pragma unroll
    for (int i = 0; i < 16; i++) sreg[i] = st[lane * 16 + i];

    for (int v = w; v < Vz; v += 8) {
        const __nv_bfloat16* wr = g_vocb16 + (size_t)v * Hz + lane * 16;
        uint4 u0 = *(const uint4*)wr;
        uint4 u1 = *(const uint4*)(wr + 8);
        const __nv_bfloat162* h0 = (const __nv_bfloat162*)&u0;
        const __nv_bfloat162* h1 = (const __nv_bfloat162*)&u1;
        float acc = 0.f;
        #pragma unroll
        for (int i = 0; i < 4; i++) {
            float2 f0 = __bfloat1622float2(h0[i]);
            float2 f1 = __bfloat1622float2(h1[i]);
            acc += f0.x * sreg[2 * i]     + f0.y * sreg[2 * i + 1];
            acc += f1.x * sreg[8 + 2 * i] + f1.y * sreg[8 + 2 * i + 1];
        }
        #pragma unroll
        for (int o = 16; o > 0; o >>= 1) acc += __shfl_xor_sync(0xffffffffu, acc, o);
        if (lane == 0) sl[v] = acc + voc_b[v];
    }
    NB(barid);

    if (w == 0) {
        float m = -INFINITY;
        for (int v = lane; v < Vz; v += 32) m = fmaxf(m, sl[v]);
        #pragma unroll
        for (int o = 16; o > 0; o >>= 1) m = fmaxf(m, __shfl_xor_sync(0xffffffffu, m, o));
        float s = 0.f;
        for (int v = lane; v < Vz; v += 32) s += expf(sl[v] - m);
        #pragma unroll
        for (int o = 16; o > 0; o >>= 1) s += __shfl_xor_sync(0xffffffffu, s, o);
        if (lane == 0) {
            int tv = E[b * LEz + tt + 1];
            int idx = b * TDEC + tt;
            if (tv != 0) { g_nll[idx] = m + logf(s) - sl[tv]; g_msk[idx] = 1.f; }
            else         { g_nll[idx] = 0.f;                  g_msk[idx] = 0.f; }
        }
    }
    NB(barid);
}

// ---------------- the single persistent kernel ------------------------------
__global__ void __launch_bounds__(NTHR, 1) persist_kernel(
    const float* __restrict__ C,       const int* __restrict__ C_pad,
    const int* __restrict__ E,         const float* __restrict__ E_emb,
    const float* __restrict__ enc_Wih, const float* __restrict__ enc_Whh,
    const float* __restrict__ enc_bih, const float* __restrict__ enc_bhh,
    const float* __restrict__ dec_Wih, const float* __restrict__ dec_Whh,
    const float* __restrict__ dec_bih, const float* __restrict__ dec_bhh,
    const float* __restrict__ att_W,   const float* __restrict__ out_W,
    const float* __restrict__ out_b,   const float* __restrict__ voc_W,
    const float* __restrict__ voc_b,   float* __restrict__ out)
{
    extern __shared__ __align__(16) float4 dsm[];
    uint4*  Wp   = (uint4*)dsm;
    float4* Ab   = dsm + 4608;
    float*  scrA = (float*)(dsm + 6528);
    float*  scrB = scrA + 4624;

    int bid = blockIdx.x, tid = threadIdx.x;
    int lane = tid & 31, w = tid >> 5;
    int mh = bid & 1, nb = bid >> 1;
    int mhb = mh * 64 + nb;

    // ---- init + bf16 pre-conversions ----
    for (int i = bid * NTHR + tid; i < BHS; i += NBLK * NTHR) {
        g_h[0][i] = 0.f; g_c[i] = 0.f;
        g_hb16[0][i] = __float2bfloat16(0.f);
        g_ab16[0][i] = __float2bfloat16(0.f);
        g_ab16[1][i] = __float2bfloat16(0.f);
    }
    float* vpf = (float*)g_vp;
    for (int i = bid * NTHR + tid; i < 4 * BHS; i += NBLK * NTHR) vpf[i] = 0.f;
    float* apf = (float*)g_attn2;
    for (int i = bid * NTHR + tid; i < 2 * BHS; i += NBLK * NTHR) apf[i] = 0.f;
    for (int i = bid * NTHR + tid; i < Vz * Hz; i += NBLK * NTHR)
        g_vocb16[i] = __float2bfloat16(voc_W[i]);
    for (size_t i = bid * NTHR + tid; i < (size_t)Bz * LCz * Vz; i += NBLK * NTHR)
        g_Cb16[i] = __float2bfloat16(C[i]);
    for (size_t i = bid * NTHR + tid; i < (size_t)Bz * LEz * Vz; i += NBLK * NTHR)
        g_Eb16[i] = __float2bfloat16(E_emb[i]);
    for (int i = bid * NTHR + tid; i < 512 * 1024; i += NBLK * NTHR)
        g_oWb16[i] = __float2bfloat16(out_W[i]);
    gsync_all();

    // ---- encoder ----
    pack_Wb3(Wp, nb, 40, enc_Wih, Vz, Vz, enc_Whh, Hz, Hz, enc_Whh, Hz);
    __syncthreads();
    float biasE[2][4];
    load_bias2(biasE, enc_bih, enc_bhh, nullptr, nb);
    for (int t = 0; t < LCz; t++) {
        gates_step<false>(Wp, Ab, g_Cb16, t, g_h[1 - (t & 1)],
                          g_hb16[t & 1], nullptr, g_hb16[1 - (t & 1)],
                          mh, nb, biasE, nullptr);
        gsync_g(mh);
    }

    // ---- pre-decoder (own batch) ----
    comp_scan(mhb, C_pad, scrA);
    build_F(mhb, att_W, (float*)dsm);
    calc_u(mhb, out_W, out_b, scrA);
    calc_c(mhb, dec_Wih, scrA);

    // ---- composition (shared) => full barrier ----
    compose(dec_Wih, dec_Whh, dec_bih, dec_bhh, out_W, out_b);
    gsync_all();

    // ---- decoder ----
    pack_Wb3(Wp, nb, 72, dec_Wih, Vz + Hz, Vz, g_Weff, Hz, Hz, g_Wcomp, Hz);
    __syncthreads();
    float biasD[2][4];
    load_bias2(biasD, dec_bih, dec_bhh, g_beff, nb);

    for (int t = 0; t < TDEC; t++) {
        // Phase A: gates(t)
        gates_step<true>(Wp, Ab, g_Eb16, t, g_h[1 - (t & 1)],
                         g_hb16[t & 1], g_ab16[(t + 1) & 1], g_hb16[1 - (t & 1)],
                         mh, nb, biasD, (t == 0) ? g_corr : nullptr);
        gsync_g(mh);

        // Phase B: group A attn(t) || group B outproj(t-1) + CE(t-2)
        if (tid < 256) {
            attn_block(mhb, g_h[1 - (t & 1)], g_attn2[t & 1], g_ab16[t & 1], scrA);
        } else {
            int t256 = tid - 256;
            if (t >= 1)
                outproj16(g_h[t & 1], g_attn2[(t + 1) & 1], out_b,
                          (float*)g_vp[(t + 1) & 1], scrB, mh, t256);
            if (t >= 2)
                logits_ce(mhb, t - 2, E, (const float*)g_vp[t & 1], voc_b, scrB,
                          t256, 2);
        }
        gsync_g(mh);
    }

    // ---- tail: V(510) (group B) || CE(509) (group A); then CE(510) ----
    if (tid < 256) {
        logits_ce(mhb, TDEC - 2, E, (const float*)g_vp[1], voc_b, scrA, tid, 1);
    } else {
        outproj16(g_h[1], g_attn2[0], out_b, (float*)g_vp[0], scrB, mh, tid - 256);
    }
    gsync_g(mh);
    if (tid < 256)
        logits_ce(mhb, TDEC - 1, E, (const float*)g_vp[0], voc_b, scrA, tid, 1);
    __syncthreads();

    // ---- per-batch reduction ----
    {
        float s = 0.f, c = 0.f;
        for (int i = tid; i < TDEC; i += NTHR) {
            s += g_nll[mhb * TDEC + i];
            c += g_msk[mhb * TDEC + i];
        }
        #pragma unroll
        for (int o = 16; o > 0; o >>= 1) {
            s += __shfl_xor_sync(0xffffffffu, s, o);
            c += __shfl_xor_sync(0xffffffffu, c, o);
        }
        __syncthreads();
        if (lane == 0) { scrA[w] = s; scrA[16 + w] = c; }
        __syncthreads();
        if (tid == 0) {
            float ts = 0.f, tc = 0.f;
            for (int i = 0; i < 16; i++) { ts += scrA[i]; tc += scrA[16 + i]; }
            g_ps[bid] = ts; g_pc[bid] = tc;
        }
    }
    gsync_all();
    if (bid == 0 && tid == 0) {
        float ts = 0.f, tc = 0.f;
        for (int i = 0; i < NBLK; i++) { ts += g_ps[i]; tc += g_pc[i]; }
        out[0] = ts / fmaxf(tc, 1.f);
    }
}

// ---------------- host entry ------------------------------------------------
extern "C" void kernel_launch(void* const* d_in, const int* in_sizes, int n_in,
                              void* d_out, int out_size)
{
    cudaFuncSetAttribute((const void*)persist_kernel,
                         cudaFuncAttributeMaxDynamicSharedMemorySize, SMEM_BYTES);
    persist_kernel<<<NBLK, NTHR, SMEM_BYTES>>>(
        (const float*)d_in[0],  (const int*)d_in[1],
        (const int*)d_in[2],    (const float*)d_in[3],
        (const float*)d_in[4],  (const float*)d_in[5],
        (const float*)d_in[6],  (const float*)d_in[7],
        (const float*)d_in[8],  (const float*)d_in[9],
        (const float*)d_in[10], (const float*)d_in[11],
        (const float*)d_in[12], (const float*)d_in[13],
        (const float*)d_in[14], (const float*)d_in[15],
        (const float*)d_in[16], (float*)d_out);
}

// round 15
// speedup vs baseline: 1.9384x; 1.0815x over previous
#include <cuda_runtime.h>
#include <cuda_bf16.h>
#include <cuda_fp16.h>
#include <cuda_fp8.h>
#include <math.h>
#include <stdint.h>

#define Bz   128
#define LCz  512
#define LEz  512
#define Hz   512
#define Vz   128
#define TDEC 511
#define NBLK 128
#define NTHR 512
#define BHS  (Bz * Hz)   // 65536

// dynamic smem (float4 units):
//   Wp [0, 4608)      : bf16 W fragment pack (72KB)
//   Ab [4608, 13888)  : A panel, 64 rows x 145 f4 stride (148.5KB)  [phase A]
//   scrA/scrB alias Ab : phase-B scratch (attn 18.5KB | outproj/CE 20.5KB)
#define SMEM_BYTES 222208
#define ASTRIDE 145

#define NB(id) asm volatile("bar.sync %0, 256;" :: "r"(id) : "memory")

// ---------------- static device scratch -------------------------------------
__device__ __align__(16) float g_h[2][BHS];
__device__ __align__(16) __nv_bfloat16 g_hb16[2][BHS];
__device__ __align__(16) float g_c[BHS];
__device__ __align__(16) float g_vp[2][2][BHS];
__device__ __align__(16) float g_attn2[2][BHS];
__device__ __align__(16) __nv_bfloat16 g_ab16[2][BHS];
__device__ __align__(16) __nv_bfloat16 g_Cb16[(size_t)Bz * LCz * Vz];
__device__ __align__(16) __nv_bfloat16 g_Eb16[(size_t)Bz * LEz * Vz];
__device__ __align__(16) __nv_bfloat16 g_enc [(size_t)Bz * LCz * Hz];
__device__ __align__(16) unsigned char g_encc[(size_t)Bz * LCz * Hz];   // fp8
__device__ __align__(16) unsigned char g_Fc  [(size_t)Bz * LCz * Hz];   // fp8
__device__ __align__(16) __nv_bfloat16 g_vocb16[Vz * Hz];
__device__ __align__(16) __nv_bfloat16 g_oWb16[512 * 1024];
__device__ __align__(16) float g_Weff [2048 * Hz];
__device__ __align__(16) float g_Wcomp[2048 * Hz];
__device__ float g_beff[2048];
__device__ float g_u[Bz * Hz];
__device__ float g_corr[Bz * 2048];
__device__ int g_lidx[Bz * LCz];
__device__ int g_Lb[Bz];
__device__ float g_nll[Bz * TDEC];
__device__ float g_msk[Bz * TDEC];
__device__ float g_ps[NBLK], g_pc[NBLK];
// full-grid barrier (fence version, rare)
__device__ unsigned g_arr1[16 * 32];
__device__ unsigned g_arr0;
__device__ volatile unsigned g_gen;
// per-half two-level monotonic barrier
__device__ unsigned g_ga[2 * 8 * 32];   // group counters (128B apart)
__device__ unsigned g_gm[2 * 32];       // masters
__device__ unsigned g_gg[2 * 32];       // generations

__device__ __forceinline__ float sigm(float x) { return 1.f / (1.f + expf(-x)); }

__device__ __forceinline__ uint32_t s2u(const void* p) {
    return (uint32_t)__cvta_generic_to_shared(p);
}
__device__ __forceinline__ uint32_t bpack(float lo, float hi) {
    __nv_bfloat162 v = __floats2bfloat162_rn(lo, hi);
    return *(uint32_t*)&v;
}
__device__ __forceinline__ void mma16(float acc[4],
    uint32_t a0, uint32_t a1, uint32_t a2, uint32_t a3,
    uint32_t b0, uint32_t b1)
{
    asm volatile("mma.sync.aligned.m16n8k16.row.col.f32.bf16.bf16.f32 "
        "{%0,%1,%2,%3},{%4,%5,%6,%7},{%8,%9},{%0,%1,%2,%3};"
        : "+f"(acc[0]), "+f"(acc[1]), "+f"(acc[2]), "+f"(acc[3])
        : "r"(a0), "r"(a1), "r"(a2), "r"(a3), "r"(b0), "r"(b1));
}
#define CPA16(dst, src) asm volatile("cp.async.cg.shared.global [%0], [%1], 16;" :: "r"(dst), "l"(src))

__device__ __forceinline__ unsigned char f2fp8(float x) {
    return (unsigned char)__nv_cvt_float_to_fp8(x, __NV_SATFINITE, __NV_E4M3);
}
__device__ __forceinline__ float2 fp8x2_to_f2(unsigned short p) {
    __half2_raw hr = __nv_cvt_fp8x2_to_halfraw2((__nv_fp8x2_storage_t)p, __NV_E4M3);
    return __half22float2(*(__half2*)&hr);
}

// ---------------- memory-order helpers --------------------------------------
__device__ __forceinline__ unsigned ld_cg_u32(const unsigned* p) {
    unsigned v;
    asm volatile("ld.global.cg.u32 %0, [%1];" : "=r"(v) : "l"(p) : "memory");
    return v;
}
__device__ __forceinline__ unsigned ld_acq_u32(const unsigned* p) {
    unsigned v;
    asm volatile("ld.acquire.gpu.global.u32 %0, [%1];" : "=r"(v) : "l"(p) : "memory");
    return v;
}
__device__ __forceinline__ unsigned atom_add_acqrel(unsigned* p, unsigned v) {
    unsigned old;
    asm volatile("atom.acq_rel.gpu.global.add.u32 %0, [%1], %2;" : "=r"(old) : "l"(p), "r"(v) : "memory");
    return old;
}
__device__ __forceinline__ void st_rel_u32(unsigned* p, unsigned v) {
    asm volatile("st.release.gpu.global.u32 [%0], %1;" :: "l"(p), "r"(v) : "memory");
}

// full-grid barrier (rare; proven fence version)
__device__ __forceinline__ void gsync_all() {
    __syncthreads();
    if (threadIdx.x == 0) {
        __threadfence();
        unsigned gen = g_gen;
        unsigned grp = blockIdx.x >> 3;
        if (atomicAdd(&g_arr1[grp * 32], 1u) == 7u) {
            if (atomicAdd(&g_arr0, 1u) == 15u) {
                #pragma unroll
                for (int i = 0; i < 16; i++) g_arr1[i * 32] = 0u;
                g_arr0 = 0u;
                __threadfence();
                g_gen = gen + 1u;
            } else {
                while (g_gen == gen) __nanosleep(32);
            }
        } else {
            while (g_gen == gen) __nanosleep(32);
        }
        __threadfence();
    }
    __syncthreads();
}

// per-half barrier: two-level monotonic acq_rel chain (8 groups x 8 blocks)
__device__ __forceinline__ void gsync_g(int mh, int nb) {
    __syncthreads();
    if (threadIdx.x == 0) {
        unsigned* grp  = &g_ga[(mh * 8 + (nb >> 3)) * 32];
        unsigned* mst  = &g_gm[mh * 32];
        unsigned* genp = &g_gg[mh * 32];
        unsigned gen = ld_cg_u32(genp);
        bool released = false;
        if ((atom_add_acqrel(grp, 1u) & 7u) == 7u) {
            if ((atom_add_acqrel(mst, 1u) & 7u) == 7u) {
                st_rel_u32(genp, gen + 1u);
                released = true;
            }
        }
        if (!released) {
            while (ld_cg_u32(genp) == gen) __nanosleep(32);
            (void)ld_acq_u32(genp);
        }
    }
    __syncthreads();
}

// ---------------- W fragment pack (bf16, 3 K-segments) ----------------------
__device__ __forceinline__ float wget(int grow, int k,
    const float* W0, int ld0, int K0,
    const float* W1, int ld1, int K1,
    const float* W2, int ld2)
{
    if (k < K0) return W0[(size_t)grow * ld0 + k];
    if (k < K0 + K1) return W1[(size_t)grow * ld1 + (k - K0)];
    return W2[(size_t)grow * ld2 + (k - K0 - K1)];
}

__device__ void pack_Wb3(uint4* Wp, int nb, int KS16,
    const float* W0, int ld0, int K0,
    const float* W1, int ld1, int K1,
    const float* W2, int ld2)
{
    for (int idx = threadIdx.x; idx < 2 * KS16 * 32; idx += NTHR) {
        int wn  = idx / (KS16 * 32);
        int rem = idx - wn * (KS16 * 32);
        int s = rem >> 5, l = rem & 31;
        int gid = l >> 2, t0 = l & 3;
        uint32_t r[4];
        #pragma unroll
        for (int hh = 0; hh < 2; hh++) {
            int c = hh * 8 + gid;
            int jj = wn * 4 + (c >> 2);
            int gate = c & 3;
            int grow = gate * Hz + nb * 8 + jj;
            int k0 = s * 16 + t0 * 2;
            float w00 = wget(grow, k0,     W0, ld0, K0, W1, ld1, K1, W2, ld2);
            float w01 = wget(grow, k0 + 1, W0, ld0, K0, W1, ld1, K1, W2, ld2);
            float w10 = wget(grow, k0 + 8, W0, ld0, K0, W1, ld1, K1, W2, ld2);
            float w11 = wget(grow, k0 + 9, W0, ld0, K0, W1, ld1, K1, W2, ld2);
            r[hh * 2]     = bpack(w00, w01);
            r[hh * 2 + 1] = bpack(w10, w11);
        }
        Wp[idx] = make_uint4(r[0], r[1], r[2], r[3]);
    }
}

// ---------------- gates GEMM: bulk A publish, sync-free mainloop ------------
template<bool DEC>
__device__ void gates_step(
    const uint4* __restrict__ Wp, float4* __restrict__ Ab,
    const __nv_bfloat16* __restrict__ xbase, int t,
    float* __restrict__ hout,
    const __nv_bfloat16* __restrict__ hb_in,
    const __nv_bfloat16* __restrict__ ab_in,
    __nv_bfloat16* __restrict__ hb_out,
    int mh, int nb, const float bias[2][4], const float* __restrict__ corr)
{
    const int NCH  = DEC ? 36 : 20;    // k32 chunks
    const int KS16 = DEC ? 72 : 40;
    int tid = threadIdx.x;
    int l = tid & 31, wrp = tid >> 5;
    bool prod = (wrp >= 8);
    int wm = wrp & 3, wn = (wrp >> 2) & 1;
    int gid = l >> 2, t0 = l & 3;
    int m16 = mh * 64 + wm * 16;
    int arow = wm * 16 + ((l >> 3) & 1) * 8 + (l & 7);
    int halfsel = l >> 4;

    uint32_t abase = s2u(Ab);

    if (prod) {
        int tid2 = tid - 256;
        int row = tid2 >> 2, cl = tid2 & 3;
        int rowb = mh * 64 + row;
        const __nv_bfloat16* s0 = xbase + (size_t)rowb * ((DEC ? LEz : LCz) * Vz) + (size_t)t * Vz;
        const __nv_bfloat16* s1 = hb_in + rowb * Hz;
        const __nv_bfloat16* s2 = DEC ? (ab_in + rowb * Hz) : s1;
        uint32_t dbase = abase + (uint32_t)(row * ASTRIDE) * 16;
        #pragma unroll
        for (int cc = 0; cc < NCH; cc++) {
            int kf4 = cc * 4 + cl;
            int k = kf4 * 8;
            const __nv_bfloat16* src =
                (k < 128) ? (s0 + k)
                : ((!DEC || k < 640) ? (s1 + (k - 128)) : (s2 + (k - 640)));
            CPA16(dbase + (uint32_t)(kf4 * 16), src);
        }
        asm volatile("cp.async.commit_group;");
        asm volatile("cp.async.wait_group 0;");
    }
    __syncthreads();   // single publish point

    if (!prod) {
        float acc[2][4];
        #pragma unroll
        for (int i = 0; i < 2; i++)
            #pragma unroll
            for (int k = 0; k < 4; k++) acc[i][k] = 0.f;

        uint32_t lbase = abase + (uint32_t)(arow * ASTRIDE + halfsel) * 16;
        const uint4* wpp = Wp + (size_t)wn * KS16 * 32 + l;
        #pragma unroll 4
        for (int cc = 0; cc < NCH; cc++) {
            #pragma unroll
            for (int kk = 0; kk < 2; kk++) {
                uint32_t addr = lbase + (uint32_t)((cc * 4 + kk * 2) * 16);
                uint32_t a0, a1, a2, a3;
                asm volatile("ldmatrix.sync.aligned.m8n8.x4.shared.b16 {%0,%1,%2,%3}, [%4];"
                             : "=r"(a0), "=r"(a1), "=r"(a2), "=r"(a3) : "r"(addr));
                uint4 wv = wpp[(size_t)(cc * 2 + kk) * 32];
                mma16(acc[0], a0, a1, a2, a3, wv.x, wv.y);
                mma16(acc[1], a0, a1, a2, a3, wv.z, wv.w);
            }
        }

        bool evn = ((t0 & 1) == 0);
        #pragma unroll
        for (int hh = 0; hh < 2; hh++) {
            float d0 = acc[hh][0], d1 = acc[hh][1], d2 = acc[hh][2], d3 = acc[hh][3];
            float x0 = __shfl_xor_sync(0xffffffffu, d0, 1);
            float x1 = __shfl_xor_sync(0xffffffffu, d1, 1);
            float x2 = __shfl_xor_sync(0xffffffffu, d2, 1);
            float x3 = __shfl_xor_sync(0xffffffffu, d3, 1);
            int j = nb * 8 + wn * 4 + hh * 2 + (t0 >> 1);
            int b = m16 + gid + (evn ? 0 : 8);
            float gi = (evn ? d0 : x2) + bias[hh][0];
            float gf = (evn ? d1 : x3) + bias[hh][1];
            float gg = (evn ? x0 : d2) + bias[hh][2];
            float go = (evn ? x1 : d3) + bias[hh][3];
            if (corr) {
                gi -= corr[b * 2048 + j];
                gf -= corr[b * 2048 + 512 + j];
                gg -= corr[b * 2048 + 1024 + j];
                go -= corr[b * 2048 + 1536 + j];
            }
            float c  = g_c[b * Hz + j];
            float cn = sigm(gf) * c + sigm(gi) * tanhf(gg);
            float hn = sigm(go) * tanhf(cn);
            g_c[b * Hz + j] = cn;
            hout[b * Hz + j] = hn;
            hb_out[b * Hz + j] = __float2bfloat16(hn);
            if (!DEC)
                g_enc[((size_t)b * LCz + t) * Hz + j] = __float2bfloat16(hn);
        }
    }
}

__device__ __forceinline__ void load_bias2(float bias[2][4],
    const float* __restrict__ bih, const float* __restrict__ bhh,
    const float* __restrict__ beff, int nb)
{
    int l = threadIdx.x & 31;
    int wn = ((threadIdx.x >> 5) >> 2) & 1;
    int t0 = l & 3;
    #pragma unroll
    for (int hh = 0; hh < 2; hh++) {
        int j = nb * 8 + wn * 4 + hh * 2 + (t0 >> 1);
        #pragma unroll
        for (int g4 = 0; g4 < 4; g4++)
            bias[hh][g4] = beff ? beff[g4 * Hz + j] : (bih[g4 * Hz + j] + bhh[g4 * Hz + j]);
    }
}

// ---------------- pad compaction (512 threads) ------------------------------
__device__ void comp_scan(int b, const int* __restrict__ C_pad, float* smf)
{
    int* sm = (int*)smf;
    int tid = threadIdx.x, lane = tid & 31, w = tid >> 5;
    int f = (C_pad[b * LCz + tid] == 0) ? 1 : 0;
    int x = f;
    #pragma unroll
    for (int o = 1; o < 32; o <<= 1) {
        int y = __shfl_up_sync(0xffffffffu, x, o);
        if (lane >= o) x += y;
    }
    if (lane == 31) sm[w] = x;
    __syncthreads();
    if (tid == 0) {
        int run = 0;
        for (int i = 0; i < 16; i++) { int v = sm[i]; sm[16 + i] = run; run += v; }
        sm[32] = run;
    }
    __syncthreads();
    int excl = sm[16 + w] + x - f;
    if (f) g_lidx[b * LCz + excl] = tid;
    if (tid == 0) g_Lb[b] = sm[32];
    __syncthreads();
}

__device__ void build_F(int b, const float* __restrict__ att_W, float* se)
{
    int tid = threadIdx.x;
    int Lb = g_Lb[b];
    for (int ci0 = 0; ci0 < Lb; ci0 += 32) {
        int R = min(32, Lb - ci0);
        for (int idx = tid; idx < R * 512; idx += NTHR) {
            int r = idx >> 9, j = idx & 511;
            int l = g_lidx[b * LCz + ci0 + r];
            __nv_bfloat16 hv = g_enc[((size_t)b * LCz + l) * Hz + j];
            float fv = __bfloat162float(hv);
            se[j * 36 + r] = fv;
            g_encc[((size_t)b * LCz + ci0 + r) * Hz + j] = f2fp8(fv);
        }
        __syncthreads();
        {
            int k = tid;
            float acc[32];
            #pragma unroll
            for (int i = 0; i < 32; i++) acc[i] = 0.f;
            for (int j = 0; j < 512; j++) {
                float wv = att_W[j * Hz + k];
                #pragma unroll
                for (int g4 = 0; g4 < 8; g4++) {
                    float4 e = *(const float4*)&se[j * 36 + g4 * 4];
                    acc[g4 * 4 + 0] += e.x * wv;
                    acc[g4 * 4 + 1] += e.y * wv;
                    acc[g4 * 4 + 2] += e.z * wv;
                    acc[g4 * 4 + 3] += e.w * wv;
                }
            }
            for (int r = 0; r < R; r++)
                g_Fc[((size_t)b * LCz + ci0 + r) * Hz + k] = f2fp8(acc[r]);
        }
        __syncthreads();
    }
}

__device__ void calc_u(int b, const float* __restrict__ out_W,
                       const float* __restrict__ out_b, float* scr)
{
    int tid = threadIdx.x;
    __syncthreads();
    if (tid < Hz) scr[tid] = g_h[0][b * Hz + tid];
    __syncthreads();
    if (tid < Hz) {
        const float* wr = out_W + (size_t)tid * (2 * Hz);
        float acc = 0.f;
        for (int h = 0; h < Hz; h += 4) {
            float4 w4 = *(const float4*)(wr + h);
            acc += w4.x * scr[h] + w4.y * scr[h + 1] + w4.z * scr[h + 2] + w4.w * scr[h + 3];
        }
        g_u[b * Hz + tid] = acc + out_b[tid];
    }
    __syncthreads();
}

__device__ void compose(const float* __restrict__ dec_Wih, const float* __restrict__ dec_Whh,
                        const float* __restrict__ dec_bih, const float* __restrict__ dec_bhh,
                        const float* __restrict__ out_W, const float* __restrict__ out_b)
{
    int bid = blockIdx.x, tid = threadIdx.x;
    if (tid >= 256) return;
    int g = bid * 16 + (tid >> 4);
    int c0 = (tid & 15) * 32;
    const float* wv = dec_Wih + (size_t)g * (Vz + Hz) + Vz;
    #pragma unroll 1
    for (int pass = 0; pass < 2; pass++) {
        float acc[32];
        #pragma unroll
        for (int i = 0; i < 32; i++) acc[i] = 0.f;
        float accb = 0.f;
        for (int v = 0; v < Hz; v++) {
            float w = wv[v];
            const float* owr = out_W + (size_t)v * (2 * Hz) + pass * Hz + c0;
            #pragma unroll
            for (int i = 0; i < 32; i += 4) {
                float4 o = *(const float4*)(owr + i);
                acc[i] += w * o.x; acc[i + 1] += w * o.y;
                acc[i + 2] += w * o.z; acc[i + 3] += w * o.w;
            }
            if (pass == 0) accb += w * out_b[v];
        }
        if (pass == 0) {
            for (int i = 0; i < 32; i++)
                g_Weff[(size_t)g * Hz + c0 + i] = dec_Whh[(size_t)g * Hz + c0 + i] + acc[i];
            if ((tid & 15) == 0) g_beff[g] = dec_bih[g] + dec_bhh[g] + accb;
        } else {
            for (int i = 0; i < 32; i++)
                g_Wcomp[(size_t)g * Hz + c0 + i] = acc[i];
        }
    }
}

__device__ void calc_c(int b, const float* __restrict__ dec_Wih, float* scr)
{
    int tid = threadIdx.x;
    __syncthreads();
    if (tid < Hz) scr[tid] = g_u[b * Hz + tid];
    __syncthreads();
    for (int g = tid; g < 2048; g += NTHR) {
        const float* wv = dec_Wih + (size_t)g * (Vz + Hz) + Vz;
        float acc = 0.f;
        for (int v = 0; v < Hz; v += 4) {
            float4 w4 = *(const float4*)(wv + v);
            acc += w4.x * scr[v] + w4.y * scr[v + 1] + w4.z * scr[v + 2] + w4.w * scr[v + 3];
        }
        g_corr[b * 2048 + g] = acc;
    }
}

// ---------------- attention (group A, fp8 streams) ---------------------------
__device__ void attn_block(int b, const float* __restrict__ hcur,
                           float* __restrict__ dst, __nv_bfloat16* __restrict__ dstb,
                           float* sm)
{
    float* ss   = sm;
    float* red  = sm + 512;
    float* sca  = sm + 520;
    float* wacc = sm + 528;
    int tid = threadIdx.x, lane = tid & 31, w = tid >> 5;
    int Lb = g_Lb[b];

    float qreg[16];
    const float* hb = hcur + b * Hz + lane * 16;
    #pragma unroll
    for (int i = 0; i < 16; i += 4) {
        float4 v = *(const float4*)(hb + i);
        qreg[i] = v.x; qreg[i + 1] = v.y; qreg[i + 2] = v.z; qreg[i + 3] = v.w;
    }

    const unsigned char* Fb = g_Fc + (size_t)b * LCz * Hz;
    #pragma unroll 4
    for (int l = w; l < Lb; l += 8) {
        uint4 u0 = *(const uint4*)(Fb + (size_t)l * Hz + lane * 16);
        const unsigned short* p2 = (const unsigned short*)&u0;
        float acc = 0.f;
        #pragma unroll
        for (int i = 0; i < 8; i++) {
            float2 f = fp8x2_to_f2(p2[i]);
            acc += f.x * qreg[2 * i] + f.y * qreg[2 * i + 1];
        }
        #pragma unroll
        for (int o = 16; o > 0; o >>= 1) acc += __shfl_xor_sync(0xffffffffu, acc, o);
        if (lane == 0) ss[l] = acc;
    }
    NB(1);

    float m = -INFINITY;
    for (int l = tid; l < Lb; l += 256) m = fmaxf(m, ss[l]);
    #pragma unroll
    for (int o = 16; o > 0; o >>= 1) m = fmaxf(m, __shfl_xor_sync(0xffffffffu, m, o));
    if (lane == 0) red[w] = m;
    NB(1);
    if (tid == 0) {
        float mm = red[0];
        for (int i = 1; i < 8; i++) mm = fmaxf(mm, red[i]);
        sca[0] = mm;
    }
    NB(1);
    float bmax = sca[0];

    float s = 0.f;
    for (int l = tid; l < Lb; l += 256) {
        float e = expf(ss[l] - bmax);
        ss[l] = e;
        s += e;
    }
    #pragma unroll
    for (int o = 16; o > 0; o >>= 1) s += __shfl_xor_sync(0xffffffffu, s, o);
    if (lane == 0) red[w] = s;
    NB(1);
    if (tid == 0) {
        float t2 = 0.f;
        for (int i = 0; i < 8; i++) t2 += red[i];
        sca[1] = t2;
    }
    NB(1);
    float inv = 1.f / sca[1];

    float acc2[16];
    #pragma unroll
    for (int i = 0; i < 16; i++) acc2[i] = 0.f;
    const unsigned char* Eb = g_encc + (size_t)b * LCz * Hz;
    #pragma unroll 4
    for (int l = w; l < Lb; l += 8) {
        float d = ss[l];
        uint4 u0 = *(const uint4*)(Eb + (size_t)l * Hz + lane * 16);
        const unsigned short* p2 = (const unsigned short*)&u0;
        #pragma unroll
        for (int i = 0; i < 8; i++) {
            float2 f = fp8x2_to_f2(p2[i]);
            acc2[2 * i]     += d * f.x;
            acc2[2 * i + 1] += d * f.y;
        }
    }
    #pragma unroll
    for (int i = 0; i < 16; i++) wacc[w * Hz + lane * 16 + i] = acc2[i];
    NB(1);

    for (int h = tid; h < Hz; h += 256) {
        float t2 = 0.f;
        #pragma unroll
        for (int ww = 0; ww < 8; ww++) t2 += wacc[ww * Hz + h];
        float v = t2 * inv;
        dst[b * Hz + h] = v;
        dstb[b * Hz + h] = __float2bfloat16(v);
    }
}

// ---------------- out-proj (group B) -----------------------------------------
__device__ void outproj16(const float* __restrict__ h_src,
                          const float* __restrict__ attn_src,
                          const float* __restrict__ out_b,
                          float* __restrict__ vout, float* sm, int mh, int t256)
{
    NB(2);
    int bid = blockIdx.x;
    int gb = bid >> 1;
    int m0 = mh * 64 + (gb & 3) * 16;
    int n0 = ((gb >> 2) & 7) * 64;
    int split = (gb >> 5) & 1;
    const float* Asrc = (split == 0) ? h_src : attn_src;

    int arow = t256 & 15, akg = t256 >> 4;
    int wr = t256 >> 2, wkg = t256 & 3;
    int m = t256 >> 4, ng = t256 & 15;

    const float* ap = Asrc + (size_t)(m0 + arow) * Hz + akg * 8;
    const __nv_bfloat16* wp = g_oWb16 + (size_t)(n0 + wr) * 1024 + split * Hz + wkg * 8;

    float4 pa0, pa1;
    uint4 pw;
    if (t256 < 64) { pa0 = *(const float4*)ap; pa1 = *(const float4*)(ap + 4); }
    pw = *(const uint4*)wp;

    float acc[4] = {0.f, 0.f, 0.f, 0.f};
    for (int it = 0; it < 16; it++) {
        float* As = sm + (it & 1) * 2560;
        float* Ws = As + 512;
        if (t256 < 64) {
            int kb = akg * 8;
            As[(kb + 0) * 16 + arow] = pa0.x; As[(kb + 1) * 16 + arow] = pa0.y;
            As[(kb + 2) * 16 + arow] = pa0.z; As[(kb + 3) * 16 + arow] = pa0.w;
            As[(kb + 4) * 16 + arow] = pa1.x; As[(kb + 5) * 16 + arow] = pa1.y;
            As[(kb + 6) * 16 + arow] = pa1.z; As[(kb + 7) * 16 + arow] = pa1.w;
        }
        {
            int kb = wkg * 8;
            const __nv_bfloat162* ph = (const __nv_bfloat162*)&pw;
            #pragma unroll
            for (int i = 0; i < 4; i++) {
                float2 f = __bfloat1622float2(ph[i]);
                Ws[(kb + 2 * i) * 64 + wr]     = f.x;
                Ws[(kb + 2 * i + 1) * 64 + wr] = f.y;
            }
        }
        NB(2);
        if (it < 15) {
            if (t256 < 64) {
                const float* ap2 = ap + (it + 1) * 32;
                pa0 = *(const float4*)ap2; pa1 = *(const float4*)(ap2 + 4);
            }
            pw = *(const uint4*)(wp + (it + 1) * 32);
        }
        #pragma unroll
        for (int kk = 0; kk < 32; kk++) {
            float a = As[kk * 16 + m];
            float4 w4 = *(const float4*)&Ws[kk * 64 + ng * 4];
            acc[0] += a * w4.x; acc[1] += a * w4.y;
            acc[2] += a * w4.z; acc[3] += a * w4.w;
        }
    }
    NB(2);
    #pragma unroll
    for (int i = 0; i < 4; i++) {
        int n = n0 + ng * 4 + i;
        float v = acc[i] + ((split == 0) ? out_b[n] : 0.f);
        vout[(size_t)split * BHS + (m0 + m) * Hz + n] = v;
    }
}

// ---------------- logits + CE ------------------------------------------------
__device__ void logits_ce(int b, int tt, const int* __restrict__ E,
                          const float* __restrict__ vp,
                          const float* __restrict__ voc_b, float* sm,
                          int t256, int barid)
{
    float* st = sm;
    float* sl = sm + 512;
    int lane = t256 & 31, w = t256 >> 5;
    NB(barid);

    for (int i = t256; i < Hz; i += 256)
        st[i] = tanhf(vp[b * Hz + i] + vp[BHS + b * Hz + i]);
    NB(barid);

    float sreg[16];
    #pragma unroll
    for (int i = 0; i < 16; i++) sreg[i] = st[lane * 16 + i];

    for (int v = w; v < Vz; v += 8) {
        const __nv_bfloat16* wr = g_vocb16 + (size_t)v * Hz + lane * 16;
        uint4 u0 = *(const uint4*)wr;
        uint4 u1 = *(const uint4*)(wr + 8);
        const __nv_bfloat162* h0 = (const __nv_bfloat162*)&u0;
        const __nv_bfloat162* h1 = (const __nv_bfloat162*)&u1;
        float acc = 0.f;
        #pragma unroll
        for (int i = 0; i < 4; i++) {
            float2 f0 = __bfloat1622float2(h0[i]);
            float2 f1 = __bfloat1622float2(h1[i]);
            acc += f0.x * sreg[2 * i]     + f0.y * sreg[2 * i + 1];
            acc += f1.x * sreg[8 + 2 * i] + f1.y * sreg[8 + 2 * i + 1];
        }
        #pragma unroll
        for (int o = 16; o > 0; o >>= 1) acc += __shfl_xor_sync(0xffffffffu, acc, o);
        if (lane == 0) sl[v] = acc + voc_b[v];
    }
    NB(barid);

    if (w == 0) {
        float m = -INFINITY;
        for (int v = lane; v < Vz; v += 32) m = fmaxf(m, sl[v]);
        #pragma unroll
        for (int o = 16; o > 0; o >>= 1) m = fmaxf(m, __shfl_xor_sync(0xffffffffu, m, o));
        float s = 0.f;
        for (int v = lane; v < Vz; v += 32) s += expf(sl[v] - m);
        #pragma unroll
        for (int o = 16; o > 0; o >>= 1) s += __shfl_xor_sync(0xffffffffu, s, o);
        if (lane == 0) {
            int tv = E[b * LEz + tt + 1];
            int idx = b * TDEC + tt;
            if (tv != 0) { g_nll[idx] = m + logf(s) - sl[tv]; g_msk[idx] = 1.f; }
            else         { g_nll[idx] = 0.f;                  g_msk[idx] = 0.f; }
        }
    }
    NB(barid);
}

// ---------------- the single persistent kernel ------------------------------
__global__ void __launch_bounds__(NTHR, 1) persist_kernel(
    const float* __restrict__ C,       const int* __restrict__ C_pad,
    const int* __restrict__ E,         const float* __restrict__ E_emb,
    const float* __restrict__ enc_Wih, const float* __restrict__ enc_Whh,
    const float* __restrict__ enc_bih, const float* __restrict__ enc_bhh,
    const float* __restrict__ dec_Wih, const float* __restrict__ dec_Whh,
    const float* __restrict__ dec_bih, const float* __restrict__ dec_bhh,
    const float* __restrict__ att_W,   const float* __restrict__ out_W,
    const float* __restrict__ out_b,   const float* __restrict__ voc_W,
    const float* __restrict__ voc_b,   float* __restrict__ out)
{
    extern __shared__ __align__(16) float4 dsm[];
    uint4*  Wp   = (uint4*)dsm;
    float4* Ab   = dsm + 4608;
    float*  scrA = (float*)(dsm + 4608);   // aliases Ab (phase-B only)
    float*  scrB = scrA + 4624;

    int bid = blockIdx.x, tid = threadIdx.x;
    int lane = tid & 31, w = tid >> 5;
    int mh = bid & 1, nb = bid >> 1;
    int mhb = mh * 64 + nb;

    // ---- init + bf16 pre-conversions ----
    for (int i = bid * NTHR + tid; i < BHS; i += NBLK * NTHR) {
        g_h[0][i] = 0.f; g_c[i] = 0.f;
        g_hb16[0][i] = __float2bfloat16(0.f);
        g_ab16[0][i] = __float2bfloat16(0.f);
        g_ab16[1][i] = __float2bfloat16(0.f);
    }
    float* vpf = (float*)g_vp;
    for (int i = bid * NTHR + tid; i < 4 * BHS; i += NBLK * NTHR) vpf[i] = 0.f;
    float* apf = (float*)g_attn2;
    for (int i = bid * NTHR + tid; i < 2 * BHS; i += NBLK * NTHR) apf[i] = 0.f;
    for (int i = bid * NTHR + tid; i < Vz * Hz; i += NBLK * NTHR)
        g_vocb16[i] = __float2bfloat16(voc_W[i]);
    for (size_t i = bid * NTHR + tid; i < (size_t)Bz * LCz * Vz; i += NBLK * NTHR)
        g_Cb16[i] = __float2bfloat16(C[i]);
    for (size_t i = bid * NTHR + tid; i < (size_t)Bz * LEz * Vz; i += NBLK * NTHR)
        g_Eb16[i] = __float2bfloat16(E_emb[i]);
    for (int i = bid * NTHR + tid; i < 512 * 1024; i += NBLK * NTHR)
        g_oWb16[i] = __float2bfloat16(out_W[i]);
    gsync_all();

    // ---- encoder ----
    pack_Wb3(Wp, nb, 40, enc_Wih, Vz, Vz, enc_Whh, Hz, Hz, enc_Whh, Hz);
    __syncthreads();
    float biasE[2][4];
    load_bias2(biasE, enc_bih, enc_bhh, nullptr, nb);
    for (int t = 0; t < LCz; t++) {
        gates_step<false>(Wp, Ab, g_Cb16, t, g_h[1 - (t & 1)],
                          g_hb16[t & 1], nullptr, g_hb16[1 - (t & 1)],
                          mh, nb, biasE, nullptr);
        gsync_g(mh, nb);
    }

    // ---- pre-decoder (own batch) ----
    comp_scan(mhb, C_pad, scrA);
    build_F(mhb, att_W, (float*)dsm);
    calc_u(mhb, out_W, out_b, scrA);
    calc_c(mhb, dec_Wih, scrA);

    // ---- composition (shared) => full barrier ----
    compose(dec_Wih, dec_Whh, dec_bih, dec_bhh, out_W, out_b);
    gsync_all();

    // ---- decoder ----
    pack_Wb3(Wp, nb, 72, dec_Wih, Vz + Hz, Vz, g_Weff, Hz, Hz, g_Wcomp, Hz);
    __syncthreads();
    float biasD[2][4];
    load_bias2(biasD, dec_bih, dec_bhh, g_beff, nb);

    for (int t = 0; t < TDEC; t++) {
        // Phase A: gates(t) — bulk publish, sync-free mainloop
        gates_step<true>(Wp, Ab, g_Eb16, t, g_h[1 - (t & 1)],
                         g_hb16[t & 1], g_ab16[(t + 1) & 1], g_hb16[1 - (t & 1)],
                         mh, nb, biasD, (t == 0) ? g_corr : nullptr);
        gsync_g(mh, nb);

        // Phase B: group A attn(t) || group B outproj(t-1) + CE(t-2)
        if (tid < 256) {
            attn_block(mhb, g_h[1 - (t & 1)], g_attn2[t & 1], g_ab16[t & 1], scrA);
        } else {
            int t256 = tid - 256;
            if (t >= 1)
                outproj16(g_h[t & 1], g_attn2[(t + 1) & 1], out_b,
                          (float*)g_vp[(t + 1) & 1], scrB, mh, t256);
            if (t >= 2)
                logits_ce(mhb, t - 2, E, (const float*)g_vp[t & 1], voc_b, scrB,
                          t256, 2);
        }
        gsync_g(mh, nb);
    }

    // ---- tail: V(510) (group B) || CE(509) (group A); then CE(510) ----
    if (tid < 256) {
        logits_ce(mhb, TDEC - 2, E, (const float*)g_vp[1], voc_b, scrA, tid, 1);
    } else {
        outproj16(g_h[1], g_attn2[0], out_b, (float*)g_vp[0], scrB, mh, tid - 256);
    }
    gsync_g(mh, nb);
    if (tid < 256)
        logits_ce(mhb, TDEC - 1, E, (const float*)g_vp[0], voc_b, scrA, tid, 1);
    __syncthreads();

    // ---- per-batch reduction ----
    {
        float s = 0.f, c = 0.f;
        for (int i = tid; i < TDEC; i += NTHR) {
            s += g_nll[mhb * TDEC + i];
            c += g_msk[mhb * TDEC + i];
        }
        #pragma unroll
        for (int o = 16; o > 0; o >>= 1) {
            s += __shfl_xor_sync(0xffffffffu, s, o);
            c += __shfl_xor_sync(0xffffffffu, c, o);
        }
        __syncthreads();
        if (lane == 0) { scrA[w] = s; scrA[16 + w] = c; }
        __syncthreads();
        if (tid == 0) {
            float ts = 0.f, tc = 0.f;
            for (int i = 0; i < 16; i++) { ts += scrA[i]; tc += scrA[16 + i]; }
            g_ps[bid] = ts; g_pc[bid] = tc;
        }
    }
    gsync_all();
    if (bid == 0 && tid == 0) {
        float ts = 0.f, tc = 0.f;
        for (int i = 0; i < NBLK; i++) { ts += g_ps[i]; tc += g_pc[i]; }
        out[0] = ts / fmaxf(tc, 1.f);
    }
}

// ---------------- host entry ------------------------------------------------
extern "C" void kernel_launch(void* const* d_in, const int* in_sizes, int n_in,
                              void* d_out, int out_size)
{
    cudaFuncSetAttribute((const void*)persist_kernel,
                         cudaFuncAttributeMaxDynamicSharedMemorySize, SMEM_BYTES);
    persist_kernel<<<NBLK, NTHR, SMEM_BYTES>>>(
        (const float*)d_in[0],  (const int*)d_in[1],
        (const int*)d_in[2],    (const float*)d_in[3],
        (const float*)d_in[4],  (const float*)d_in[5],
        (const float*)d_in[6],  (const float*)d_in[7],
        (const float*)d_in[8],  (const float*)d_in[9],
        (const float*)d_in[10], (const float*)d_in[11],
        (const float*)d_in[12], (const float*)d_in[13],
        (const float*)d_in[14], (const float*)d_in[15],
        (const float*)d_in[16], (float*)d_out);
}